// round 1
// baseline (speedup 1.0000x reference)
#include <cuda_runtime.h>
#include <cuda_bf16.h>
#include <math.h>

#define NN 16384
#define EE 524288
#define ET (EE + NN)   // 540672 edges incl. self loops
#define GIN 1568       // 32*7*7

// ---------------- scratch (device globals; no allocs allowed) ----------------
__device__ float g_h1[NN * 16 * 14 * 14];  // conv1+pool output
__device__ float g_h2[NN * GIN];           // conv2+pool output (flattened NCHW)
__device__ float g_xl1[NN * 128];
__device__ float g_xr1[NN * 128];
__device__ float g_ex1[ET * 2];
__device__ float g_den1[NN * 2];
__device__ float g_o1[NN * 128];           // gat1 out (in-place bias+relu)
__device__ float g_xl2[NN * 64];
__device__ float g_xr2[NN * 64];
__device__ float g_ex2[ET];
__device__ float g_den2[NN];
__device__ float g_o2[NN * 64];            // gat2 out (pre-bias)

__device__ __forceinline__ float lrelu(float v) { return v > 0.f ? v : 0.2f * v; }

// ---------------- zero accumulators (graph replays must reset) ----------------
__global__ void k_zero() {
    int i = blockIdx.x * blockDim.x + threadIdx.x;
    int stride = gridDim.x * blockDim.x;
    for (int j = i; j < NN * 2; j += stride) g_den1[j] = 0.f;
    for (int j = i; j < NN; j += stride) g_den2[j] = 0.f;
    for (int j = i; j < NN * 128; j += stride) g_o1[j] = 0.f;
    for (int j = i; j < NN * 64; j += stride) g_o2[j] = 0.f;
}

// ---------------- conv1 (1->16, 3x3 SAME) + relu + maxpool2 ----------------
__global__ void k_conv1(const float* __restrict__ x, const float* __restrict__ w,
                        const float* __restrict__ b) {
    __shared__ float sin_[30 * 30];
    __shared__ float sw[16 * 9];
    __shared__ float sb[16];
    const int n = blockIdx.x;
    const int t = threadIdx.x;  // 256
    for (int i = t; i < 900; i += 256) sin_[i] = 0.f;
    if (t < 144) sw[t] = w[t];
    if (t < 16) sb[t] = b[t];
    __syncthreads();
    const float* xi = x + n * 784;
    for (int i = t; i < 784; i += 256) {
        int y = i / 28, xx = i % 28;
        sin_[(y + 1) * 30 + xx + 1] = xi[i];
    }
    __syncthreads();
    for (int idx = t; idx < 16 * 196; idx += 256) {
        int c = idx / 196, p = idx % 196;
        int py = p / 14, px = p % 14;
        const float* wc = sw + c * 9;
        float bias = sb[c];
        float mx = 0.f;  // relu then max == max(0, max conv)
#pragma unroll
        for (int dy = 0; dy < 2; dy++)
#pragma unroll
            for (int dx = 0; dx < 2; dx++) {
                int oy = 2 * py + dy, ox = 2 * px + dx;
                float acc = bias;
#pragma unroll
                for (int ky = 0; ky < 3; ky++)
#pragma unroll
                    for (int kx = 0; kx < 3; kx++)
                        acc += sin_[(oy + ky) * 30 + ox + kx] * wc[ky * 3 + kx];
                mx = fmaxf(mx, acc);
            }
        g_h1[n * 3136 + idx] = mx;
    }
}

// ---------------- conv2 (16->32, 3x3 SAME) + relu + maxpool2 ----------------
__global__ void k_conv2(const float* __restrict__ w, const float* __restrict__ b) {
    __shared__ float sin_[16 * 16 * 16];  // [ci][16][16] padded (14+2)
    __shared__ float sw[32 * 16 * 9];
    __shared__ float sb[32];
    const int n = blockIdx.x;
    const int t = threadIdx.x;  // 256
    for (int i = t; i < 4096; i += 256) sin_[i] = 0.f;
    for (int i = t; i < 4608; i += 256) sw[i] = w[i];
    if (t < 32) sb[t] = b[t];
    __syncthreads();
    const float* hi = g_h1 + n * 3136;
    for (int i = t; i < 3136; i += 256) {
        int ci = i / 196, p = i % 196, y = p / 14, xx = p % 14;
        sin_[ci * 256 + (y + 1) * 16 + (xx + 1)] = hi[i];
    }
    __syncthreads();
    // work items: 8 channel-groups (4 ch) x 49 pooled positions
    for (int item = t; item < 392; item += 256) {
        int cg = item / 49, p = item % 49;
        int c0 = cg * 4;
        int py = p / 7, px = p % 7;
        float acc[4][4];
#pragma unroll
        for (int cc = 0; cc < 4; cc++) {
            float bb = sb[c0 + cc];
#pragma unroll
            for (int q = 0; q < 4; q++) acc[cc][q] = bb;
        }
        for (int ci = 0; ci < 16; ci++) {
            const float* ip = sin_ + ci * 256;
            const float* wp = sw + ci * 9;
#pragma unroll
            for (int ky = 0; ky < 3; ky++)
#pragma unroll
                for (int kx = 0; kx < 3; kx++) {
                    float w0 = wp[(c0 + 0) * 144 + ky * 3 + kx];
                    float w1 = wp[(c0 + 1) * 144 + ky * 3 + kx];
                    float w2 = wp[(c0 + 2) * 144 + ky * 3 + kx];
                    float w3 = wp[(c0 + 3) * 144 + ky * 3 + kx];
#pragma unroll
                    for (int dy = 0; dy < 2; dy++)
#pragma unroll
                        for (int dx = 0; dx < 2; dx++) {
                            float v = ip[(2 * py + dy + ky) * 16 + (2 * px + dx + kx)];
                            int q = dy * 2 + dx;
                            acc[0][q] += w0 * v;
                            acc[1][q] += w1 * v;
                            acc[2][q] += w2 * v;
                            acc[3][q] += w3 * v;
                        }
                }
        }
#pragma unroll
        for (int cc = 0; cc < 4; cc++) {
            float mx = 0.f;
#pragma unroll
            for (int q = 0; q < 4; q++) mx = fmaxf(mx, acc[cc][q]);
            g_h2[n * GIN + (c0 + cc) * 49 + p] = mx;
        }
    }
}

// ---------------- tiled fp32 GEMM: C = A[MxK] * B[KxN] + bias ----------------
template <int BM, int BN, int BK, int TM, int TN>
__global__ void k_gemm_bias(const float* __restrict__ A, const float* __restrict__ B,
                            const float* __restrict__ bias, float* __restrict__ C,
                            int M, int K, int NC) {
    constexpr int NTHR = (BM / TM) * (BN / TN);
    static_assert(BM * BK == NTHR * 4 && BK * BN == NTHR * 4, "one float4 per thread per tile");
    __shared__ float As[BK][BM];
    __shared__ float Bs[BK][BN];
    const int t = threadIdx.x;
    const int bm = blockIdx.y * BM, bn = blockIdx.x * BN;
    const int tx = t % (BN / TN), ty = t / (BN / TN);
    const int ar = t / (BK / 4), ac = (t % (BK / 4)) * 4;
    const int bkr = t / (BN / 4), bc = (t % (BN / 4)) * 4;

    float acc[TM][TN];
#pragma unroll
    for (int i = 0; i < TM; i++)
#pragma unroll
        for (int j = 0; j < TN; j++) acc[i][j] = 0.f;

    for (int k0 = 0; k0 < K; k0 += BK) {
        float4 av = *(const float4*)(A + (size_t)(bm + ar) * K + k0 + ac);
        As[ac + 0][ar] = av.x;
        As[ac + 1][ar] = av.y;
        As[ac + 2][ar] = av.z;
        As[ac + 3][ar] = av.w;
        *(float4*)&Bs[bkr][bc] = *(const float4*)(B + (size_t)(k0 + bkr) * NC + bn + bc);
        __syncthreads();
#pragma unroll
        for (int k = 0; k < BK; k++) {
            float a[TM], bb[TN];
#pragma unroll
            for (int i = 0; i < TM; i += 4) *(float4*)&a[i] = *(const float4*)&As[k][ty * TM + i];
#pragma unroll
            for (int j = 0; j < TN; j += 4) *(float4*)&bb[j] = *(const float4*)&Bs[k][tx * TN + j];
#pragma unroll
            for (int i = 0; i < TM; i++)
#pragma unroll
                for (int j = 0; j < TN; j++) acc[i][j] += a[i] * bb[j];
        }
        __syncthreads();
    }
#pragma unroll
    for (int i = 0; i < TM; i++) {
        int row = bm + ty * TM + i;
#pragma unroll
        for (int j = 0; j < TN; j++) {
            int col = bn + tx * TN + j;
            C[(size_t)row * NC + col] = acc[i][j] + bias[col];
        }
    }
}

// ---------------- GAT layer 1: edge alpha + denom (2 heads, 64 ch) -----------
__global__ void k_edge1_a(const int* __restrict__ ei, const float* __restrict__ att) {
    int e = (blockIdx.x * blockDim.x + threadIdx.x) >> 5;
    int lane = threadIdx.x & 31;
    if (e >= ET) return;
    int s, d;
    if (e < EE) { s = ei[e]; d = ei[EE + e]; } else { s = d = e - EE; }
    float4 xl = *(const float4*)(g_xl1 + (size_t)s * 128 + lane * 4);
    float4 xr = *(const float4*)(g_xr1 + (size_t)d * 128 + lane * 4);
    float4 at = *(const float4*)(att + lane * 4);  // att flattened [2*64]
    float sum = lrelu(xl.x + xr.x) * at.x + lrelu(xl.y + xr.y) * at.y +
                lrelu(xl.z + xr.z) * at.z + lrelu(xl.w + xr.w) * at.w;
    // reduce within each 16-lane half (head 0 = lanes 0-15, head 1 = lanes 16-31)
    sum += __shfl_xor_sync(0xffffffffu, sum, 8);
    sum += __shfl_xor_sync(0xffffffffu, sum, 4);
    sum += __shfl_xor_sync(0xffffffffu, sum, 2);
    sum += __shfl_xor_sync(0xffffffffu, sum, 1);
    if (lane == 0 || lane == 16) {
        int h = lane >> 4;
        float ex = expf(sum);  // |alpha| ~ 0.1: max-subtraction unnecessary
        g_ex1[(size_t)e * 2 + h] = ex;
        atomicAdd(&g_den1[d * 2 + h], ex);
    }
}

// ---------------- GAT layer 1: weighted scatter -------------------------------
__global__ void k_edge2_a(const int* __restrict__ ei) {
    int e = (blockIdx.x * blockDim.x + threadIdx.x) >> 5;
    int lane = threadIdx.x & 31;
    if (e >= ET) return;
    int s, d;
    if (e < EE) { s = ei[e]; d = ei[EE + e]; } else { s = d = e - EE; }
    int h = lane >> 4;
    float a = g_ex1[(size_t)e * 2 + h] / g_den1[d * 2 + h];
    float4 xl = *(const float4*)(g_xl1 + (size_t)s * 128 + lane * 4);
    float4 r = make_float4(a * xl.x, a * xl.y, a * xl.z, a * xl.w);
    atomicAdd((float4*)(g_o1 + (size_t)d * 128 + lane * 4), r);
}

__global__ void k_bias_relu1(const float* __restrict__ bias) {
    int i = blockIdx.x * blockDim.x + threadIdx.x;
    g_o1[i] = fmaxf(g_o1[i] + bias[i & 127], 0.f);
}

// ---------------- GAT layer 2: edge alpha + denom (1 head, 64 ch) ------------
__global__ void k_edge1_b(const int* __restrict__ ei, const float* __restrict__ att) {
    int e = (blockIdx.x * blockDim.x + threadIdx.x) >> 5;
    int lane = threadIdx.x & 31;
    if (e >= ET) return;
    int s, d;
    if (e < EE) { s = ei[e]; d = ei[EE + e]; } else { s = d = e - EE; }
    float2 xl = *(const float2*)(g_xl2 + (size_t)s * 64 + lane * 2);
    float2 xr = *(const float2*)(g_xr2 + (size_t)d * 64 + lane * 2);
    float2 at = *(const float2*)(att + lane * 2);
    float sum = lrelu(xl.x + xr.x) * at.x + lrelu(xl.y + xr.y) * at.y;
    sum += __shfl_xor_sync(0xffffffffu, sum, 16);
    sum += __shfl_xor_sync(0xffffffffu, sum, 8);
    sum += __shfl_xor_sync(0xffffffffu, sum, 4);
    sum += __shfl_xor_sync(0xffffffffu, sum, 2);
    sum += __shfl_xor_sync(0xffffffffu, sum, 1);
    if (lane == 0) {
        float ex = expf(sum);
        g_ex2[e] = ex;
        atomicAdd(&g_den2[d], ex);
    }
}

__global__ void k_edge2_b(const int* __restrict__ ei) {
    int e = (blockIdx.x * blockDim.x + threadIdx.x) >> 5;
    int lane = threadIdx.x & 31;
    if (e >= ET) return;
    int s, d;
    if (e < EE) { s = ei[e]; d = ei[EE + e]; } else { s = d = e - EE; }
    float a = g_ex2[e] / g_den2[d];
    float2 xl = *(const float2*)(g_xl2 + (size_t)s * 64 + lane * 2);
    atomicAdd((float2*)(g_o2 + (size_t)d * 64 + lane * 2), make_float2(a * xl.x, a * xl.y));
}

// ---------------- classifier: (o2 + bias2) @ Wc + bc -------------------------
__global__ void k_cls(const float* __restrict__ Wc, const float* __restrict__ bc,
                      const float* __restrict__ bias2, float* __restrict__ out) {
    int i = blockIdx.x * blockDim.x + threadIdx.x;
    if (i >= NN * 10) return;
    int n = i / 10, j = i % 10;
    const float* r = g_o2 + (size_t)n * 64;
    float acc = bc[j];
#pragma unroll
    for (int c = 0; c < 64; c++) acc += (r[c] + bias2[c]) * Wc[c * 10 + j];
    out[i] = acc;
}

// ---------------- launcher ----------------------------------------------------
extern "C" void kernel_launch(void* const* d_in, const int* in_sizes, int n_in,
                              void* d_out, int out_size) {
    const float* x = (const float*)d_in[0];
    const int* ei = (const int*)d_in[1];
    const float* c1w = (const float*)d_in[2];
    const float* c1b = (const float*)d_in[3];
    const float* c2w = (const float*)d_in[4];
    const float* c2b = (const float*)d_in[5];
    const float* Wl1 = (const float*)d_in[6];
    const float* bl1 = (const float*)d_in[7];
    const float* Wr1 = (const float*)d_in[8];
    const float* br1 = (const float*)d_in[9];
    const float* att1 = (const float*)d_in[10];
    const float* bias1 = (const float*)d_in[11];
    const float* Wl2 = (const float*)d_in[12];
    const float* bl2 = (const float*)d_in[13];
    const float* Wr2 = (const float*)d_in[14];
    const float* br2 = (const float*)d_in[15];
    const float* att2 = (const float*)d_in[16];
    const float* bias2 = (const float*)d_in[17];
    const float* Wc = (const float*)d_in[18];
    const float* bc = (const float*)d_in[19];
    float* out = (float*)d_out;

    void *ph2, *pxl1, *pxr1, *po1, *pxl2, *pxr2;
    cudaGetSymbolAddress(&ph2, g_h2);
    cudaGetSymbolAddress(&pxl1, g_xl1);
    cudaGetSymbolAddress(&pxr1, g_xr1);
    cudaGetSymbolAddress(&po1, g_o1);
    cudaGetSymbolAddress(&pxl2, g_xl2);
    cudaGetSymbolAddress(&pxr2, g_xr2);

    k_zero<<<2048, 256>>>();
    k_conv1<<<NN, 256>>>(x, c1w, c1b);
    k_conv2<<<NN, 256>>>(c2w, c2b);
    k_gemm_bias<128, 128, 8, 8, 8><<<dim3(1, NN / 128), 256>>>(
        (const float*)ph2, Wl1, bl1, (float*)pxl1, NN, GIN, 128);
    k_gemm_bias<128, 128, 8, 8, 8><<<dim3(1, NN / 128), 256>>>(
        (const float*)ph2, Wr1, br1, (float*)pxr1, NN, GIN, 128);
    k_edge1_a<<<ET / 8, 256>>>(ei, att1);
    k_edge2_a<<<ET / 8, 256>>>(ei);
    k_bias_relu1<<<NN * 128 / 256, 256>>>(bias1);
    k_gemm_bias<64, 64, 16, 4, 4><<<dim3(1, NN / 64), 256>>>(
        (const float*)po1, Wl2, bl2, (float*)pxl2, NN, 128, 64);
    k_gemm_bias<64, 64, 16, 4, 4><<<dim3(1, NN / 64), 256>>>(
        (const float*)po1, Wr2, br2, (float*)pxr2, NN, 128, 64);
    k_edge1_b<<<ET / 8, 256>>>(ei, att2);
    k_edge2_b<<<ET / 8, 256>>>(ei);
    k_cls<<<(NN * 10 + 255) / 256, 256>>>(Wc, bc, bias2, out);
}

// round 3
// speedup vs baseline: 1.1906x; 1.1906x over previous
#include <cuda_runtime.h>
#include <cuda_bf16.h>
#include <math.h>

#define NN 16384
#define EE 524288
#define ET (EE + NN)   // 540672 edges incl. self loops
#define GIN 1568       // 32*7*7

typedef unsigned long long u64;

// ---------------- f32x2 packed math helpers ----------------------------------
__device__ __forceinline__ u64 pk2(float x, float y) {
    u64 r; asm("mov.b64 %0, {%1,%2};" : "=l"(r) : "f"(x), "f"(y)); return r;
}
__device__ __forceinline__ u64 pkb(float x) { return pk2(x, x); }
__device__ __forceinline__ u64 ffma2(u64 a, u64 b, u64 c) {
    u64 d; asm("fma.rn.f32x2 %0, %1, %2, %3;" : "=l"(d) : "l"(a), "l"(b), "l"(c)); return d;
}
__device__ __forceinline__ float2 upk(u64 v) {
    float2 r; asm("mov.b64 {%0,%1}, %2;" : "=f"(r.x), "=f"(r.y) : "l"(v)); return r;
}

// ---------------- scratch (device globals; no allocs allowed) ----------------
__device__ float g_h1[NN * 16 * 14 * 14];  // conv1+pool output
__device__ float g_h2[NN * GIN];           // conv2+pool output (flattened NCHW)
__device__ float g_xl1[NN * 128];
__device__ float g_xr1[NN * 128];
__device__ float g_ex1[ET * 2];
__device__ float g_den1[NN * 2];
__device__ float g_o1[NN * 128];           // gat1 out (in-place bias+relu)
__device__ float g_xl2[NN * 64];
__device__ float g_xr2[NN * 64];
__device__ float g_ex2[ET];
__device__ float g_den2[NN];
__device__ float g_o2[NN * 64];            // gat2 out (pre-bias)

__device__ __forceinline__ float lrelu(float v) { return v > 0.f ? v : 0.2f * v; }

// ---------------- zero accumulators (graph replays must reset) ----------------
__global__ void k_zero() {
    int i = blockIdx.x * blockDim.x + threadIdx.x;
    int stride = gridDim.x * blockDim.x;
    for (int j = i; j < NN * 2; j += stride) g_den1[j] = 0.f;
    for (int j = i; j < NN; j += stride) g_den2[j] = 0.f;
    for (int j = i; j < NN * 128; j += stride) g_o1[j] = 0.f;
    for (int j = i; j < NN * 64; j += stride) g_o2[j] = 0.f;
}

// ---------------- conv1 (1->16, 3x3 SAME) + relu + maxpool2 ------------------
// Thread handles one (channel-pair, pooled-pos) item with a 4x4 register window.
__global__ void k_conv1(const float* __restrict__ x, const float* __restrict__ w,
                        const float* __restrict__ b) {
    __shared__ float sin_[30 * 30];
    __shared__ float sw[9 * 16];   // [k][oc] channel-contiguous
    __shared__ float sb[16];
    const int n = blockIdx.x;
    const int t = threadIdx.x;  // 256
    for (int i = t; i < 900; i += 256) sin_[i] = 0.f;
    if (t < 144) { int oc = t / 9, k = t % 9; sw[k * 16 + oc] = w[t]; }
    if (t < 16) sb[t] = b[t];
    __syncthreads();
    const float* xi = x + n * 784;
    for (int i = t; i < 784; i += 256) {
        int y = i / 28, xx = i % 28;
        sin_[(y + 1) * 30 + xx + 1] = xi[i];
    }
    __syncthreads();
    for (int item = t; item < 8 * 196; item += 256) {
        int cp = item / 196, p = item % 196;
        int c0 = cp * 2;
        int py = p / 14, px = p % 14;
        float v[4][4];
#pragma unroll
        for (int r = 0; r < 4; r++) {
            float2 a = *(const float2*)&sin_[(2 * py + r) * 30 + 2 * px];
            float2 c = *(const float2*)&sin_[(2 * py + r) * 30 + 2 * px + 2];
            v[r][0] = a.x; v[r][1] = a.y; v[r][2] = c.x; v[r][3] = c.y;
        }
        u64 bi = *(const u64*)&sb[c0];
        u64 acc[4] = {bi, bi, bi, bi};
#pragma unroll
        for (int ky = 0; ky < 3; ky++)
#pragma unroll
            for (int kx = 0; kx < 3; kx++) {
                u64 wp = *(const u64*)&sw[(ky * 3 + kx) * 16 + c0];
#pragma unroll
                for (int q = 0; q < 4; q++) {
                    int dy = q >> 1, dx = q & 1;
                    acc[q] = ffma2(wp, pkb(v[dy + ky][dx + kx]), acc[q]);
                }
            }
        float2 m0 = upk(acc[0]);
        float mx0 = m0.x, mx1 = m0.y;
#pragma unroll
        for (int q = 1; q < 4; q++) {
            float2 mq = upk(acc[q]);
            mx0 = fmaxf(mx0, mq.x); mx1 = fmaxf(mx1, mq.y);
        }
        g_h1[n * 3136 + c0 * 196 + p] = fmaxf(mx0, 0.f);
        g_h1[n * 3136 + (c0 + 1) * 196 + p] = fmaxf(mx1, 0.f);
    }
}

// ---------------- conv2 (16->32, 3x3 SAME) + relu + maxpool2 -----------------
__global__ void k_conv2(const float* __restrict__ w, const float* __restrict__ b) {
    __shared__ float sin_[16 * 16 * 16];   // [ci][16][16] padded (14+2)
    __shared__ float sw[16 * 9 * 32];      // [ci][k][oc] channel-contiguous
    __shared__ float sb[32];
    const int n = blockIdx.x;
    const int t = threadIdx.x;  // 256
    for (int i = t; i < 4096; i += 256) sin_[i] = 0.f;
    for (int i = t; i < 4608; i += 256) {
        int oc = i / 144, r = i % 144, ci = r / 9, k = r % 9;
        sw[ci * 288 + k * 32 + oc] = w[i];
    }
    if (t < 32) sb[t] = b[t];
    __syncthreads();
    const float* hi = g_h1 + n * 3136;
    for (int i = t; i < 3136; i += 256) {
        int ci = i / 196, p = i % 196, y = p / 14, xx = p % 14;
        sin_[ci * 256 + (y + 1) * 16 + (xx + 1)] = hi[i];
    }
    __syncthreads();
    // work items: 8 channel-groups (4 ch) x 49 pooled positions
    for (int item = t; item < 392; item += 256) {
        int cg = item / 49, p = item % 49;
        int c0 = cg * 4;
        int py = p / 7, px = p % 7;
        u64 b01 = *(const u64*)&sb[c0];
        u64 b23 = *(const u64*)&sb[c0 + 2];
        u64 acc01[4] = {b01, b01, b01, b01};
        u64 acc23[4] = {b23, b23, b23, b23};
        for (int ci = 0; ci < 16; ci++) {
            const float* ip = sin_ + ci * 256 + 2 * py * 16 + 2 * px;
            float v[4][4];
#pragma unroll
            for (int r = 0; r < 4; r++) {
                float2 a = *(const float2*)&ip[r * 16];
                float2 c = *(const float2*)&ip[r * 16 + 2];
                v[r][0] = a.x; v[r][1] = a.y; v[r][2] = c.x; v[r][3] = c.y;
            }
            const float* wp0 = sw + ci * 288 + c0;
#pragma unroll
            for (int ky = 0; ky < 3; ky++)
#pragma unroll
                for (int kx = 0; kx < 3; kx++) {
                    float4 wv = *(const float4*)&wp0[(ky * 3 + kx) * 32];
                    u64 w01 = pk2(wv.x, wv.y);
                    u64 w23 = pk2(wv.z, wv.w);
#pragma unroll
                    for (int q = 0; q < 4; q++) {
                        int dy = q >> 1, dx = q & 1;
                        u64 vb = pkb(v[dy + ky][dx + kx]);
                        acc01[q] = ffma2(w01, vb, acc01[q]);
                        acc23[q] = ffma2(w23, vb, acc23[q]);
                    }
                }
        }
        float2 a0 = upk(acc01[0]), b0 = upk(acc23[0]);
        float m0 = a0.x, m1 = a0.y, m2 = b0.x, m3 = b0.y;
#pragma unroll
        for (int q = 1; q < 4; q++) {
            float2 aq = upk(acc01[q]), bq = upk(acc23[q]);
            m0 = fmaxf(m0, aq.x); m1 = fmaxf(m1, aq.y);
            m2 = fmaxf(m2, bq.x); m3 = fmaxf(m3, bq.y);
        }
        float* outp = g_h2 + (size_t)n * GIN + c0 * 49 + p;
        outp[0]      = fmaxf(m0, 0.f);
        outp[49]     = fmaxf(m1, 0.f);
        outp[98]     = fmaxf(m2, 0.f);
        outp[147]    = fmaxf(m3, 0.f);
    }
}

// ---- fused dual-weight GEMM: C{0,1} = A[MxK] @ B{0,1}[KxNC] + bias{0,1} -----
// BM=128, BN=64, BK=16; blockDim=256 (16x16); TM=8 rows (4 f32x2 pairs), TN=4.
template <int BM, int BN, int BK>
__global__ void k_gemm2(const float* __restrict__ A,
                        const float* __restrict__ B0, const float* __restrict__ B1,
                        const float* __restrict__ bias0, const float* __restrict__ bias1,
                        float* __restrict__ C0, float* __restrict__ C1,
                        int K, int NC) {
    __shared__ float As[BK][BM];
    __shared__ float Bs[BK][BN];
    const int t = threadIdx.x;
    const int tx = t & 15, ty = t >> 4;
    const int ncolb = NC / BN;
    const int which = blockIdx.x / ncolb;
    const int bn = (blockIdx.x % ncolb) * BN;
    const int bm = blockIdx.y * BM;
    const float* B = which ? B1 : B0;
    const float* bias = which ? bias1 : bias0;
    float* C = which ? C1 : C0;

    u64 acc[4][4];
#pragma unroll
    for (int i = 0; i < 4; i++)
#pragma unroll
        for (int j = 0; j < 4; j++) acc[i][j] = 0ull;

    const int ar = t >> 1, ac = (t & 1) * 8;        // A fill: 8 floats/thread
    const int bkr = t >> 4, bc = (t & 15) * 4;      // B fill: 4 floats/thread

    for (int k0 = 0; k0 < K; k0 += BK) {
        float4 a0 = *(const float4*)&A[(size_t)(bm + ar) * K + k0 + ac];
        float4 a1 = *(const float4*)&A[(size_t)(bm + ar) * K + k0 + ac + 4];
        As[ac + 0][ar] = a0.x; As[ac + 1][ar] = a0.y;
        As[ac + 2][ar] = a0.z; As[ac + 3][ar] = a0.w;
        As[ac + 4][ar] = a1.x; As[ac + 5][ar] = a1.y;
        As[ac + 6][ar] = a1.z; As[ac + 7][ar] = a1.w;
        *(float4*)&Bs[bkr][bc] = *(const float4*)&B[(size_t)(k0 + bkr) * NC + bn + bc];
        __syncthreads();
#pragma unroll
        for (int k = 0; k < BK; k++) {
            const u64* ap = (const u64*)&As[k][ty * 8];
            u64 a2[4] = {ap[0], ap[1], ap[2], ap[3]};
            float4 bv = *(const float4*)&Bs[k][tx * 4];
            u64 bb[4] = {pkb(bv.x), pkb(bv.y), pkb(bv.z), pkb(bv.w)};
#pragma unroll
            for (int ip = 0; ip < 4; ip++)
#pragma unroll
                for (int j = 0; j < 4; j++) acc[ip][j] = ffma2(a2[ip], bb[j], acc[ip][j]);
        }
        __syncthreads();
    }
    const int col = bn + tx * 4;
    float4 bsv = *(const float4*)&bias[col];
#pragma unroll
    for (int ip = 0; ip < 4; ip++) {
        int m0 = bm + ty * 8 + 2 * ip;
        float2 r0 = upk(acc[ip][0]), r1 = upk(acc[ip][1]);
        float2 r2 = upk(acc[ip][2]), r3 = upk(acc[ip][3]);
        float4 lo = make_float4(r0.x + bsv.x, r1.x + bsv.y, r2.x + bsv.z, r3.x + bsv.w);
        float4 hi = make_float4(r0.y + bsv.x, r1.y + bsv.y, r2.y + bsv.z, r3.y + bsv.w);
        *(float4*)&C[(size_t)m0 * NC + col] = lo;
        *(float4*)&C[(size_t)(m0 + 1) * NC + col] = hi;
    }
}

// ---------------- GAT layer 1: edge alpha + denom (2 heads, 64 ch) -----------
__global__ void k_edge1_a(const int* __restrict__ ei, const float* __restrict__ att) {
    int e = (blockIdx.x * blockDim.x + threadIdx.x) >> 5;
    int lane = threadIdx.x & 31;
    if (e >= ET) return;
    int s, d;
    if (e < EE) { s = ei[e]; d = ei[EE + e]; } else { s = d = e - EE; }
    float4 xl = *(const float4*)(g_xl1 + (size_t)s * 128 + lane * 4);
    float4 xr = *(const float4*)(g_xr1 + (size_t)d * 128 + lane * 4);
    float4 at = *(const float4*)(att + lane * 4);  // att flattened [2*64]
    float sum = lrelu(xl.x + xr.x) * at.x + lrelu(xl.y + xr.y) * at.y +
                lrelu(xl.z + xr.z) * at.z + lrelu(xl.w + xr.w) * at.w;
    sum += __shfl_xor_sync(0xffffffffu, sum, 8);
    sum += __shfl_xor_sync(0xffffffffu, sum, 4);
    sum += __shfl_xor_sync(0xffffffffu, sum, 2);
    sum += __shfl_xor_sync(0xffffffffu, sum, 1);
    if (lane == 0 || lane == 16) {
        int h = lane >> 4;
        float ex = expf(sum);  // |alpha| ~ 0.1: max-subtraction unnecessary
        g_ex1[(size_t)e * 2 + h] = ex;
        atomicAdd(&g_den1[d * 2 + h], ex);
    }
}

// ---------------- GAT layer 1: weighted scatter -------------------------------
__global__ void k_edge2_a(const int* __restrict__ ei) {
    int e = (blockIdx.x * blockDim.x + threadIdx.x) >> 5;
    int lane = threadIdx.x & 31;
    if (e >= ET) return;
    int s, d;
    if (e < EE) { s = ei[e]; d = ei[EE + e]; } else { s = d = e - EE; }
    int h = lane >> 4;
    float a = g_ex1[(size_t)e * 2 + h] / g_den1[d * 2 + h];
    float4 xl = *(const float4*)(g_xl1 + (size_t)s * 128 + lane * 4);
    float4 r = make_float4(a * xl.x, a * xl.y, a * xl.z, a * xl.w);
    atomicAdd((float4*)(g_o1 + (size_t)d * 128 + lane * 4), r);
}

__global__ void k_bias_relu1(const float* __restrict__ bias) {
    int i = blockIdx.x * blockDim.x + threadIdx.x;
    g_o1[i] = fmaxf(g_o1[i] + bias[i & 127], 0.f);
}

// ---------------- GAT layer 2: edge alpha + denom (1 head, 64 ch) ------------
__global__ void k_edge1_b(const int* __restrict__ ei, const float* __restrict__ att) {
    int e = (blockIdx.x * blockDim.x + threadIdx.x) >> 5;
    int lane = threadIdx.x & 31;
    if (e >= ET) return;
    int s, d;
    if (e < EE) { s = ei[e]; d = ei[EE + e]; } else { s = d = e - EE; }
    float2 xl = *(const float2*)(g_xl2 + (size_t)s * 64 + lane * 2);
    float2 xr = *(const float2*)(g_xr2 + (size_t)d * 64 + lane * 2);
    float2 at = *(const float2*)(att + lane * 2);
    float sum = lrelu(xl.x + xr.x) * at.x + lrelu(xl.y + xr.y) * at.y;
    sum += __shfl_xor_sync(0xffffffffu, sum, 16);
    sum += __shfl_xor_sync(0xffffffffu, sum, 8);
    sum += __shfl_xor_sync(0xffffffffu, sum, 4);
    sum += __shfl_xor_sync(0xffffffffu, sum, 2);
    sum += __shfl_xor_sync(0xffffffffu, sum, 1);
    if (lane == 0) {
        float ex = expf(sum);
        g_ex2[e] = ex;
        atomicAdd(&g_den2[d], ex);
    }
}

__global__ void k_edge2_b(const int* __restrict__ ei) {
    int e = (blockIdx.x * blockDim.x + threadIdx.x) >> 5;
    int lane = threadIdx.x & 31;
    if (e >= ET) return;
    int s, d;
    if (e < EE) { s = ei[e]; d = ei[EE + e]; } else { s = d = e - EE; }
    float a = g_ex2[e] / g_den2[d];
    float2 xl = *(const float2*)(g_xl2 + (size_t)s * 64 + lane * 2);
    atomicAdd((float2*)(g_o2 + (size_t)d * 64 + lane * 2), make_float2(a * xl.x, a * xl.y));
}

// ---------------- classifier: (o2 + bias2) @ Wc + bc -------------------------
__global__ void k_cls(const float* __restrict__ Wc, const float* __restrict__ bc,
                      const float* __restrict__ bias2, float* __restrict__ out) {
    int i = blockIdx.x * blockDim.x + threadIdx.x;
    if (i >= NN * 10) return;
    int n = i / 10, j = i % 10;
    const float* r = g_o2 + (size_t)n * 64;
    float acc = bc[j];
#pragma unroll
    for (int c = 0; c < 64; c++) acc += (r[c] + bias2[c]) * Wc[c * 10 + j];
    out[i] = acc;
}

// ---------------- launcher ----------------------------------------------------
extern "C" void kernel_launch(void* const* d_in, const int* in_sizes, int n_in,
                              void* d_out, int out_size) {
    const float* x = (const float*)d_in[0];
    const int* ei = (const int*)d_in[1];
    const float* c1w = (const float*)d_in[2];
    const float* c1b = (const float*)d_in[3];
    const float* c2w = (const float*)d_in[4];
    const float* c2b = (const float*)d_in[5];
    const float* Wl1 = (const float*)d_in[6];
    const float* bl1 = (const float*)d_in[7];
    const float* Wr1 = (const float*)d_in[8];
    const float* br1 = (const float*)d_in[9];
    const float* att1 = (const float*)d_in[10];
    const float* bias1 = (const float*)d_in[11];
    const float* Wl2 = (const float*)d_in[12];
    const float* bl2 = (const float*)d_in[13];
    const float* Wr2 = (const float*)d_in[14];
    const float* br2 = (const float*)d_in[15];
    const float* att2 = (const float*)d_in[16];
    const float* bias2 = (const float*)d_in[17];
    const float* Wc = (const float*)d_in[18];
    const float* bc = (const float*)d_in[19];
    float* out = (float*)d_out;

    void *ph2, *pxl1, *pxr1, *po1, *pxl2, *pxr2;
    cudaGetSymbolAddress(&ph2, g_h2);
    cudaGetSymbolAddress(&pxl1, g_xl1);
    cudaGetSymbolAddress(&pxr1, g_xr1);
    cudaGetSymbolAddress(&po1, g_o1);
    cudaGetSymbolAddress(&pxl2, g_xl2);
    cudaGetSymbolAddress(&pxr2, g_xr2);

    k_zero<<<2048, 256>>>();
    k_conv1<<<NN, 256>>>(x, c1w, c1b);
    k_conv2<<<NN, 256>>>(c2w, c2b);
    // big fused GEMM: NC=128 -> 2 col blocks x 2 weights = gx 4, gy 128
    k_gemm2<128, 64, 16><<<dim3(4, NN / 128), 256>>>(
        (const float*)ph2, Wl1, Wr1, bl1, br1, (float*)pxl1, (float*)pxr1, GIN, 128);
    k_edge1_a<<<ET / 8, 256>>>(ei, att1);
    k_edge2_a<<<ET / 8, 256>>>(ei);
    k_bias_relu1<<<NN * 128 / 256, 256>>>(bias1);
    // small fused GEMM: NC=64 -> 1 col block x 2 weights = gx 2, gy 128
    k_gemm2<128, 64, 16><<<dim3(2, NN / 128), 256>>>(
        (const float*)po1, Wl2, Wr2, bl2, br2, (float*)pxl2, (float*)pxr2, 128, 64);
    k_edge1_b<<<ET / 8, 256>>>(ei, att2);
    k_edge2_b<<<ET / 8, 256>>>(ei);
    k_cls<<<(NN * 10 + 255) / 256, 256>>>(Wc, bc, bias2, out);
}

// round 4
// speedup vs baseline: 1.2991x; 1.0911x over previous
#include <cuda_runtime.h>
#include <cuda_bf16.h>
#include <math.h>

#define NN 16384
#define EE 524288
#define GIN 1568       // 32*7*7

typedef unsigned long long u64;

// ---------------- f32x2 packed math helpers ----------------------------------
__device__ __forceinline__ u64 pk2(float x, float y) {
    u64 r; asm("mov.b64 %0, {%1,%2};" : "=l"(r) : "f"(x), "f"(y)); return r;
}
__device__ __forceinline__ u64 pkb(float x) { return pk2(x, x); }
__device__ __forceinline__ u64 ffma2(u64 a, u64 b, u64 c) {
    u64 d; asm("fma.rn.f32x2 %0, %1, %2, %3;" : "=l"(d) : "l"(a), "l"(b), "l"(c)); return d;
}
__device__ __forceinline__ float2 upk(u64 v) {
    float2 r; asm("mov.b64 {%0,%1}, %2;" : "=f"(r.x), "=f"(r.y) : "l"(v)); return r;
}

// ---------------- scratch (device globals; no allocs allowed) ----------------
__device__ float g_h1[NN * 16 * 14 * 14];  // conv1+pool output
__device__ float g_h2[NN * GIN];           // conv2+pool output (flattened NCHW)
__device__ float g_xl1[NN * 128];
__device__ float g_xr1[NN * 128];
__device__ float g_o1[NN * 128];           // gat1 out (bias+relu fused)
__device__ float g_xl2[NN * 64];
__device__ float g_xr2[NN * 64];
__device__ float g_o2[NN * 64];            // gat2 out (pre-bias)
// CSR by destination
__device__ int g_deg[NN];                  // histogram, then scatter cursor
__device__ int g_roff[NN + 1];
__device__ int g_esrc[EE];

__device__ __forceinline__ float lrelu(float v) { return v > 0.f ? v : 0.2f * v; }

// ---------------- CSR build ---------------------------------------------------
__global__ void k_zero_deg() {
    int i = blockIdx.x * blockDim.x + threadIdx.x;
    if (i < NN) g_deg[i] = 0;
}

__global__ void k_hist(const int* __restrict__ ei) {
    int e = blockIdx.x * blockDim.x + threadIdx.x;
    if (e < EE) atomicAdd(&g_deg[ei[EE + e]], 1);
}

// single CTA, 1024 threads, 16 nodes/thread exclusive scan
__global__ void k_scan() {
    __shared__ int wsum[32];
    int t = threadIdx.x, lane = t & 31, wid = t >> 5;
    int base = t * 16;
    int c[16];
    int s = 0;
#pragma unroll
    for (int i = 0; i < 16; i++) { c[i] = s; s += g_deg[base + i]; }
    int v = s;
#pragma unroll
    for (int off = 1; off < 32; off <<= 1) {
        int n = __shfl_up_sync(0xffffffffu, v, off);
        if (lane >= off) v += n;
    }
    if (lane == 31) wsum[wid] = v;
    __syncthreads();
    if (wid == 0) {
        int w = wsum[lane];
#pragma unroll
        for (int off = 1; off < 32; off <<= 1) {
            int n = __shfl_up_sync(0xffffffffu, w, off);
            if (lane >= off) w += n;
        }
        wsum[lane] = w;  // inclusive
    }
    __syncthreads();
    int wbase = (wid == 0) ? 0 : wsum[wid - 1];
    int tbase = wbase + (v - s);  // exclusive base for this thread
#pragma unroll
    for (int i = 0; i < 16; i++) {
        int r = tbase + c[i];
        g_roff[base + i] = r;
        g_deg[base + i] = r;   // cursor for scatter
    }
    if (t == 1023) g_roff[NN] = EE;
}

__global__ void k_scatter(const int* __restrict__ ei) {
    int e = blockIdx.x * blockDim.x + threadIdx.x;
    if (e >= EE) return;
    int d = ei[EE + e];
    int pos = atomicAdd(&g_deg[d], 1);
    g_esrc[pos] = ei[e];
}

// ---------------- conv1 (1->16, 3x3 SAME) + relu + maxpool2 ------------------
__global__ void k_conv1(const float* __restrict__ x, const float* __restrict__ w,
                        const float* __restrict__ b) {
    __shared__ __align__(16) float sin_[30 * 30];
    __shared__ __align__(16) float sw[9 * 16];   // [k][oc]
    __shared__ __align__(16) float sb[16];
    const int n = blockIdx.x;
    const int t = threadIdx.x;  // 256
    for (int i = t; i < 900; i += 256) sin_[i] = 0.f;
    if (t < 144) { int oc = t / 9, k = t % 9; sw[k * 16 + oc] = w[t]; }
    if (t < 16) sb[t] = b[t];
    __syncthreads();
    const float* xi = x + n * 784;
    for (int i = t; i < 784; i += 256) {
        int y = i / 28, xx = i % 28;
        sin_[(y + 1) * 30 + xx + 1] = xi[i];
    }
    __syncthreads();
    for (int item = t; item < 8 * 196; item += 256) {
        int cp = item / 196, p = item % 196;
        int c0 = cp * 2;
        int py = p / 14, px = p % 14;
        float v[4][4];
#pragma unroll
        for (int r = 0; r < 4; r++) {
            float2 a = *(const float2*)&sin_[(2 * py + r) * 30 + 2 * px];
            float2 c = *(const float2*)&sin_[(2 * py + r) * 30 + 2 * px + 2];
            v[r][0] = a.x; v[r][1] = a.y; v[r][2] = c.x; v[r][3] = c.y;
        }
        u64 bi = *(const u64*)&sb[c0];
        u64 acc[4] = {bi, bi, bi, bi};
#pragma unroll
        for (int ky = 0; ky < 3; ky++)
#pragma unroll
            for (int kx = 0; kx < 3; kx++) {
                u64 wp = *(const u64*)&sw[(ky * 3 + kx) * 16 + c0];
#pragma unroll
                for (int q = 0; q < 4; q++) {
                    int dy = q >> 1, dx = q & 1;
                    acc[q] = ffma2(wp, pkb(v[dy + ky][dx + kx]), acc[q]);
                }
            }
        float2 m0 = upk(acc[0]);
        float mx0 = m0.x, mx1 = m0.y;
#pragma unroll
        for (int q = 1; q < 4; q++) {
            float2 mq = upk(acc[q]);
            mx0 = fmaxf(mx0, mq.x); mx1 = fmaxf(mx1, mq.y);
        }
        g_h1[n * 3136 + c0 * 196 + p] = fmaxf(mx0, 0.f);
        g_h1[n * 3136 + (c0 + 1) * 196 + p] = fmaxf(mx1, 0.f);
    }
}

// ---------------- conv2 (16->32, 3x3 SAME) + relu + maxpool2 -----------------
// blockDim = 416; items = 392 (one per thread)
__global__ void k_conv2(const float* __restrict__ w, const float* __restrict__ b) {
    __shared__ __align__(16) float sin_[16 * 16 * 16];   // [ci][16][16]
    __shared__ __align__(16) float sw[16 * 9 * 32];      // [ci][k][oc]
    __shared__ __align__(16) float sb[32];
    const int n = blockIdx.x;
    const int t = threadIdx.x;  // 416
    for (int i = t; i < 4096; i += 416) sin_[i] = 0.f;
    for (int i = t; i < 4608; i += 416) {
        int oc = i / 144, r = i % 144, ci = r / 9, k = r % 9;
        sw[ci * 288 + k * 32 + oc] = w[i];
    }
    if (t < 32) sb[t] = b[t];
    __syncthreads();
    const float* hi = g_h1 + n * 3136;
    for (int i = t; i < 3136; i += 416) {
        int ci = i / 196, p = i % 196, y = p / 14, xx = p % 14;
        sin_[ci * 256 + (y + 1) * 16 + (xx + 1)] = hi[i];
    }
    __syncthreads();
    if (t < 392) {
        int cg = t / 49, p = t % 49;
        int c0 = cg * 4;
        int py = p / 7, px = p % 7;
        u64 b01 = *(const u64*)&sb[c0];
        u64 b23 = *(const u64*)&sb[c0 + 2];
        u64 acc01[4] = {b01, b01, b01, b01};
        u64 acc23[4] = {b23, b23, b23, b23};
        for (int ci = 0; ci < 16; ci++) {
            const float* ip = sin_ + ci * 256 + 2 * py * 16 + 2 * px;
            float v[4][4];
#pragma unroll
            for (int r = 0; r < 4; r++) {
                float2 a = *(const float2*)&ip[r * 16];
                float2 c = *(const float2*)&ip[r * 16 + 2];
                v[r][0] = a.x; v[r][1] = a.y; v[r][2] = c.x; v[r][3] = c.y;
            }
            const float* wp0 = sw + ci * 288 + c0;
#pragma unroll
            for (int ky = 0; ky < 3; ky++)
#pragma unroll
                for (int kx = 0; kx < 3; kx++) {
                    u64 w01 = *(const u64*)&wp0[(ky * 3 + kx) * 32];
                    u64 w23 = *(const u64*)&wp0[(ky * 3 + kx) * 32 + 2];
#pragma unroll
                    for (int q = 0; q < 4; q++) {
                        int dy = q >> 1, dx = q & 1;
                        u64 vb = pkb(v[dy + ky][dx + kx]);
                        acc01[q] = ffma2(w01, vb, acc01[q]);
                        acc23[q] = ffma2(w23, vb, acc23[q]);
                    }
                }
        }
        float2 a0 = upk(acc01[0]), b0 = upk(acc23[0]);
        float m0 = a0.x, m1 = a0.y, m2 = b0.x, m3 = b0.y;
#pragma unroll
        for (int q = 1; q < 4; q++) {
            float2 aq = upk(acc01[q]), bq = upk(acc23[q]);
            m0 = fmaxf(m0, aq.x); m1 = fmaxf(m1, aq.y);
            m2 = fmaxf(m2, bq.x); m3 = fmaxf(m3, bq.y);
        }
        float* outp = g_h2 + (size_t)n * GIN + c0 * 49 + p;
        outp[0]   = fmaxf(m0, 0.f);
        outp[49]  = fmaxf(m1, 0.f);
        outp[98]  = fmaxf(m2, 0.f);
        outp[147] = fmaxf(m3, 0.f);
    }
}

// ---- fused dual-weight GEMM: C{0,1} = A[MxK] @ B{0,1}[KxNC] + bias{0,1} -----
// blockDim=256 (16x16); per-thread 8 rows (4 f32x2 pairs) x TN cols.
template <int BM, int BN, int BK>
__global__ void k_gemm2(const float* __restrict__ A,
                        const float* __restrict__ B0, const float* __restrict__ B1,
                        const float* __restrict__ bias0, const float* __restrict__ bias1,
                        float* __restrict__ C0, float* __restrict__ C1,
                        int K, int NC) {
    constexpr int TN = BN / 16;
    __shared__ __align__(16) float As[BK][BM];
    __shared__ __align__(16) float Bs[BK][BN];
    const int t = threadIdx.x;
    const int tx = t & 15, ty = t >> 4;
    const int ncolb = NC / BN;
    const int which = blockIdx.x / ncolb;
    const int bn = (blockIdx.x % ncolb) * BN;
    const int bm = blockIdx.y * BM;
    const float* B = which ? B1 : B0;
    const float* bias = which ? bias1 : bias0;
    float* C = which ? C1 : C0;

    u64 acc[4][TN];
#pragma unroll
    for (int i = 0; i < 4; i++)
#pragma unroll
        for (int j = 0; j < TN; j++) acc[i][j] = 0ull;

    const int ar = t >> 1, ac = (t & 1) * 8;   // A fill: 8 floats/thread
    const int bkr = t >> 4, bc = (t & 15) * TN; // B fill: TN floats/thread

    for (int k0 = 0; k0 < K; k0 += BK) {
        float4 a0 = *(const float4*)&A[(size_t)(bm + ar) * K + k0 + ac];
        float4 a1 = *(const float4*)&A[(size_t)(bm + ar) * K + k0 + ac + 4];
        As[ac + 0][ar] = a0.x; As[ac + 1][ar] = a0.y;
        As[ac + 2][ar] = a0.z; As[ac + 3][ar] = a0.w;
        As[ac + 4][ar] = a1.x; As[ac + 5][ar] = a1.y;
        As[ac + 6][ar] = a1.z; As[ac + 7][ar] = a1.w;
#pragma unroll
        for (int j = 0; j < TN; j += 4)
            *(float4*)&Bs[bkr][bc + j] = *(const float4*)&B[(size_t)(k0 + bkr) * NC + bn + bc + j];
        __syncthreads();
#pragma unroll
        for (int k = 0; k < BK; k++) {
            const u64* ap = (const u64*)&As[k][ty * 8];
            u64 a2[4] = {ap[0], ap[1], ap[2], ap[3]};
            u64 bb[TN];
#pragma unroll
            for (int j = 0; j < TN; j += 4) {
                float4 bv = *(const float4*)&Bs[k][tx * TN + j];
                bb[j + 0] = pkb(bv.x); bb[j + 1] = pkb(bv.y);
                bb[j + 2] = pkb(bv.z); bb[j + 3] = pkb(bv.w);
            }
#pragma unroll
            for (int ip = 0; ip < 4; ip++)
#pragma unroll
                for (int j = 0; j < TN; j++) acc[ip][j] = ffma2(a2[ip], bb[j], acc[ip][j]);
        }
        __syncthreads();
    }
    const int col = bn + tx * TN;
    float bsv[TN];
#pragma unroll
    for (int j = 0; j < TN; j += 4) *(float4*)&bsv[j] = *(const float4*)&bias[col + j];
#pragma unroll
    for (int ip = 0; ip < 4; ip++) {
        int m0 = bm + ty * 8 + 2 * ip;
        float lo[TN], hi[TN];
#pragma unroll
        for (int j = 0; j < TN; j++) {
            float2 r = upk(acc[ip][j]);
            lo[j] = r.x + bsv[j];
            hi[j] = r.y + bsv[j];
        }
#pragma unroll
        for (int j = 0; j < TN; j += 4) {
            *(float4*)&C[(size_t)m0 * NC + col + j] = *(float4*)&lo[j];
            *(float4*)&C[(size_t)(m0 + 1) * NC + col + j] = *(float4*)&hi[j];
        }
    }
}

// ---------------- GAT layer 1: fused gather (2 heads, 64 ch each) ------------
// warp per destination node; lanes 0-15 = head0, 16-31 = head1 (4 ch each)
__global__ void k_gat1(const float* __restrict__ att, const float* __restrict__ bias) {
    int d = (blockIdx.x * blockDim.x + threadIdx.x) >> 5;
    int lane = threadIdx.x & 31;
    if (d >= NN) return;
    const float4 at = *(const float4*)&att[lane * 4];
    float4 xr = *(const float4*)&g_xr1[(size_t)d * 128 + lane * 4];
    float4 xd = *(const float4*)&g_xl1[(size_t)d * 128 + lane * 4];
    // self loop
    float a = lrelu(xd.x + xr.x) * at.x + lrelu(xd.y + xr.y) * at.y +
              lrelu(xd.z + xr.z) * at.z + lrelu(xd.w + xr.w) * at.w;
    a += __shfl_xor_sync(0xffffffffu, a, 8);
    a += __shfl_xor_sync(0xffffffffu, a, 4);
    a += __shfl_xor_sync(0xffffffffu, a, 2);
    a += __shfl_xor_sync(0xffffffffu, a, 1);
    float ex = __expf(a);
    float den = ex;
    float4 acc = make_float4(ex * xd.x, ex * xd.y, ex * xd.z, ex * xd.w);

    int i0 = g_roff[d], i1 = g_roff[d + 1];
    int sN = (i0 < i1) ? g_esrc[i0] : 0;
    for (int i = i0; i < i1; i++) {
        int s = sN;
        if (i + 1 < i1) sN = g_esrc[i + 1];
        float4 xs = *(const float4*)&g_xl1[(size_t)s * 128 + lane * 4];
        float a2 = lrelu(xs.x + xr.x) * at.x + lrelu(xs.y + xr.y) * at.y +
                   lrelu(xs.z + xr.z) * at.z + lrelu(xs.w + xr.w) * at.w;
        a2 += __shfl_xor_sync(0xffffffffu, a2, 8);
        a2 += __shfl_xor_sync(0xffffffffu, a2, 4);
        a2 += __shfl_xor_sync(0xffffffffu, a2, 2);
        a2 += __shfl_xor_sync(0xffffffffu, a2, 1);
        float e2 = __expf(a2);
        den += e2;
        acc.x += e2 * xs.x; acc.y += e2 * xs.y;
        acc.z += e2 * xs.z; acc.w += e2 * xs.w;
    }
    float inv = 1.f / den;
    float4 bv = *(const float4*)&bias[lane * 4];
    float4 o;
    o.x = fmaxf(acc.x * inv + bv.x, 0.f);
    o.y = fmaxf(acc.y * inv + bv.y, 0.f);
    o.z = fmaxf(acc.z * inv + bv.z, 0.f);
    o.w = fmaxf(acc.w * inv + bv.w, 0.f);
    *(float4*)&g_o1[(size_t)d * 128 + lane * 4] = o;
}

// ---------------- GAT layer 2: fused gather (1 head, 64 ch) ------------------
__global__ void k_gat2(const float* __restrict__ att) {
    int d = (blockIdx.x * blockDim.x + threadIdx.x) >> 5;
    int lane = threadIdx.x & 31;
    if (d >= NN) return;
    const float2 at = *(const float2*)&att[lane * 2];
    float2 xr = *(const float2*)&g_xr2[(size_t)d * 64 + lane * 2];
    float2 xd = *(const float2*)&g_xl2[(size_t)d * 64 + lane * 2];
    float a = lrelu(xd.x + xr.x) * at.x + lrelu(xd.y + xr.y) * at.y;
    a += __shfl_xor_sync(0xffffffffu, a, 16);
    a += __shfl_xor_sync(0xffffffffu, a, 8);
    a += __shfl_xor_sync(0xffffffffu, a, 4);
    a += __shfl_xor_sync(0xffffffffu, a, 2);
    a += __shfl_xor_sync(0xffffffffu, a, 1);
    float ex = __expf(a);
    float den = ex;
    float2 acc = make_float2(ex * xd.x, ex * xd.y);

    int i0 = g_roff[d], i1 = g_roff[d + 1];
    int sN = (i0 < i1) ? g_esrc[i0] : 0;
    for (int i = i0; i < i1; i++) {
        int s = sN;
        if (i + 1 < i1) sN = g_esrc[i + 1];
        float2 xs = *(const float2*)&g_xl2[(size_t)s * 64 + lane * 2];
        float a2 = lrelu(xs.x + xr.x) * at.x + lrelu(xs.y + xr.y) * at.y;
        a2 += __shfl_xor_sync(0xffffffffu, a2, 16);
        a2 += __shfl_xor_sync(0xffffffffu, a2, 8);
        a2 += __shfl_xor_sync(0xffffffffu, a2, 4);
        a2 += __shfl_xor_sync(0xffffffffu, a2, 2);
        a2 += __shfl_xor_sync(0xffffffffu, a2, 1);
        float e2 = __expf(a2);
        den += e2;
        acc.x += e2 * xs.x; acc.y += e2 * xs.y;
    }
    float inv = 1.f / den;
    *(float2*)&g_o2[(size_t)d * 64 + lane * 2] = make_float2(acc.x * inv, acc.y * inv);
}

// ---------------- classifier: (o2 + bias2) @ Wc + bc -------------------------
__global__ void k_cls(const float* __restrict__ Wc, const float* __restrict__ bc,
                      const float* __restrict__ bias2, float* __restrict__ out) {
    int i = blockIdx.x * blockDim.x + threadIdx.x;
    if (i >= NN * 10) return;
    int n = i / 10, j = i % 10;
    const float* r = g_o2 + (size_t)n * 64;
    float acc = bc[j];
#pragma unroll
    for (int c = 0; c < 64; c++) acc += (r[c] + bias2[c]) * Wc[c * 10 + j];
    out[i] = acc;
}

// ---------------- launcher ----------------------------------------------------
extern "C" void kernel_launch(void* const* d_in, const int* in_sizes, int n_in,
                              void* d_out, int out_size) {
    const float* x = (const float*)d_in[0];
    const int* ei = (const int*)d_in[1];
    const float* c1w = (const float*)d_in[2];
    const float* c1b = (const float*)d_in[3];
    const float* c2w = (const float*)d_in[4];
    const float* c2b = (const float*)d_in[5];
    const float* Wl1 = (const float*)d_in[6];
    const float* bl1 = (const float*)d_in[7];
    const float* Wr1 = (const float*)d_in[8];
    const float* br1 = (const float*)d_in[9];
    const float* att1 = (const float*)d_in[10];
    const float* bias1 = (const float*)d_in[11];
    const float* Wl2 = (const float*)d_in[12];
    const float* bl2 = (const float*)d_in[13];
    const float* Wr2 = (const float*)d_in[14];
    const float* br2 = (const float*)d_in[15];
    const float* att2 = (const float*)d_in[16];
    const float* bias2 = (const float*)d_in[17];
    const float* Wc = (const float*)d_in[18];
    const float* bc = (const float*)d_in[19];
    float* out = (float*)d_out;

    void *ph2, *pxl1, *pxr1, *po1, *pxl2, *pxr2;
    cudaGetSymbolAddress(&ph2, g_h2);
    cudaGetSymbolAddress(&pxl1, g_xl1);
    cudaGetSymbolAddress(&pxr1, g_xr1);
    cudaGetSymbolAddress(&po1, g_o1);
    cudaGetSymbolAddress(&pxl2, g_xl2);
    cudaGetSymbolAddress(&pxr2, g_xr2);

    // CSR build (independent of conv path)
    k_zero_deg<<<NN / 256, 256>>>();
    k_hist<<<EE / 256, 256>>>(ei);
    k_scan<<<1, 1024>>>();
    k_scatter<<<EE / 256, 256>>>(ei);
    // CNN
    k_conv1<<<NN, 256>>>(x, c1w, c1b);
    k_conv2<<<NN, 416>>>(c2w, c2b);
    // big fused GEMM: NC=128, BN=128 -> 1 colblock x 2 weights
    k_gemm2<128, 128, 16><<<dim3(2, NN / 128), 256>>>(
        (const float*)ph2, Wl1, Wr1, bl1, br1, (float*)pxl1, (float*)pxr1, GIN, 128);
    k_gat1<<<NN / 8, 256>>>(att1, bias1);
    // small fused GEMM: NC=64, BN=64 -> 1 colblock x 2 weights
    k_gemm2<128, 64, 16><<<dim3(2, NN / 128), 256>>>(
        (const float*)po1, Wl2, Wr2, bl2, br2, (float*)pxl2, (float*)pxr2, 128, 64);
    k_gat2<<<NN / 8, 256>>>(att2);
    k_cls<<<(NN * 10 + 255) / 256, 256>>>(Wc, bc, bias2, out);
}

// round 5
// speedup vs baseline: 1.3883x; 1.0686x over previous
#include <cuda_runtime.h>
#include <cuda_bf16.h>
#include <math.h>

#define NN 16384
#define EE 524288
#define GIN 1568       // 32*7*7

typedef unsigned long long u64;

// ---------------- f32x2 packed math helpers ----------------------------------
__device__ __forceinline__ u64 pk2(float x, float y) {
    u64 r; asm("mov.b64 %0, {%1,%2};" : "=l"(r) : "f"(x), "f"(y)); return r;
}
__device__ __forceinline__ u64 pkb(float x) { return pk2(x, x); }
__device__ __forceinline__ u64 ffma2(u64 a, u64 b, u64 c) {
    u64 d; asm("fma.rn.f32x2 %0, %1, %2, %3;" : "=l"(d) : "l"(a), "l"(b), "l"(c)); return d;
}
__device__ __forceinline__ float2 upk(u64 v) {
    float2 r; asm("mov.b64 {%0,%1}, %2;" : "=f"(r.x), "=f"(r.y) : "l"(v)); return r;
}
__device__ __forceinline__ unsigned cvt_tf32(float f) {
    unsigned r; asm("cvt.rna.tf32.f32 %0, %1;" : "=r"(r) : "f"(f)); return r;
}
__device__ __forceinline__ void mma_tf32(float* d, const unsigned* a, const unsigned* b) {
    asm volatile(
        "mma.sync.aligned.m16n8k8.row.col.f32.tf32.tf32.f32 "
        "{%0,%1,%2,%3}, {%4,%5,%6,%7}, {%8,%9}, {%0,%1,%2,%3};"
        : "+f"(d[0]), "+f"(d[1]), "+f"(d[2]), "+f"(d[3])
        : "r"(a[0]), "r"(a[1]), "r"(a[2]), "r"(a[3]), "r"(b[0]), "r"(b[1]));
}

// ---------------- scratch (device globals; no allocs allowed) ----------------
__device__ float g_h1[NN * 16 * 14 * 14];  // conv1+pool output
__device__ float g_h2[NN * GIN];           // conv2+pool output (flattened NCHW)
__device__ float g_xl1[NN * 128];
__device__ float g_xr1[NN * 128];
__device__ float g_o1[NN * 128];           // gat1 out (bias+relu fused)
__device__ float g_xl2[NN * 64];
__device__ float g_xr2[NN * 64];
__device__ float g_o2[NN * 64];            // gat2 out (pre-bias)
// CSR by destination
__device__ int g_deg[NN];                  // histogram, then scatter cursor
__device__ int g_roff[NN + 1];
__device__ int g_esrc[EE];

__device__ __forceinline__ float lrelu(float v) { return v > 0.f ? v : 0.2f * v; }

// ---------------- CSR build ---------------------------------------------------
__global__ void k_zero_deg() {
    int i = blockIdx.x * blockDim.x + threadIdx.x;
    if (i < NN) g_deg[i] = 0;
}

__global__ void k_hist(const int* __restrict__ ei) {
    int e = blockIdx.x * blockDim.x + threadIdx.x;
    if (e < EE) atomicAdd(&g_deg[ei[EE + e]], 1);
}

// single CTA, 1024 threads, 16 nodes/thread exclusive scan
__global__ void k_scan() {
    __shared__ int wsum[32];
    int t = threadIdx.x, lane = t & 31, wid = t >> 5;
    int base = t * 16;
    int c[16];
    int s = 0;
#pragma unroll
    for (int i = 0; i < 16; i++) { c[i] = s; s += g_deg[base + i]; }
    int v = s;
#pragma unroll
    for (int off = 1; off < 32; off <<= 1) {
        int n = __shfl_up_sync(0xffffffffu, v, off);
        if (lane >= off) v += n;
    }
    if (lane == 31) wsum[wid] = v;
    __syncthreads();
    if (wid == 0) {
        int w = wsum[lane];
#pragma unroll
        for (int off = 1; off < 32; off <<= 1) {
            int n = __shfl_up_sync(0xffffffffu, w, off);
            if (lane >= off) w += n;
        }
        wsum[lane] = w;  // inclusive
    }
    __syncthreads();
    int wbase = (wid == 0) ? 0 : wsum[wid - 1];
    int tbase = wbase + (v - s);  // exclusive base for this thread
#pragma unroll
    for (int i = 0; i < 16; i++) {
        int r = tbase + c[i];
        g_roff[base + i] = r;
        g_deg[base + i] = r;   // cursor for scatter
    }
    if (t == 1023) g_roff[NN] = EE;
}

__global__ void k_scatter(const int* __restrict__ ei) {
    int e = blockIdx.x * blockDim.x + threadIdx.x;
    if (e >= EE) return;
    int d = ei[EE + e];
    int pos = atomicAdd(&g_deg[d], 1);
    g_esrc[pos] = ei[e];
}

// ---------------- conv1 (1->16, 3x3 SAME) + relu + maxpool2 ------------------
__global__ void k_conv1(const float* __restrict__ x, const float* __restrict__ w,
                        const float* __restrict__ b) {
    __shared__ __align__(16) float sin_[30 * 30];
    __shared__ __align__(16) float sw[9 * 16];   // [k][oc]
    __shared__ __align__(16) float sb[16];
    const int n = blockIdx.x;
    const int t = threadIdx.x;  // 256
    for (int i = t; i < 900; i += 256) sin_[i] = 0.f;
    if (t < 144) { int oc = t / 9, k = t % 9; sw[k * 16 + oc] = w[t]; }
    if (t < 16) sb[t] = b[t];
    __syncthreads();
    const float* xi = x + n * 784;
    for (int i = t; i < 784; i += 256) {
        int y = i / 28, xx = i % 28;
        sin_[(y + 1) * 30 + xx + 1] = xi[i];
    }
    __syncthreads();
    for (int item = t; item < 8 * 196; item += 256) {
        int cp = item / 196, p = item % 196;
        int c0 = cp * 2;
        int py = p / 14, px = p % 14;
        float v[4][4];
#pragma unroll
        for (int r = 0; r < 4; r++) {
            float2 a = *(const float2*)&sin_[(2 * py + r) * 30 + 2 * px];
            float2 c = *(const float2*)&sin_[(2 * py + r) * 30 + 2 * px + 2];
            v[r][0] = a.x; v[r][1] = a.y; v[r][2] = c.x; v[r][3] = c.y;
        }
        u64 bi = *(const u64*)&sb[c0];
        u64 acc[4] = {bi, bi, bi, bi};
#pragma unroll
        for (int ky = 0; ky < 3; ky++)
#pragma unroll
            for (int kx = 0; kx < 3; kx++) {
                u64 wp = *(const u64*)&sw[(ky * 3 + kx) * 16 + c0];
#pragma unroll
                for (int q = 0; q < 4; q++) {
                    int dy = q >> 1, dx = q & 1;
                    acc[q] = ffma2(wp, pkb(v[dy + ky][dx + kx]), acc[q]);
                }
            }
        float2 m0 = upk(acc[0]);
        float mx0 = m0.x, mx1 = m0.y;
#pragma unroll
        for (int q = 1; q < 4; q++) {
            float2 mq = upk(acc[q]);
            mx0 = fmaxf(mx0, mq.x); mx1 = fmaxf(mx1, mq.y);
        }
        g_h1[n * 3136 + c0 * 196 + p] = fmaxf(mx0, 0.f);
        g_h1[n * 3136 + (c0 + 1) * 196 + p] = fmaxf(mx1, 0.f);
    }
}

// ---------------- conv2 (16->32, 3x3 SAME) + relu + maxpool2 -----------------
// blockDim = 416; items = 392 (one per thread)
__global__ void k_conv2(const float* __restrict__ w, const float* __restrict__ b) {
    __shared__ __align__(16) float sin_[16 * 16 * 16];   // [ci][16][16]
    __shared__ __align__(16) float sw[16 * 9 * 32];      // [ci][k][oc]
    __shared__ __align__(16) float sb[32];
    const int n = blockIdx.x;
    const int t = threadIdx.x;  // 416
    for (int i = t; i < 4096; i += 416) sin_[i] = 0.f;
    for (int i = t; i < 4608; i += 416) {
        int oc = i / 144, r = i % 144, ci = r / 9, k = r % 9;
        sw[ci * 288 + k * 32 + oc] = w[i];
    }
    if (t < 32) sb[t] = b[t];
    __syncthreads();
    const float* hi = g_h1 + n * 3136;
    for (int i = t; i < 3136; i += 416) {
        int ci = i / 196, p = i % 196, y = p / 14, xx = p % 14;
        sin_[ci * 256 + (y + 1) * 16 + (xx + 1)] = hi[i];
    }
    __syncthreads();
    if (t < 392) {
        int cg = t / 49, p = t % 49;
        int c0 = cg * 4;
        int py = p / 7, px = p % 7;
        u64 b01 = *(const u64*)&sb[c0];
        u64 b23 = *(const u64*)&sb[c0 + 2];
        u64 acc01[4] = {b01, b01, b01, b01};
        u64 acc23[4] = {b23, b23, b23, b23};
        for (int ci = 0; ci < 16; ci++) {
            const float* ip = sin_ + ci * 256 + 2 * py * 16 + 2 * px;
            float v[4][4];
#pragma unroll
            for (int r = 0; r < 4; r++) {
                float2 a = *(const float2*)&ip[r * 16];
                float2 c = *(const float2*)&ip[r * 16 + 2];
                v[r][0] = a.x; v[r][1] = a.y; v[r][2] = c.x; v[r][3] = c.y;
            }
            const float* wp0 = sw + ci * 288 + c0;
#pragma unroll
            for (int ky = 0; ky < 3; ky++)
#pragma unroll
                for (int kx = 0; kx < 3; kx++) {
                    u64 w01 = *(const u64*)&wp0[(ky * 3 + kx) * 32];
                    u64 w23 = *(const u64*)&wp0[(ky * 3 + kx) * 32 + 2];
#pragma unroll
                    for (int q = 0; q < 4; q++) {
                        int dy = q >> 1, dx = q & 1;
                        u64 vb = pkb(v[dy + ky][dx + kx]);
                        acc01[q] = ffma2(w01, vb, acc01[q]);
                        acc23[q] = ffma2(w23, vb, acc23[q]);
                    }
                }
        }
        float2 a0 = upk(acc01[0]), b0 = upk(acc23[0]);
        float m0 = a0.x, m1 = a0.y, m2 = b0.x, m3 = b0.y;
#pragma unroll
        for (int q = 1; q < 4; q++) {
            float2 aq = upk(acc01[q]), bq = upk(acc23[q]);
            m0 = fmaxf(m0, aq.x); m1 = fmaxf(m1, aq.y);
            m2 = fmaxf(m2, bq.x); m3 = fmaxf(m3, bq.y);
        }
        float* outp = g_h2 + (size_t)n * GIN + c0 * 49 + p;
        outp[0]   = fmaxf(m0, 0.f);
        outp[49]  = fmaxf(m1, 0.f);
        outp[98]  = fmaxf(m2, 0.f);
        outp[147] = fmaxf(m3, 0.f);
    }
}

// ---- TF32 tensor-core dual-weight GEMM: C{0,1} = A @ B{0,1} + bias{0,1} -----
// BM=128, BN=64, BK=32; 128 threads = 4 warps (2x2); warp tile 64x32 of m16n8k8.
__global__ void k_gemm_tc(const float* __restrict__ A,
                          const float* __restrict__ B0, const float* __restrict__ B1,
                          const float* __restrict__ bias0, const float* __restrict__ bias1,
                          float* __restrict__ C0, float* __restrict__ C1,
                          int K, int NC) {
    constexpr int BM = 128, BN = 64, BK = 32;
    constexpr int BKP = BK + 4;   // pad -> conflict-free A frag loads
    constexpr int BNP = BN + 4;   // pad -> conflict-free B frag loads
    __shared__ __align__(16) unsigned As[BM][BKP];
    __shared__ __align__(16) unsigned Bs[BK][BNP];
    const int t = threadIdx.x, lane = t & 31, w = t >> 5;
    const int wm = (w >> 1) * 64, wn = (w & 1) * 32;
    const int ncolb = NC / BN;
    const int which = blockIdx.x / ncolb;
    const int bn = (blockIdx.x % ncolb) * BN;
    const int bm = blockIdx.y * BM;
    const float* B = which ? B1 : B0;
    const float* bias = which ? bias1 : bias0;
    float* C = which ? C1 : C0;

    float acc[4][4][4];
#pragma unroll
    for (int mt = 0; mt < 4; mt++)
#pragma unroll
        for (int nt = 0; nt < 4; nt++)
#pragma unroll
            for (int c = 0; c < 4; c++) acc[mt][nt][c] = 0.f;

    const float* arow = A + (size_t)(bm + t) * K;
    const int brow = t >> 2, bcol = (t & 3) * 16;

    for (int k0 = 0; k0 < K; k0 += BK) {
        // A fill: thread t owns smem row t (contiguous uint4 stores)
#pragma unroll
        for (int j = 0; j < BK; j += 4) {
            float4 v = *(const float4*)&arow[k0 + j];
            uint4 u = make_uint4(cvt_tf32(v.x), cvt_tf32(v.y), cvt_tf32(v.z), cvt_tf32(v.w));
            *(uint4*)&As[t][j] = u;
        }
        // B fill: thread t -> Bs[brow][bcol..bcol+16)
        const float* bp = B + (size_t)(k0 + brow) * NC + bn + bcol;
#pragma unroll
        for (int j = 0; j < 16; j += 4) {
            float4 v = *(const float4*)&bp[j];
            uint4 u = make_uint4(cvt_tf32(v.x), cvt_tf32(v.y), cvt_tf32(v.z), cvt_tf32(v.w));
            *(uint4*)&Bs[brow][bcol + j] = u;
        }
        __syncthreads();
#pragma unroll
        for (int ks = 0; ks < BK / 8; ks++) {
            const int kk = ks * 8;
            unsigned af[4][4], bf[4][2];
#pragma unroll
            for (int mt = 0; mt < 4; mt++) {
                int r = wm + mt * 16 + (lane >> 2);
                int c = kk + (lane & 3);
                af[mt][0] = As[r][c];
                af[mt][1] = As[r + 8][c];
                af[mt][2] = As[r][c + 4];
                af[mt][3] = As[r + 8][c + 4];
            }
#pragma unroll
            for (int nt = 0; nt < 4; nt++) {
                int c = wn + nt * 8 + (lane >> 2);
                bf[nt][0] = Bs[kk + (lane & 3)][c];
                bf[nt][1] = Bs[kk + (lane & 3) + 4][c];
            }
#pragma unroll
            for (int mt = 0; mt < 4; mt++)
#pragma unroll
                for (int nt = 0; nt < 4; nt++)
                    mma_tf32(acc[mt][nt], af[mt], bf[nt]);
        }
        __syncthreads();
    }
    // epilogue: c0,c1 at (row, 2q),(row, 2q+1); c2,c3 at row+8
#pragma unroll
    for (int nt = 0; nt < 4; nt++) {
        int col = bn + wn + nt * 8 + 2 * (lane & 3);
        float2 bv = *(const float2*)&bias[col];
#pragma unroll
        for (int mt = 0; mt < 4; mt++) {
            int r = bm + wm + mt * 16 + (lane >> 2);
            *(float2*)&C[(size_t)r * NC + col] =
                make_float2(acc[mt][nt][0] + bv.x, acc[mt][nt][1] + bv.y);
            *(float2*)&C[(size_t)(r + 8) * NC + col] =
                make_float2(acc[mt][nt][2] + bv.x, acc[mt][nt][3] + bv.y);
        }
    }
}

// ---------------- GAT layer 1: fused gather (2 heads, 64 ch each) ------------
// warp per destination node; lanes 0-15 = head0, 16-31 = head1 (4 ch each)
__global__ void k_gat1(const float* __restrict__ att, const float* __restrict__ bias) {
    int d = (blockIdx.x * blockDim.x + threadIdx.x) >> 5;
    int lane = threadIdx.x & 31;
    if (d >= NN) return;
    const float4 at = *(const float4*)&att[lane * 4];
    float4 xr = *(const float4*)&g_xr1[(size_t)d * 128 + lane * 4];
    float4 xd = *(const float4*)&g_xl1[(size_t)d * 128 + lane * 4];
    // self loop
    float a = lrelu(xd.x + xr.x) * at.x + lrelu(xd.y + xr.y) * at.y +
              lrelu(xd.z + xr.z) * at.z + lrelu(xd.w + xr.w) * at.w;
    a += __shfl_xor_sync(0xffffffffu, a, 8);
    a += __shfl_xor_sync(0xffffffffu, a, 4);
    a += __shfl_xor_sync(0xffffffffu, a, 2);
    a += __shfl_xor_sync(0xffffffffu, a, 1);
    float ex = __expf(a);
    float den = ex;
    float4 acc = make_float4(ex * xd.x, ex * xd.y, ex * xd.z, ex * xd.w);

    int i0 = g_roff[d], i1 = g_roff[d + 1];
    int sN = (i0 < i1) ? g_esrc[i0] : 0;
    for (int i = i0; i < i1; i++) {
        int s = sN;
        if (i + 1 < i1) sN = g_esrc[i + 1];
        float4 xs = *(const float4*)&g_xl1[(size_t)s * 128 + lane * 4];
        float a2 = lrelu(xs.x + xr.x) * at.x + lrelu(xs.y + xr.y) * at.y +
                   lrelu(xs.z + xr.z) * at.z + lrelu(xs.w + xr.w) * at.w;
        a2 += __shfl_xor_sync(0xffffffffu, a2, 8);
        a2 += __shfl_xor_sync(0xffffffffu, a2, 4);
        a2 += __shfl_xor_sync(0xffffffffu, a2, 2);
        a2 += __shfl_xor_sync(0xffffffffu, a2, 1);
        float e2 = __expf(a2);
        den += e2;
        acc.x += e2 * xs.x; acc.y += e2 * xs.y;
        acc.z += e2 * xs.z; acc.w += e2 * xs.w;
    }
    float inv = 1.f / den;
    float4 bv = *(const float4*)&bias[lane * 4];
    float4 o;
    o.x = fmaxf(acc.x * inv + bv.x, 0.f);
    o.y = fmaxf(acc.y * inv + bv.y, 0.f);
    o.z = fmaxf(acc.z * inv + bv.z, 0.f);
    o.w = fmaxf(acc.w * inv + bv.w, 0.f);
    *(float4*)&g_o1[(size_t)d * 128 + lane * 4] = o;
}

// ---------------- GAT layer 2: fused gather (1 head, 64 ch) ------------------
__global__ void k_gat2(const float* __restrict__ att) {
    int d = (blockIdx.x * blockDim.x + threadIdx.x) >> 5;
    int lane = threadIdx.x & 31;
    if (d >= NN) return;
    const float2 at = *(const float2*)&att[lane * 2];
    float2 xr = *(const float2*)&g_xr2[(size_t)d * 64 + lane * 2];
    float2 xd = *(const float2*)&g_xl2[(size_t)d * 64 + lane * 2];
    float a = lrelu(xd.x + xr.x) * at.x + lrelu(xd.y + xr.y) * at.y;
    a += __shfl_xor_sync(0xffffffffu, a, 16);
    a += __shfl_xor_sync(0xffffffffu, a, 8);
    a += __shfl_xor_sync(0xffffffffu, a, 4);
    a += __shfl_xor_sync(0xffffffffu, a, 2);
    a += __shfl_xor_sync(0xffffffffu, a, 1);
    float ex = __expf(a);
    float den = ex;
    float2 acc = make_float2(ex * xd.x, ex * xd.y);

    int i0 = g_roff[d], i1 = g_roff[d + 1];
    int sN = (i0 < i1) ? g_esrc[i0] : 0;
    for (int i = i0; i < i1; i++) {
        int s = sN;
        if (i + 1 < i1) sN = g_esrc[i + 1];
        float2 xs = *(const float2*)&g_xl2[(size_t)s * 64 + lane * 2];
        float a2 = lrelu(xs.x + xr.x) * at.x + lrelu(xs.y + xr.y) * at.y;
        a2 += __shfl_xor_sync(0xffffffffu, a2, 16);
        a2 += __shfl_xor_sync(0xffffffffu, a2, 8);
        a2 += __shfl_xor_sync(0xffffffffu, a2, 4);
        a2 += __shfl_xor_sync(0xffffffffu, a2, 2);
        a2 += __shfl_xor_sync(0xffffffffu, a2, 1);
        float e2 = __expf(a2);
        den += e2;
        acc.x += e2 * xs.x; acc.y += e2 * xs.y;
    }
    float inv = 1.f / den;
    *(float2*)&g_o2[(size_t)d * 64 + lane * 2] = make_float2(acc.x * inv, acc.y * inv);
}

// ---------------- classifier: (o2 + bias2) @ Wc + bc -------------------------
__global__ void k_cls(const float* __restrict__ Wc, const float* __restrict__ bc,
                      const float* __restrict__ bias2, float* __restrict__ out) {
    int i = blockIdx.x * blockDim.x + threadIdx.x;
    if (i >= NN * 10) return;
    int n = i / 10, j = i % 10;
    const float* r = g_o2 + (size_t)n * 64;
    float acc = bc[j];
#pragma unroll
    for (int c = 0; c < 64; c++) acc += (r[c] + bias2[c]) * Wc[c * 10 + j];
    out[i] = acc;
}

// ---------------- launcher ----------------------------------------------------
extern "C" void kernel_launch(void* const* d_in, const int* in_sizes, int n_in,
                              void* d_out, int out_size) {
    const float* x = (const float*)d_in[0];
    const int* ei = (const int*)d_in[1];
    const float* c1w = (const float*)d_in[2];
    const float* c1b = (const float*)d_in[3];
    const float* c2w = (const float*)d_in[4];
    const float* c2b = (const float*)d_in[5];
    const float* Wl1 = (const float*)d_in[6];
    const float* bl1 = (const float*)d_in[7];
    const float* Wr1 = (const float*)d_in[8];
    const float* br1 = (const float*)d_in[9];
    const float* att1 = (const float*)d_in[10];
    const float* bias1 = (const float*)d_in[11];
    const float* Wl2 = (const float*)d_in[12];
    const float* bl2 = (const float*)d_in[13];
    const float* Wr2 = (const float*)d_in[14];
    const float* br2 = (const float*)d_in[15];
    const float* att2 = (const float*)d_in[16];
    const float* bias2 = (const float*)d_in[17];
    const float* Wc = (const float*)d_in[18];
    const float* bc = (const float*)d_in[19];
    float* out = (float*)d_out;

    void *ph2, *pxl1, *pxr1, *po1, *pxl2, *pxr2;
    cudaGetSymbolAddress(&ph2, g_h2);
    cudaGetSymbolAddress(&pxl1, g_xl1);
    cudaGetSymbolAddress(&pxr1, g_xr1);
    cudaGetSymbolAddress(&po1, g_o1);
    cudaGetSymbolAddress(&pxl2, g_xl2);
    cudaGetSymbolAddress(&pxr2, g_xr2);

    // CSR build (independent of conv path)
    k_zero_deg<<<NN / 256, 256>>>();
    k_hist<<<EE / 256, 256>>>(ei);
    k_scan<<<1, 1024>>>();
    k_scatter<<<EE / 256, 256>>>(ei);
    // CNN
    k_conv1<<<NN, 256>>>(x, c1w, c1b);
    k_conv2<<<NN, 416>>>(c2w, c2b);
    // big fused GEMM (TF32 tensor cores): NC=128 -> 2 colblocks x 2 weights
    k_gemm_tc<<<dim3(4, NN / 128), 128>>>(
        (const float*)ph2, Wl1, Wr1, bl1, br1, (float*)pxl1, (float*)pxr1, GIN, 128);
    k_gat1<<<NN / 8, 256>>>(att1, bias1);
    // small fused GEMM (TF32): NC=64 -> 1 colblock x 2 weights
    k_gemm_tc<<<dim3(2, NN / 128), 128>>>(
        (const float*)po1, Wl2, Wr2, bl2, br2, (float*)pxl2, (float*)pxr2, 128, 64);
    k_gat2<<<NN / 8, 256>>>(att2);
    k_cls<<<(NN * 10 + 255) / 256, 256>>>(Wc, bc, bias2, out);
}

// round 9
// speedup vs baseline: 1.3934x; 1.0037x over previous
#include <cuda_runtime.h>
#include <cuda_bf16.h>
#include <math.h>

#define NN 16384
#define EE 524288
#define GIN 1568       // 32*7*7

typedef unsigned long long u64;

// ---------------- packed / tf32 helpers ---------------------------------------
__device__ __forceinline__ u64 pk2(float x, float y) {
    u64 r; asm("mov.b64 %0, {%1,%2};" : "=l"(r) : "f"(x), "f"(y)); return r;
}
__device__ __forceinline__ u64 pkb(float x) { return pk2(x, x); }
__device__ __forceinline__ u64 ffma2(u64 a, u64 b, u64 c) {
    u64 d; asm("fma.rn.f32x2 %0, %1, %2, %3;" : "=l"(d) : "l"(a), "l"(b), "l"(c)); return d;
}
__device__ __forceinline__ float2 upk(u64 v) {
    float2 r; asm("mov.b64 {%0,%1}, %2;" : "=f"(r.x), "=f"(r.y) : "l"(v)); return r;
}
__device__ __forceinline__ unsigned cvt_tf32(float f) {
    unsigned r; asm("cvt.rna.tf32.f32 %0, %1;" : "=r"(r) : "f"(f)); return r;
}
__device__ __forceinline__ void mma_tf32(float* d, const unsigned* a, const unsigned* b) {
    asm volatile(
        "mma.sync.aligned.m16n8k8.row.col.f32.tf32.tf32.f32 "
        "{%0,%1,%2,%3}, {%4,%5,%6,%7}, {%8,%9}, {%0,%1,%2,%3};"
        : "+f"(d[0]), "+f"(d[1]), "+f"(d[2]), "+f"(d[3])
        : "r"(a[0]), "r"(a[1]), "r"(a[2]), "r"(a[3]), "r"(b[0]), "r"(b[1]));
}

// ---------------- scratch (device globals; no allocs allowed) ----------------
__device__ float g_h1[NN * 16 * 14 * 14];  // conv1+pool output
__device__ float g_h2[NN * GIN];           // conv2+pool output (flattened NCHW)
__device__ float g_xl1[NN * 128];
__device__ float g_xr1[NN * 128];
__device__ float g_o1[NN * 128];           // gat1 out (bias+relu fused)
__device__ float g_xl2[NN * 64];
__device__ float g_xr2[NN * 64];
__device__ float g_o2[NN * 64];            // gat2 out (pre-bias)
// CSR by destination
__device__ int g_deg[NN];                  // histogram, then scatter cursor
__device__ int g_roff[NN + 1];
__device__ int g_esrc[EE];

__device__ __forceinline__ float lrelu(float v) { return v > 0.f ? v : 0.2f * v; }

// ---------------- CSR build ---------------------------------------------------
__global__ void k_zero_deg() {
    int i = blockIdx.x * blockDim.x + threadIdx.x;
    if (i < NN) g_deg[i] = 0;
}

__global__ void k_hist(const int* __restrict__ ei) {
    int e = blockIdx.x * blockDim.x + threadIdx.x;
    if (e < EE) atomicAdd(&g_deg[ei[EE + e]], 1);
}

// single CTA, 1024 threads, 16 nodes/thread exclusive scan
__global__ void k_scan() {
    __shared__ int wsum[32];
    int t = threadIdx.x, lane = t & 31, wid = t >> 5;
    int base = t * 16;
    int c[16];
    int s = 0;
#pragma unroll
    for (int i = 0; i < 16; i++) { c[i] = s; s += g_deg[base + i]; }
    int v = s;
#pragma unroll
    for (int off = 1; off < 32; off <<= 1) {
        int n = __shfl_up_sync(0xffffffffu, v, off);
        if (lane >= off) v += n;
    }
    if (lane == 31) wsum[wid] = v;
    __syncthreads();
    if (wid == 0) {
        int w = wsum[lane];
#pragma unroll
        for (int off = 1; off < 32; off <<= 1) {
            int n = __shfl_up_sync(0xffffffffu, w, off);
            if (lane >= off) w += n;
        }
        wsum[lane] = w;  // inclusive
    }
    __syncthreads();
    int wbase = (wid == 0) ? 0 : wsum[wid - 1];
    int tbase = wbase + (v - s);  // exclusive base for this thread
#pragma unroll
    for (int i = 0; i < 16; i++) {
        int r = tbase + c[i];
        g_roff[base + i] = r;
        g_deg[base + i] = r;   // cursor for scatter
    }
    if (t == 1023) g_roff[NN] = EE;
}

__global__ void k_scatter(const int* __restrict__ ei) {
    int e = blockIdx.x * blockDim.x + threadIdx.x;
    if (e >= EE) return;
    int d = ei[EE + e];
    int pos = atomicAdd(&g_deg[d], 1);
    g_esrc[pos] = ei[e];
}

// ---------------- conv1 (1->16, 3x3 SAME) + relu + maxpool2 ------------------
__global__ void k_conv1(const float* __restrict__ x, const float* __restrict__ w,
                        const float* __restrict__ b) {
    __shared__ __align__(16) float sin_[30 * 30];
    __shared__ __align__(16) float sw[9 * 16];   // [k][oc]
    __shared__ __align__(16) float sb[16];
    const int n = blockIdx.x;
    const int t = threadIdx.x;  // 256
    for (int i = t; i < 900; i += 256) sin_[i] = 0.f;
    if (t < 144) { int oc = t / 9, k = t % 9; sw[k * 16 + oc] = w[t]; }
    if (t < 16) sb[t] = b[t];
    __syncthreads();
    const float* xi = x + n * 784;
    for (int i = t; i < 784; i += 256) {
        int y = i / 28, xx = i % 28;
        sin_[(y + 1) * 30 + xx + 1] = xi[i];
    }
    __syncthreads();
    for (int item = t; item < 8 * 196; item += 256) {
        int cp = item / 196, p = item % 196;
        int c0 = cp * 2;
        int py = p / 14, px = p % 14;
        float v[4][4];
#pragma unroll
        for (int r = 0; r < 4; r++) {
            float2 a = *(const float2*)&sin_[(2 * py + r) * 30 + 2 * px];
            float2 c = *(const float2*)&sin_[(2 * py + r) * 30 + 2 * px + 2];
            v[r][0] = a.x; v[r][1] = a.y; v[r][2] = c.x; v[r][3] = c.y;
        }
        u64 bi = *(const u64*)&sb[c0];
        u64 acc[4] = {bi, bi, bi, bi};
#pragma unroll
        for (int ky = 0; ky < 3; ky++)
#pragma unroll
            for (int kx = 0; kx < 3; kx++) {
                u64 wp = *(const u64*)&sw[(ky * 3 + kx) * 16 + c0];
#pragma unroll
                for (int q = 0; q < 4; q++) {
                    int dy = q >> 1, dx = q & 1;
                    acc[q] = ffma2(wp, pkb(v[dy + ky][dx + kx]), acc[q]);
                }
            }
        float2 m0 = upk(acc[0]);
        float mx0 = m0.x, mx1 = m0.y;
#pragma unroll
        for (int q = 1; q < 4; q++) {
            float2 mq = upk(acc[q]);
            mx0 = fmaxf(mx0, mq.x); mx1 = fmaxf(mx1, mq.y);
        }
        g_h1[n * 3136 + c0 * 196 + p] = fmaxf(mx0, 0.f);
        g_h1[n * 3136 + (c0 + 1) * 196 + p] = fmaxf(mx1, 0.f);
    }
}

// ---------------- conv2 (16->32, 3x3 SAME) + relu + maxpool2 -----------------
// blockDim = 416; items = 392 (one per thread)
__global__ void k_conv2(const float* __restrict__ w, const float* __restrict__ b) {
    __shared__ __align__(16) float sin_[16 * 16 * 16];   // [ci][16][16]
    __shared__ __align__(16) float sw[16 * 9 * 32];      // [ci][k][oc]
    __shared__ __align__(16) float sb[32];
    const int n = blockIdx.x;
    const int t = threadIdx.x;  // 416
    for (int i = t; i < 4096; i += 416) sin_[i] = 0.f;
    for (int i = t; i < 4608; i += 416) {
        int oc = i / 144, r = i % 144, ci = r / 9, k = r % 9;
        sw[ci * 288 + k * 32 + oc] = w[i];
    }
    if (t < 32) sb[t] = b[t];
    __syncthreads();
    const float* hi = g_h1 + n * 3136;
    for (int i = t; i < 3136; i += 416) {
        int ci = i / 196, p = i % 196, y = p / 14, xx = p % 14;
        sin_[ci * 256 + (y + 1) * 16 + (xx + 1)] = hi[i];
    }
    __syncthreads();
    if (t < 392) {
        int cg = t / 49, p = t % 49;
        int c0 = cg * 4;
        int py = p / 7, px = p % 7;
        u64 b01 = *(const u64*)&sb[c0];
        u64 b23 = *(const u64*)&sb[c0 + 2];
        u64 acc01[4] = {b01, b01, b01, b01};
        u64 acc23[4] = {b23, b23, b23, b23};
        for (int ci = 0; ci < 16; ci++) {
            const float* ip = sin_ + ci * 256 + 2 * py * 16 + 2 * px;
            float v[4][4];
#pragma unroll
            for (int r = 0; r < 4; r++) {
                float2 a = *(const float2*)&ip[r * 16];
                float2 c = *(const float2*)&ip[r * 16 + 2];
                v[r][0] = a.x; v[r][1] = a.y; v[r][2] = c.x; v[r][3] = c.y;
            }
            const float* wp0 = sw + ci * 288 + c0;
#pragma unroll
            for (int ky = 0; ky < 3; ky++)
#pragma unroll
                for (int kx = 0; kx < 3; kx++) {
                    u64 w01 = *(const u64*)&wp0[(ky * 3 + kx) * 32];
                    u64 w23 = *(const u64*)&wp0[(ky * 3 + kx) * 32 + 2];
#pragma unroll
                    for (int q = 0; q < 4; q++) {
                        int dy = q >> 1, dx = q & 1;
                        u64 vb = pkb(v[dy + ky][dx + kx]);
                        acc01[q] = ffma2(w01, vb, acc01[q]);
                        acc23[q] = ffma2(w23, vb, acc23[q]);
                    }
                }
        }
        float2 a0 = upk(acc01[0]), b0 = upk(acc23[0]);
        float m0 = a0.x, m1 = a0.y, m2 = b0.x, m3 = b0.y;
#pragma unroll
        for (int q = 1; q < 4; q++) {
            float2 aq = upk(acc01[q]), bq = upk(acc23[q]);
            m0 = fmaxf(m0, aq.x); m1 = fmaxf(m1, aq.y);
            m2 = fmaxf(m2, bq.x); m3 = fmaxf(m3, bq.y);
        }
        float* outp = g_h2 + (size_t)n * GIN + c0 * 49 + p;
        outp[0]   = fmaxf(m0, 0.f);
        outp[49]  = fmaxf(m1, 0.f);
        outp[98]  = fmaxf(m2, 0.f);
        outp[147] = fmaxf(m3, 0.f);
    }
}

// ---- TF32 tensor-core dual-weight GEMM: C{0,1} = A @ B{0,1} + bias{0,1} -----
// BM=128, BN=64, BK=32; 128 threads = 4 warps (2x2); warp tile 64x32 of m16n8k8.
__global__ void k_gemm_tc(const float* __restrict__ A,
                          const float* __restrict__ B0, const float* __restrict__ B1,
                          const float* __restrict__ bias0, const float* __restrict__ bias1,
                          float* __restrict__ C0, float* __restrict__ C1,
                          int K, int NC) {
    constexpr int BM = 128, BN = 64, BK = 32;
    constexpr int BKP = BK + 4;
    constexpr int BNP = BN + 4;
    __shared__ __align__(16) unsigned As[BM][BKP];
    __shared__ __align__(16) unsigned Bs[BK][BNP];
    const int t = threadIdx.x, lane = t & 31, w = t >> 5;
    const int wm = (w >> 1) * 64, wn = (w & 1) * 32;
    const int ncolb = NC / BN;
    const int which = blockIdx.x / ncolb;
    const int bn = (blockIdx.x % ncolb) * BN;
    const int bm = blockIdx.y * BM;
    const float* B = which ? B1 : B0;
    const float* bias = which ? bias1 : bias0;
    float* C = which ? C1 : C0;

    float acc[4][4][4];
#pragma unroll
    for (int mt = 0; mt < 4; mt++)
#pragma unroll
        for (int nt = 0; nt < 4; nt++)
#pragma unroll
            for (int c = 0; c < 4; c++) acc[mt][nt][c] = 0.f;

    const float* arow = A + (size_t)(bm + t) * K;
    const int brow = t >> 2, bcol = (t & 3) * 16;

    for (int k0 = 0; k0 < K; k0 += BK) {
#pragma unroll
        for (int j = 0; j < BK; j += 4) {
            float4 v = *(const float4*)&arow[k0 + j];
            uint4 u = make_uint4(cvt_tf32(v.x), cvt_tf32(v.y), cvt_tf32(v.z), cvt_tf32(v.w));
            *(uint4*)&As[t][j] = u;
        }
        const float* bp = B + (size_t)(k0 + brow) * NC + bn + bcol;
#pragma unroll
        for (int j = 0; j < 16; j += 4) {
            float4 v = *(const float4*)&bp[j];
            uint4 u = make_uint4(cvt_tf32(v.x), cvt_tf32(v.y), cvt_tf32(v.z), cvt_tf32(v.w));
            *(uint4*)&Bs[brow][bcol + j] = u;
        }
        __syncthreads();
#pragma unroll
        for (int ks = 0; ks < BK / 8; ks++) {
            const int kk = ks * 8;
            unsigned af[4][4], bf[4][2];
#pragma unroll
            for (int mt = 0; mt < 4; mt++) {
                int r = wm + mt * 16 + (lane >> 2);
                int c = kk + (lane & 3);
                af[mt][0] = As[r][c];
                af[mt][1] = As[r + 8][c];
                af[mt][2] = As[r][c + 4];
                af[mt][3] = As[r + 8][c + 4];
            }
#pragma unroll
            for (int nt = 0; nt < 4; nt++) {
                int c = wn + nt * 8 + (lane >> 2);
                bf[nt][0] = Bs[kk + (lane & 3)][c];
                bf[nt][1] = Bs[kk + (lane & 3) + 4][c];
            }
#pragma unroll
            for (int mt = 0; mt < 4; mt++)
#pragma unroll
                for (int nt = 0; nt < 4; nt++)
                    mma_tf32(acc[mt][nt], af[mt], bf[nt]);
        }
        __syncthreads();
    }
#pragma unroll
    for (int nt = 0; nt < 4; nt++) {
        int col = bn + wn + nt * 8 + 2 * (lane & 3);
        float2 bv = *(const float2*)&bias[col];
#pragma unroll
        for (int mt = 0; mt < 4; mt++) {
            int r = bm + wm + mt * 16 + (lane >> 2);
            *(float2*)&C[(size_t)r * NC + col] =
                make_float2(acc[mt][nt][0] + bv.x, acc[mt][nt][1] + bv.y);
            *(float2*)&C[(size_t)(r + 8) * NC + col] =
                make_float2(acc[mt][nt][2] + bv.x, acc[mt][nt][3] + bv.y);
        }
    }
}

// ---------------- GAT layer 1: fused gather, 2-edge pipelined ----------------
// warp per destination node; lanes 0-15 = head0, 16-31 = head1 (4 ch each)
__global__ void k_gat1(const float* __restrict__ att, const float* __restrict__ bias) {
    int d = (blockIdx.x * blockDim.x + threadIdx.x) >> 5;
    int lane = threadIdx.x & 31;
    if (d >= NN) return;
    const float4 at = *(const float4*)&att[lane * 4];
    float4 xr = *(const float4*)&g_xr1[(size_t)d * 128 + lane * 4];
    float4 xd = *(const float4*)&g_xl1[(size_t)d * 128 + lane * 4];
    // self loop
    float a = lrelu(xd.x + xr.x) * at.x + lrelu(xd.y + xr.y) * at.y +
              lrelu(xd.z + xr.z) * at.z + lrelu(xd.w + xr.w) * at.w;
    a += __shfl_xor_sync(0xffffffffu, a, 8);
    a += __shfl_xor_sync(0xffffffffu, a, 4);
    a += __shfl_xor_sync(0xffffffffu, a, 2);
    a += __shfl_xor_sync(0xffffffffu, a, 1);
    float ex = __expf(a);
    float den = ex;
    float4 acc = make_float4(ex * xd.x, ex * xd.y, ex * xd.z, ex * xd.w);

    const int i0 = g_roff[d], i1 = g_roff[d + 1];
    int i = i0;
    // 2-edge pipelined main loop: both gathers in flight, reduces interleaved
    for (; i + 1 < i1; i += 2) {
        int s0 = g_esrc[i];
        int s1 = g_esrc[i + 1];
        float4 x0 = *(const float4*)&g_xl1[(size_t)s0 * 128 + lane * 4];
        float4 x1 = *(const float4*)&g_xl1[(size_t)s1 * 128 + lane * 4];
        float a0 = lrelu(x0.x + xr.x) * at.x + lrelu(x0.y + xr.y) * at.y +
                   lrelu(x0.z + xr.z) * at.z + lrelu(x0.w + xr.w) * at.w;
        float a1 = lrelu(x1.x + xr.x) * at.x + lrelu(x1.y + xr.y) * at.y +
                   lrelu(x1.z + xr.z) * at.z + lrelu(x1.w + xr.w) * at.w;
        a0 += __shfl_xor_sync(0xffffffffu, a0, 8);
        a1 += __shfl_xor_sync(0xffffffffu, a1, 8);
        a0 += __shfl_xor_sync(0xffffffffu, a0, 4);
        a1 += __shfl_xor_sync(0xffffffffu, a1, 4);
        a0 += __shfl_xor_sync(0xffffffffu, a0, 2);
        a1 += __shfl_xor_sync(0xffffffffu, a1, 2);
        a0 += __shfl_xor_sync(0xffffffffu, a0, 1);
        a1 += __shfl_xor_sync(0xffffffffu, a1, 1);
        float e0 = __expf(a0);
        float e1 = __expf(a1);
        den += e0 + e1;
        acc.x += e0 * x0.x + e1 * x1.x;
        acc.y += e0 * x0.y + e1 * x1.y;
        acc.z += e0 * x0.z + e1 * x1.z;
        acc.w += e0 * x0.w + e1 * x1.w;
    }
    if (i < i1) {
        int s = g_esrc[i];
        float4 xs = *(const float4*)&g_xl1[(size_t)s * 128 + lane * 4];
        float a2 = lrelu(xs.x + xr.x) * at.x + lrelu(xs.y + xr.y) * at.y +
                   lrelu(xs.z + xr.z) * at.z + lrelu(xs.w + xr.w) * at.w;
        a2 += __shfl_xor_sync(0xffffffffu, a2, 8);
        a2 += __shfl_xor_sync(0xffffffffu, a2, 4);
        a2 += __shfl_xor_sync(0xffffffffu, a2, 2);
        a2 += __shfl_xor_sync(0xffffffffu, a2, 1);
        float e2 = __expf(a2);
        den += e2;
        acc.x += e2 * xs.x; acc.y += e2 * xs.y;
        acc.z += e2 * xs.z; acc.w += e2 * xs.w;
    }
    float inv = 1.f / den;
    float4 bv = *(const float4*)&bias[lane * 4];
    float4 o;
    o.x = fmaxf(acc.x * inv + bv.x, 0.f);
    o.y = fmaxf(acc.y * inv + bv.y, 0.f);
    o.z = fmaxf(acc.z * inv + bv.z, 0.f);
    o.w = fmaxf(acc.w * inv + bv.w, 0.f);
    *(float4*)&g_o1[(size_t)d * 128 + lane * 4] = o;
}

// ---------------- GAT layer 2: fused gather, 2-edge pipelined ----------------
__global__ void k_gat2(const float* __restrict__ att) {
    int d = (blockIdx.x * blockDim.x + threadIdx.x) >> 5;
    int lane = threadIdx.x & 31;
    if (d >= NN) return;
    const float2 at = *(const float2*)&att[lane * 2];
    float2 xr = *(const float2*)&g_xr2[(size_t)d * 64 + lane * 2];
    float2 xd = *(const float2*)&g_xl2[(size_t)d * 64 + lane * 2];
    float a = lrelu(xd.x + xr.x) * at.x + lrelu(xd.y + xr.y) * at.y;
    a += __shfl_xor_sync(0xffffffffu, a, 16);
    a += __shfl_xor_sync(0xffffffffu, a, 8);
    a += __shfl_xor_sync(0xffffffffu, a, 4);
    a += __shfl_xor_sync(0xffffffffu, a, 2);
    a += __shfl_xor_sync(0xffffffffu, a, 1);
    float ex = __expf(a);
    float den = ex;
    float2 acc = make_float2(ex * xd.x, ex * xd.y);

    const int i0 = g_roff[d], i1 = g_roff[d + 1];
    int i = i0;
    for (; i + 1 < i1; i += 2) {
        int s0 = g_esrc[i];
        int s1 = g_esrc[i + 1];
        float2 x0 = *(const float2*)&g_xl2[(size_t)s0 * 64 + lane * 2];
        float2 x1 = *(const float2*)&g_xl2[(size_t)s1 * 64 + lane * 2];
        float a0 = lrelu(x0.x + xr.x) * at.x + lrelu(x0.y + xr.y) * at.y;
        float a1 = lrelu(x1.x + xr.x) * at.x + lrelu(x1.y + xr.y) * at.y;
        a0 += __shfl_xor_sync(0xffffffffu, a0, 16);
        a1 += __shfl_xor_sync(0xffffffffu, a1, 16);
        a0 += __shfl_xor_sync(0xffffffffu, a0, 8);
        a1 += __shfl_xor_sync(0xffffffffu, a1, 8);
        a0 += __shfl_xor_sync(0xffffffffu, a0, 4);
        a1 += __shfl_xor_sync(0xffffffffu, a1, 4);
        a0 += __shfl_xor_sync(0xffffffffu, a0, 2);
        a1 += __shfl_xor_sync(0xffffffffu, a1, 2);
        a0 += __shfl_xor_sync(0xffffffffu, a0, 1);
        a1 += __shfl_xor_sync(0xffffffffu, a1, 1);
        float e0 = __expf(a0);
        float e1 = __expf(a1);
        den += e0 + e1;
        acc.x += e0 * x0.x + e1 * x1.x;
        acc.y += e0 * x0.y + e1 * x1.y;
    }
    if (i < i1) {
        int s = g_esrc[i];
        float2 xs = *(const float2*)&g_xl2[(size_t)s * 64 + lane * 2];
        float a2 = lrelu(xs.x + xr.x) * at.x + lrelu(xs.y + xr.y) * at.y;
        a2 += __shfl_xor_sync(0xffffffffu, a2, 16);
        a2 += __shfl_xor_sync(0xffffffffu, a2, 8);
        a2 += __shfl_xor_sync(0xffffffffu, a2, 4);
        a2 += __shfl_xor_sync(0xffffffffu, a2, 2);
        a2 += __shfl_xor_sync(0xffffffffu, a2, 1);
        float e2 = __expf(a2);
        den += e2;
        acc.x += e2 * xs.x; acc.y += e2 * xs.y;
    }
    float inv = 1.f / den;
    *(float2*)&g_o2[(size_t)d * 64 + lane * 2] = make_float2(acc.x * inv, acc.y * inv);
}

// ---------------- classifier: (o2 + bias2) @ Wc + bc -------------------------
__global__ void k_cls(const float* __restrict__ Wc, const float* __restrict__ bc,
                      const float* __restrict__ bias2, float* __restrict__ out) {
    int i = blockIdx.x * blockDim.x + threadIdx.x;
    if (i >= NN * 10) return;
    int n = i / 10, j = i % 10;
    const float* r = g_o2 + (size_t)n * 64;
    float acc = bc[j];
#pragma unroll
    for (int c = 0; c < 64; c++) acc += (r[c] + bias2[c]) * Wc[c * 10 + j];
    out[i] = acc;
}

// ---------------- launcher ----------------------------------------------------
extern "C" void kernel_launch(void* const* d_in, const int* in_sizes, int n_in,
                              void* d_out, int out_size) {
    const float* x = (const float*)d_in[0];
    const int* ei = (const int*)d_in[1];
    const float* c1w = (const float*)d_in[2];
    const float* c1b = (const float*)d_in[3];
    const float* c2w = (const float*)d_in[4];
    const float* c2b = (const float*)d_in[5];
    const float* Wl1 = (const float*)d_in[6];
    const float* bl1 = (const float*)d_in[7];
    const float* Wr1 = (const float*)d_in[8];
    const float* br1 = (const float*)d_in[9];
    const float* att1 = (const float*)d_in[10];
    const float* bias1 = (const float*)d_in[11];
    const float* Wl2 = (const float*)d_in[12];
    const float* bl2 = (const float*)d_in[13];
    const float* Wr2 = (const float*)d_in[14];
    const float* br2 = (const float*)d_in[15];
    const float* att2 = (const float*)d_in[16];
    const float* bias2 = (const float*)d_in[17];
    const float* Wc = (const float*)d_in[18];
    const float* bc = (const float*)d_in[19];
    float* out = (float*)d_out;

    void *ph2, *pxl1, *pxr1, *po1, *pxl2, *pxr2;
    cudaGetSymbolAddress(&ph2, g_h2);
    cudaGetSymbolAddress(&pxl1, g_xl1);
    cudaGetSymbolAddress(&pxr1, g_xr1);
    cudaGetSymbolAddress(&po1, g_o1);
    cudaGetSymbolAddress(&pxl2, g_xl2);
    cudaGetSymbolAddress(&pxr2, g_xr2);

    // CSR build (independent of conv path)
    k_zero_deg<<<NN / 256, 256>>>();
    k_hist<<<EE / 256, 256>>>(ei);
    k_scan<<<1, 1024>>>();
    k_scatter<<<EE / 256, 256>>>(ei);
    // CNN (round-5 proven kernels)
    k_conv1<<<NN, 256>>>(x, c1w, c1b);
    k_conv2<<<NN, 416>>>(c2w, c2b);
    // big fused GEMM (TF32 tensor cores): NC=128 -> 2 colblocks x 2 weights
    k_gemm_tc<<<dim3(4, NN / 128), 128>>>(
        (const float*)ph2, Wl1, Wr1, bl1, br1, (float*)pxl1, (float*)pxr1, GIN, 128);
    k_gat1<<<NN / 8, 256>>>(att1, bias1);
    // small fused GEMM (TF32): NC=64 -> 1 colblock x 2 weights
    k_gemm_tc<<<dim3(2, NN / 128), 128>>>(
        (const float*)po1, Wl2, Wr2, bl2, br2, (float*)pxl2, (float*)pxr2, 128, 64);
    k_gat2<<<NN / 8, 256>>>(att2);
    k_cls<<<(NN * 10 + 255) / 256, 256>>>(Wc, bc, bias2, out);
}

// round 10
// speedup vs baseline: 1.3985x; 1.0037x over previous
#include <cuda_runtime.h>
#include <cuda_bf16.h>
#include <math.h>

#define NN 16384
#define EE 524288
#define GIN 1568       // 32*7*7

typedef unsigned long long u64;

// ---------------- packed / tf32 helpers ---------------------------------------
__device__ __forceinline__ u64 pk2(float x, float y) {
    u64 r; asm("mov.b64 %0, {%1,%2};" : "=l"(r) : "f"(x), "f"(y)); return r;
}
__device__ __forceinline__ u64 pkb(float x) { return pk2(x, x); }
__device__ __forceinline__ u64 ffma2(u64 a, u64 b, u64 c) {
    u64 d; asm("fma.rn.f32x2 %0, %1, %2, %3;" : "=l"(d) : "l"(a), "l"(b), "l"(c)); return d;
}
__device__ __forceinline__ float2 upk(u64 v) {
    float2 r; asm("mov.b64 {%0,%1}, %2;" : "=f"(r.x), "=f"(r.y) : "l"(v)); return r;
}
__device__ __forceinline__ unsigned cvt_tf32(float f) {
    unsigned r; asm("cvt.rna.tf32.f32 %0, %1;" : "=r"(r) : "f"(f)); return r;
}
__device__ __forceinline__ void mma_tf32(float* d, const unsigned* a, const unsigned* b) {
    asm volatile(
        "mma.sync.aligned.m16n8k8.row.col.f32.tf32.tf32.f32 "
        "{%0,%1,%2,%3}, {%4,%5,%6,%7}, {%8,%9}, {%0,%1,%2,%3};"
        : "+f"(d[0]), "+f"(d[1]), "+f"(d[2]), "+f"(d[3])
        : "r"(a[0]), "r"(a[1]), "r"(a[2]), "r"(a[3]), "r"(b[0]), "r"(b[1]));
}

// ---------------- scratch (device globals; no allocs allowed) ----------------
__device__ float g_h1[NN * 16 * 14 * 14];  // conv1+pool output
__device__ float g_h2[NN * GIN];           // conv2+pool output (flattened NCHW)
__device__ float g_xl1[NN * 128];
__device__ float g_xr1[NN * 128];
__device__ float g_o1[NN * 128];           // gat1 out (bias+relu fused)
__device__ float g_xl2[NN * 64];
__device__ float g_xr2[NN * 64];
__device__ float g_o2[NN * 64];            // gat2 out (pre-bias)
// CSR by destination
__device__ int g_deg[NN];                  // histogram, then scatter cursor
__device__ int g_roff[NN + 1];
__device__ int g_esrc[EE];

__device__ __forceinline__ float lrelu(float v) { return v > 0.f ? v : 0.2f * v; }

// ---------------- CSR build ---------------------------------------------------
__global__ void k_zero_deg() {
    int i = blockIdx.x * blockDim.x + threadIdx.x;
    if (i < NN) g_deg[i] = 0;
}

__global__ void k_hist(const int* __restrict__ ei) {
    int e = blockIdx.x * blockDim.x + threadIdx.x;
    if (e < EE) atomicAdd(&g_deg[ei[EE + e]], 1);
}

// single CTA, 1024 threads, 16 nodes/thread exclusive scan
__global__ void k_scan() {
    __shared__ int wsum[32];
    int t = threadIdx.x, lane = t & 31, wid = t >> 5;
    int base = t * 16;
    int c[16];
    int s = 0;
#pragma unroll
    for (int i = 0; i < 16; i++) { c[i] = s; s += g_deg[base + i]; }
    int v = s;
#pragma unroll
    for (int off = 1; off < 32; off <<= 1) {
        int n = __shfl_up_sync(0xffffffffu, v, off);
        if (lane >= off) v += n;
    }
    if (lane == 31) wsum[wid] = v;
    __syncthreads();
    if (wid == 0) {
        int w = wsum[lane];
#pragma unroll
        for (int off = 1; off < 32; off <<= 1) {
            int n = __shfl_up_sync(0xffffffffu, w, off);
            if (lane >= off) w += n;
        }
        wsum[lane] = w;  // inclusive
    }
    __syncthreads();
    int wbase = (wid == 0) ? 0 : wsum[wid - 1];
    int tbase = wbase + (v - s);  // exclusive base for this thread
#pragma unroll
    for (int i = 0; i < 16; i++) {
        int r = tbase + c[i];
        g_roff[base + i] = r;
        g_deg[base + i] = r;   // cursor for scatter
    }
    if (t == 1023) g_roff[NN] = EE;
}

__global__ void k_scatter(const int* __restrict__ ei) {
    int e = blockIdx.x * blockDim.x + threadIdx.x;
    if (e >= EE) return;
    int d = ei[EE + e];
    int pos = atomicAdd(&g_deg[d], 1);
    g_esrc[pos] = ei[e];
}

// ---------------- conv1 (1->16, 3x3 SAME) + relu + maxpool2 ------------------
__global__ void k_conv1(const float* __restrict__ x, const float* __restrict__ w,
                        const float* __restrict__ b) {
    __shared__ __align__(16) float sin_[30 * 30];
    __shared__ __align__(16) float sw[9 * 16];   // [k][oc]
    __shared__ __align__(16) float sb[16];
    const int n = blockIdx.x;
    const int t = threadIdx.x;  // 256
    for (int i = t; i < 900; i += 256) sin_[i] = 0.f;
    if (t < 144) { int oc = t / 9, k = t % 9; sw[k * 16 + oc] = w[t]; }
    if (t < 16) sb[t] = b[t];
    __syncthreads();
    const float* xi = x + n * 784;
    for (int i = t; i < 784; i += 256) {
        int y = i / 28, xx = i % 28;
        sin_[(y + 1) * 30 + xx + 1] = xi[i];
    }
    __syncthreads();
    for (int item = t; item < 8 * 196; item += 256) {
        int cp = item / 196, p = item % 196;
        int c0 = cp * 2;
        int py = p / 14, px = p % 14;
        float v[4][4];
#pragma unroll
        for (int r = 0; r < 4; r++) {
            float2 a = *(const float2*)&sin_[(2 * py + r) * 30 + 2 * px];
            float2 c = *(const float2*)&sin_[(2 * py + r) * 30 + 2 * px + 2];
            v[r][0] = a.x; v[r][1] = a.y; v[r][2] = c.x; v[r][3] = c.y;
        }
        u64 bi = *(const u64*)&sb[c0];
        u64 acc[4] = {bi, bi, bi, bi};
#pragma unroll
        for (int ky = 0; ky < 3; ky++)
#pragma unroll
            for (int kx = 0; kx < 3; kx++) {
                u64 wp = *(const u64*)&sw[(ky * 3 + kx) * 16 + c0];
#pragma unroll
                for (int q = 0; q < 4; q++) {
                    int dy = q >> 1, dx = q & 1;
                    acc[q] = ffma2(wp, pkb(v[dy + ky][dx + kx]), acc[q]);
                }
            }
        float2 m0 = upk(acc[0]);
        float mx0 = m0.x, mx1 = m0.y;
#pragma unroll
        for (int q = 1; q < 4; q++) {
            float2 mq = upk(acc[q]);
            mx0 = fmaxf(mx0, mq.x); mx1 = fmaxf(mx1, mq.y);
        }
        g_h1[n * 3136 + c0 * 196 + p] = fmaxf(mx0, 0.f);
        g_h1[n * 3136 + (c0 + 1) * 196 + p] = fmaxf(mx1, 0.f);
    }
}

// ---------------- conv2 (16->32, 3x3 SAME) + relu + maxpool2 -----------------
// grid (2, NN): x = output-channel half (16 oc), y = image. 256 threads.
// smem 25.3KB -> 3-4 CTAs/SM resident (vs 1 before) for latency hiding.
__global__ void k_conv2(const float* __restrict__ w, const float* __restrict__ b) {
    __shared__ __align__(16) float sin_[16 * 256];   // [ci][16][16]
    __shared__ __align__(16) float sw[16 * 144];     // [ci][k][16 local oc]
    __shared__ __align__(16) float sb[16];
    const int half = blockIdx.x;
    const int n = blockIdx.y;
    const int oc0 = half * 16;
    const int t = threadIdx.x;  // 256
    for (int i = t; i < 4096; i += 256) sin_[i] = 0.f;
    for (int i = t; i < 2304; i += 256) {
        int ocl = i / 144, r = i % 144, ci = r / 9, k = r % 9;
        sw[ci * 144 + k * 16 + ocl] = w[(oc0 + ocl) * 144 + r];
    }
    if (t < 16) sb[t] = b[oc0 + t];
    __syncthreads();
    const float* hi = g_h1 + n * 3136;
    for (int i = t; i < 3136; i += 256) {
        int ci = i / 196, p = i % 196, y = p / 14, xx = p % 14;
        sin_[ci * 256 + (y + 1) * 16 + (xx + 1)] = hi[i];
    }
    __syncthreads();
    if (t < 196) {
        int cg = t / 49, p = t % 49;
        int c0 = cg * 4;                 // local oc base (0,4,8,12)
        int py = p / 7, px = p % 7;
        u64 b01 = *(const u64*)&sb[c0];
        u64 b23 = *(const u64*)&sb[c0 + 2];
        u64 acc01[4] = {b01, b01, b01, b01};
        u64 acc23[4] = {b23, b23, b23, b23};
        for (int ci = 0; ci < 16; ci++) {
            const float* ip = sin_ + ci * 256 + 2 * py * 16 + 2 * px;
            float v[4][4];
#pragma unroll
            for (int r = 0; r < 4; r++) {
                float2 a = *(const float2*)&ip[r * 16];
                float2 c = *(const float2*)&ip[r * 16 + 2];
                v[r][0] = a.x; v[r][1] = a.y; v[r][2] = c.x; v[r][3] = c.y;
            }
            const float* wp0 = sw + ci * 144 + c0;
#pragma unroll
            for (int ky = 0; ky < 3; ky++)
#pragma unroll
                for (int kx = 0; kx < 3; kx++) {
                    u64 w01 = *(const u64*)&wp0[(ky * 3 + kx) * 16];
                    u64 w23 = *(const u64*)&wp0[(ky * 3 + kx) * 16 + 2];
#pragma unroll
                    for (int q = 0; q < 4; q++) {
                        int dy = q >> 1, dx = q & 1;
                        u64 vb = pkb(v[dy + ky][dx + kx]);
                        acc01[q] = ffma2(w01, vb, acc01[q]);
                        acc23[q] = ffma2(w23, vb, acc23[q]);
                    }
                }
        }
        float2 a0 = upk(acc01[0]), b0 = upk(acc23[0]);
        float m0 = a0.x, m1 = a0.y, m2 = b0.x, m3 = b0.y;
#pragma unroll
        for (int q = 1; q < 4; q++) {
            float2 aq = upk(acc01[q]), bq = upk(acc23[q]);
            m0 = fmaxf(m0, aq.x); m1 = fmaxf(m1, aq.y);
            m2 = fmaxf(m2, bq.x); m3 = fmaxf(m3, bq.y);
        }
        float* outp = g_h2 + (size_t)n * GIN + (oc0 + c0) * 49 + p;
        outp[0]   = fmaxf(m0, 0.f);
        outp[49]  = fmaxf(m1, 0.f);
        outp[98]  = fmaxf(m2, 0.f);
        outp[147] = fmaxf(m3, 0.f);
    }
}

// ---- TF32 tensor-core dual-weight GEMM: C{0,1} = A @ B{0,1} + bias{0,1} -----
// BM=128, BN=64, BK=32; 128 threads = 4 warps (2x2); warp tile 64x32 of m16n8k8.
__global__ void k_gemm_tc(const float* __restrict__ A,
                          const float* __restrict__ B0, const float* __restrict__ B1,
                          const float* __restrict__ bias0, const float* __restrict__ bias1,
                          float* __restrict__ C0, float* __restrict__ C1,
                          int K, int NC) {
    constexpr int BM = 128, BN = 64, BK = 32;
    constexpr int BKP = BK + 4;
    constexpr int BNP = BN + 4;
    __shared__ __align__(16) unsigned As[BM][BKP];
    __shared__ __align__(16) unsigned Bs[BK][BNP];
    const int t = threadIdx.x, lane = t & 31, w = t >> 5;
    const int wm = (w >> 1) * 64, wn = (w & 1) * 32;
    const int ncolb = NC / BN;
    const int which = blockIdx.x / ncolb;
    const int bn = (blockIdx.x % ncolb) * BN;
    const int bm = blockIdx.y * BM;
    const float* B = which ? B1 : B0;
    const float* bias = which ? bias1 : bias0;
    float* C = which ? C1 : C0;

    float acc[4][4][4];
#pragma unroll
    for (int mt = 0; mt < 4; mt++)
#pragma unroll
        for (int nt = 0; nt < 4; nt++)
#pragma unroll
            for (int c = 0; c < 4; c++) acc[mt][nt][c] = 0.f;

    const float* arow = A + (size_t)(bm + t) * K;
    const int brow = t >> 2, bcol = (t & 3) * 16;

    for (int k0 = 0; k0 < K; k0 += BK) {
#pragma unroll
        for (int j = 0; j < BK; j += 4) {
            float4 v = *(const float4*)&arow[k0 + j];
            uint4 u = make_uint4(cvt_tf32(v.x), cvt_tf32(v.y), cvt_tf32(v.z), cvt_tf32(v.w));
            *(uint4*)&As[t][j] = u;
        }
        const float* bp = B + (size_t)(k0 + brow) * NC + bn + bcol;
#pragma unroll
        for (int j = 0; j < 16; j += 4) {
            float4 v = *(const float4*)&bp[j];
            uint4 u = make_uint4(cvt_tf32(v.x), cvt_tf32(v.y), cvt_tf32(v.z), cvt_tf32(v.w));
            *(uint4*)&Bs[brow][bcol + j] = u;
        }
        __syncthreads();
#pragma unroll
        for (int ks = 0; ks < BK / 8; ks++) {
            const int kk = ks * 8;
            unsigned af[4][4], bf[4][2];
#pragma unroll
            for (int mt = 0; mt < 4; mt++) {
                int r = wm + mt * 16 + (lane >> 2);
                int c = kk + (lane & 3);
                af[mt][0] = As[r][c];
                af[mt][1] = As[r + 8][c];
                af[mt][2] = As[r][c + 4];
                af[mt][3] = As[r + 8][c + 4];
            }
#pragma unroll
            for (int nt = 0; nt < 4; nt++) {
                int c = wn + nt * 8 + (lane >> 2);
                bf[nt][0] = Bs[kk + (lane & 3)][c];
                bf[nt][1] = Bs[kk + (lane & 3) + 4][c];
            }
#pragma unroll
            for (int mt = 0; mt < 4; mt++)
#pragma unroll
                for (int nt = 0; nt < 4; nt++)
                    mma_tf32(acc[mt][nt], af[mt], bf[nt]);
        }
        __syncthreads();
    }
#pragma unroll
    for (int nt = 0; nt < 4; nt++) {
        int col = bn + wn + nt * 8 + 2 * (lane & 3);
        float2 bv = *(const float2*)&bias[col];
#pragma unroll
        for (int mt = 0; mt < 4; mt++) {
            int r = bm + wm + mt * 16 + (lane >> 2);
            *(float2*)&C[(size_t)r * NC + col] =
                make_float2(acc[mt][nt][0] + bv.x, acc[mt][nt][1] + bv.y);
            *(float2*)&C[(size_t)(r + 8) * NC + col] =
                make_float2(acc[mt][nt][2] + bv.x, acc[mt][nt][3] + bv.y);
        }
    }
}

// ---------------- GAT layer 1: fused gather, 2-edge pipelined ----------------
__global__ void k_gat1(const float* __restrict__ att, const float* __restrict__ bias) {
    int d = (blockIdx.x * blockDim.x + threadIdx.x) >> 5;
    int lane = threadIdx.x & 31;
    if (d >= NN) return;
    const float4 at = *(const float4*)&att[lane * 4];
    float4 xr = *(const float4*)&g_xr1[(size_t)d * 128 + lane * 4];
    float4 xd = *(const float4*)&g_xl1[(size_t)d * 128 + lane * 4];
    float a = lrelu(xd.x + xr.x) * at.x + lrelu(xd.y + xr.y) * at.y +
              lrelu(xd.z + xr.z) * at.z + lrelu(xd.w + xr.w) * at.w;
    a += __shfl_xor_sync(0xffffffffu, a, 8);
    a += __shfl_xor_sync(0xffffffffu, a, 4);
    a += __shfl_xor_sync(0xffffffffu, a, 2);
    a += __shfl_xor_sync(0xffffffffu, a, 1);
    float ex = __expf(a);
    float den = ex;
    float4 acc = make_float4(ex * xd.x, ex * xd.y, ex * xd.z, ex * xd.w);

    const int i0 = g_roff[d], i1 = g_roff[d + 1];
    int i = i0;
    for (; i + 1 < i1; i += 2) {
        int s0 = g_esrc[i];
        int s1 = g_esrc[i + 1];
        float4 x0 = *(const float4*)&g_xl1[(size_t)s0 * 128 + lane * 4];
        float4 x1 = *(const float4*)&g_xl1[(size_t)s1 * 128 + lane * 4];
        float a0 = lrelu(x0.x + xr.x) * at.x + lrelu(x0.y + xr.y) * at.y +
                   lrelu(x0.z + xr.z) * at.z + lrelu(x0.w + xr.w) * at.w;
        float a1 = lrelu(x1.x + xr.x) * at.x + lrelu(x1.y + xr.y) * at.y +
                   lrelu(x1.z + xr.z) * at.z + lrelu(x1.w + xr.w) * at.w;
        a0 += __shfl_xor_sync(0xffffffffu, a0, 8);
        a1 += __shfl_xor_sync(0xffffffffu, a1, 8);
        a0 += __shfl_xor_sync(0xffffffffu, a0, 4);
        a1 += __shfl_xor_sync(0xffffffffu, a1, 4);
        a0 += __shfl_xor_sync(0xffffffffu, a0, 2);
        a1 += __shfl_xor_sync(0xffffffffu, a1, 2);
        a0 += __shfl_xor_sync(0xffffffffu, a0, 1);
        a1 += __shfl_xor_sync(0xffffffffu, a1, 1);
        float e0 = __expf(a0);
        float e1 = __expf(a1);
        den += e0 + e1;
        acc.x += e0 * x0.x + e1 * x1.x;
        acc.y += e0 * x0.y + e1 * x1.y;
        acc.z += e0 * x0.z + e1 * x1.z;
        acc.w += e0 * x0.w + e1 * x1.w;
    }
    if (i < i1) {
        int s = g_esrc[i];
        float4 xs = *(const float4*)&g_xl1[(size_t)s * 128 + lane * 4];
        float a2 = lrelu(xs.x + xr.x) * at.x + lrelu(xs.y + xr.y) * at.y +
                   lrelu(xs.z + xr.z) * at.z + lrelu(xs.w + xr.w) * at.w;
        a2 += __shfl_xor_sync(0xffffffffu, a2, 8);
        a2 += __shfl_xor_sync(0xffffffffu, a2, 4);
        a2 += __shfl_xor_sync(0xffffffffu, a2, 2);
        a2 += __shfl_xor_sync(0xffffffffu, a2, 1);
        float e2 = __expf(a2);
        den += e2;
        acc.x += e2 * xs.x; acc.y += e2 * xs.y;
        acc.z += e2 * xs.z; acc.w += e2 * xs.w;
    }
    float inv = 1.f / den;
    float4 bv = *(const float4*)&bias[lane * 4];
    float4 o;
    o.x = fmaxf(acc.x * inv + bv.x, 0.f);
    o.y = fmaxf(acc.y * inv + bv.y, 0.f);
    o.z = fmaxf(acc.z * inv + bv.z, 0.f);
    o.w = fmaxf(acc.w * inv + bv.w, 0.f);
    *(float4*)&g_o1[(size_t)d * 128 + lane * 4] = o;
}

// ---------------- GAT layer 2: fused gather, 2-edge pipelined ----------------
__global__ void k_gat2(const float* __restrict__ att) {
    int d = (blockIdx.x * blockDim.x + threadIdx.x) >> 5;
    int lane = threadIdx.x & 31;
    if (d >= NN) return;
    const float2 at = *(const float2*)&att[lane * 2];
    float2 xr = *(const float2*)&g_xr2[(size_t)d * 64 + lane * 2];
    float2 xd = *(const float2*)&g_xl2[(size_t)d * 64 + lane * 2];
    float a = lrelu(xd.x + xr.x) * at.x + lrelu(xd.y + xr.y) * at.y;
    a += __shfl_xor_sync(0xffffffffu, a, 16);
    a += __shfl_xor_sync(0xffffffffu, a, 8);
    a += __shfl_xor_sync(0xffffffffu, a, 4);
    a += __shfl_xor_sync(0xffffffffu, a, 2);
    a += __shfl_xor_sync(0xffffffffu, a, 1);
    float ex = __expf(a);
    float den = ex;
    float2 acc = make_float2(ex * xd.x, ex * xd.y);

    const int i0 = g_roff[d], i1 = g_roff[d + 1];
    int i = i0;
    for (; i + 1 < i1; i += 2) {
        int s0 = g_esrc[i];
        int s1 = g_esrc[i + 1];
        float2 x0 = *(const float2*)&g_xl2[(size_t)s0 * 64 + lane * 2];
        float2 x1 = *(const float2*)&g_xl2[(size_t)s1 * 64 + lane * 2];
        float a0 = lrelu(x0.x + xr.x) * at.x + lrelu(x0.y + xr.y) * at.y;
        float a1 = lrelu(x1.x + xr.x) * at.x + lrelu(x1.y + xr.y) * at.y;
        a0 += __shfl_xor_sync(0xffffffffu, a0, 16);
        a1 += __shfl_xor_sync(0xffffffffu, a1, 16);
        a0 += __shfl_xor_sync(0xffffffffu, a0, 8);
        a1 += __shfl_xor_sync(0xffffffffu, a1, 8);
        a0 += __shfl_xor_sync(0xffffffffu, a0, 4);
        a1 += __shfl_xor_sync(0xffffffffu, a1, 4);
        a0 += __shfl_xor_sync(0xffffffffu, a0, 2);
        a1 += __shfl_xor_sync(0xffffffffu, a1, 2);
        a0 += __shfl_xor_sync(0xffffffffu, a0, 1);
        a1 += __shfl_xor_sync(0xffffffffu, a1, 1);
        float e0 = __expf(a0);
        float e1 = __expf(a1);
        den += e0 + e1;
        acc.x += e0 * x0.x + e1 * x1.x;
        acc.y += e0 * x0.y + e1 * x1.y;
    }
    if (i < i1) {
        int s = g_esrc[i];
        float2 xs = *(const float2*)&g_xl2[(size_t)s * 64 + lane * 2];
        float a2 = lrelu(xs.x + xr.x) * at.x + lrelu(xs.y + xr.y) * at.y;
        a2 += __shfl_xor_sync(0xffffffffu, a2, 16);
        a2 += __shfl_xor_sync(0xffffffffu, a2, 8);
        a2 += __shfl_xor_sync(0xffffffffu, a2, 4);
        a2 += __shfl_xor_sync(0xffffffffu, a2, 2);
        a2 += __shfl_xor_sync(0xffffffffu, a2, 1);
        float e2 = __expf(a2);
        den += e2;
        acc.x += e2 * xs.x; acc.y += e2 * xs.y;
    }
    float inv = 1.f / den;
    *(float2*)&g_o2[(size_t)d * 64 + lane * 2] = make_float2(acc.x * inv, acc.y * inv);
}

// ---------------- classifier: (o2 + bias2) @ Wc + bc -------------------------
__global__ void k_cls(const float* __restrict__ Wc, const float* __restrict__ bc,
                      const float* __restrict__ bias2, float* __restrict__ out) {
    int i = blockIdx.x * blockDim.x + threadIdx.x;
    if (i >= NN * 10) return;
    int n = i / 10, j = i % 10;
    const float* r = g_o2 + (size_t)n * 64;
    float acc = bc[j];
#pragma unroll
    for (int c = 0; c < 64; c++) acc += (r[c] + bias2[c]) * Wc[c * 10 + j];
    out[i] = acc;
}

// ---------------- launcher ----------------------------------------------------
extern "C" void kernel_launch(void* const* d_in, const int* in_sizes, int n_in,
                              void* d_out, int out_size) {
    const float* x = (const float*)d_in[0];
    const int* ei = (const int*)d_in[1];
    const float* c1w = (const float*)d_in[2];
    const float* c1b = (const float*)d_in[3];
    const float* c2w = (const float*)d_in[4];
    const float* c2b = (const float*)d_in[5];
    const float* Wl1 = (const float*)d_in[6];
    const float* bl1 = (const float*)d_in[7];
    const float* Wr1 = (const float*)d_in[8];
    const float* br1 = (const float*)d_in[9];
    const float* att1 = (const float*)d_in[10];
    const float* bias1 = (const float*)d_in[11];
    const float* Wl2 = (const float*)d_in[12];
    const float* bl2 = (const float*)d_in[13];
    const float* Wr2 = (const float*)d_in[14];
    const float* br2 = (const float*)d_in[15];
    const float* att2 = (const float*)d_in[16];
    const float* bias2 = (const float*)d_in[17];
    const float* Wc = (const float*)d_in[18];
    const float* bc = (const float*)d_in[19];
    float* out = (float*)d_out;

    void *ph2, *pxl1, *pxr1, *po1, *pxl2, *pxr2;
    cudaGetSymbolAddress(&ph2, g_h2);
    cudaGetSymbolAddress(&pxl1, g_xl1);
    cudaGetSymbolAddress(&pxr1, g_xr1);
    cudaGetSymbolAddress(&po1, g_o1);
    cudaGetSymbolAddress(&pxl2, g_xl2);
    cudaGetSymbolAddress(&pxr2, g_xr2);

    // Launch order puts k_conv2 in the ncu-profiled slot (4th launch).
    // Dependencies preserved on the single stream: hist->scan->scatter->gat1,
    // conv1->conv2->gemm->gat1.
    k_zero_deg<<<NN / 256, 256>>>();                       // 1
    k_hist<<<EE / 256, 256>>>(ei);                         // 2
    k_conv1<<<NN, 256>>>(x, c1w, c1b);                     // 3
    k_conv2<<<dim3(2, NN), 256>>>(c2w, c2b);               // 4  <- profiled
    k_scan<<<1, 1024>>>();                                 // 5
    k_scatter<<<EE / 256, 256>>>(ei);                      // 6
    // big fused GEMM (TF32 tensor cores): NC=128 -> 2 colblocks x 2 weights
    k_gemm_tc<<<dim3(4, NN / 128), 128>>>(
        (const float*)ph2, Wl1, Wr1, bl1, br1, (float*)pxl1, (float*)pxr1, GIN, 128);
    k_gat1<<<NN / 8, 256>>>(att1, bias1);
    // small fused GEMM (TF32): NC=64 -> 1 colblock x 2 weights
    k_gemm_tc<<<dim3(2, NN / 128), 128>>>(
        (const float*)po1, Wl2, Wr2, bl2, br2, (float*)pxl2, (float*)pxr2, 128, 64);
    k_gat2<<<NN / 8, 256>>>(att2);
    k_cls<<<(NN * 10 + 255) / 256, 256>>>(Wc, bc, bias2, out);
}

// round 12
// speedup vs baseline: 1.4469x; 1.0346x over previous
#include <cuda_runtime.h>
#include <cuda_bf16.h>
#include <math.h>

#define NN 16384
#define EE 524288
#define GIN 1568       // 32*7*7

typedef unsigned long long u64;

// ---------------- packed / tf32 helpers ---------------------------------------
__device__ __forceinline__ u64 pk2(float x, float y) {
    u64 r; asm("mov.b64 %0, {%1,%2};" : "=l"(r) : "f"(x), "f"(y)); return r;
}
__device__ __forceinline__ u64 pkb(float x) { return pk2(x, x); }
__device__ __forceinline__ u64 ffma2(u64 a, u64 b, u64 c) {
    u64 d; asm("fma.rn.f32x2 %0, %1, %2, %3;" : "=l"(d) : "l"(a), "l"(b), "l"(c)); return d;
}
__device__ __forceinline__ float2 upk(u64 v) {
    float2 r; asm("mov.b64 {%0,%1}, %2;" : "=f"(r.x), "=f"(r.y) : "l"(v)); return r;
}
__device__ __forceinline__ unsigned cvt_tf32(float f) {
    unsigned r; asm("cvt.rna.tf32.f32 %0, %1;" : "=r"(r) : "f"(f)); return r;
}
__device__ __forceinline__ void mma_tf32(float* d, const unsigned* a, const unsigned* b) {
    asm volatile(
        "mma.sync.aligned.m16n8k8.row.col.f32.tf32.tf32.f32 "
        "{%0,%1,%2,%3}, {%4,%5,%6,%7}, {%8,%9}, {%0,%1,%2,%3};"
        : "+f"(d[0]), "+f"(d[1]), "+f"(d[2]), "+f"(d[3])
        : "r"(a[0]), "r"(a[1]), "r"(a[2]), "r"(a[3]), "r"(b[0]), "r"(b[1]));
}

// ---------------- scratch (device globals; no allocs allowed) ----------------
__device__ float g_h1[NN * 16 * 14 * 14];  // conv1+pool output
__device__ float g_h2[NN * GIN];           // conv2+pool output (flattened NCHW)
__device__ float g_xl1[NN * 128];
__device__ float g_xr1[NN * 128];
__device__ float g_o1[NN * 128];           // gat1 out (bias+relu fused)
__device__ float g_xl2[NN * 64];
__device__ float g_xr2[NN * 64];
__device__ float g_o2[NN * 64];            // gat2 out (pre-bias)
// CSR by destination
__device__ int g_deg[NN];                  // histogram, then scatter cursor
__device__ int g_roff[NN + 1];
__device__ int g_esrc[EE];

__device__ __forceinline__ float lrelu(float v) { return v > 0.f ? v : 0.2f * v; }

// ---------------- CSR build ---------------------------------------------------
__global__ void k_zero_deg() {
    int i = blockIdx.x * blockDim.x + threadIdx.x;
    if (i < NN) g_deg[i] = 0;
}

__global__ void k_hist(const int* __restrict__ ei) {
    int e = blockIdx.x * blockDim.x + threadIdx.x;
    if (e < EE) atomicAdd(&g_deg[ei[EE + e]], 1);
}

// single CTA, 1024 threads, 16 nodes/thread exclusive scan
__global__ void k_scan() {
    __shared__ int wsum[32];
    int t = threadIdx.x, lane = t & 31, wid = t >> 5;
    int base = t * 16;
    int c[16];
    int s = 0;
#pragma unroll
    for (int i = 0; i < 16; i++) { c[i] = s; s += g_deg[base + i]; }
    int v = s;
#pragma unroll
    for (int off = 1; off < 32; off <<= 1) {
        int n = __shfl_up_sync(0xffffffffu, v, off);
        if (lane >= off) v += n;
    }
    if (lane == 31) wsum[wid] = v;
    __syncthreads();
    if (wid == 0) {
        int w = wsum[lane];
#pragma unroll
        for (int off = 1; off < 32; off <<= 1) {
            int n = __shfl_up_sync(0xffffffffu, w, off);
            if (lane >= off) w += n;
        }
        wsum[lane] = w;  // inclusive
    }
    __syncthreads();
    int wbase = (wid == 0) ? 0 : wsum[wid - 1];
    int tbase = wbase + (v - s);  // exclusive base for this thread
#pragma unroll
    for (int i = 0; i < 16; i++) {
        int r = tbase + c[i];
        g_roff[base + i] = r;
        g_deg[base + i] = r;   // cursor for scatter
    }
    if (t == 1023) g_roff[NN] = EE;
}

__global__ void k_scatter(const int* __restrict__ ei) {
    int e = blockIdx.x * blockDim.x + threadIdx.x;
    if (e >= EE) return;
    int d = ei[EE + e];
    int pos = atomicAdd(&g_deg[d], 1);
    g_esrc[pos] = ei[e];
}

// ---------------- conv1 (1->16, 3x3 SAME) + relu + maxpool2 ------------------
__global__ void k_conv1(const float* __restrict__ x, const float* __restrict__ w,
                        const float* __restrict__ b) {
    __shared__ __align__(16) float sin_[30 * 30];
    __shared__ __align__(16) float sw[9 * 16];   // [k][oc]
    __shared__ __align__(16) float sb[16];
    const int n = blockIdx.x;
    const int t = threadIdx.x;  // 256
    for (int i = t; i < 900; i += 256) sin_[i] = 0.f;
    if (t < 144) { int oc = t / 9, k = t % 9; sw[k * 16 + oc] = w[t]; }
    if (t < 16) sb[t] = b[t];
    __syncthreads();
    const float* xi = x + n * 784;
    for (int i = t; i < 784; i += 256) {
        int y = i / 28, xx = i % 28;
        sin_[(y + 1) * 30 + xx + 1] = xi[i];
    }
    __syncthreads();
    for (int item = t; item < 8 * 196; item += 256) {
        int cp = item / 196, p = item % 196;
        int c0 = cp * 2;
        int py = p / 14, px = p % 14;
        float v[4][4];
#pragma unroll
        for (int r = 0; r < 4; r++) {
            float2 a = *(const float2*)&sin_[(2 * py + r) * 30 + 2 * px];
            float2 c = *(const float2*)&sin_[(2 * py + r) * 30 + 2 * px + 2];
            v[r][0] = a.x; v[r][1] = a.y; v[r][2] = c.x; v[r][3] = c.y;
        }
        u64 bi = *(const u64*)&sb[c0];
        u64 acc[4] = {bi, bi, bi, bi};
#pragma unroll
        for (int ky = 0; ky < 3; ky++)
#pragma unroll
            for (int kx = 0; kx < 3; kx++) {
                u64 wp = *(const u64*)&sw[(ky * 3 + kx) * 16 + c0];
#pragma unroll
                for (int q = 0; q < 4; q++) {
                    int dy = q >> 1, dx = q & 1;
                    acc[q] = ffma2(wp, pkb(v[dy + ky][dx + kx]), acc[q]);
                }
            }
        float2 m0 = upk(acc[0]);
        float mx0 = m0.x, mx1 = m0.y;
#pragma unroll
        for (int q = 1; q < 4; q++) {
            float2 mq = upk(acc[q]);
            mx0 = fmaxf(mx0, mq.x); mx1 = fmaxf(mx1, mq.y);
        }
        g_h1[n * 3136 + c0 * 196 + p] = fmaxf(mx0, 0.f);
        g_h1[n * 3136 + (c0 + 1) * 196 + p] = fmaxf(mx1, 0.f);
    }
}

// ---------------- conv2 (16->32, 3x3 SAME) + relu + maxpool2 -----------------
// grid (2, NN): x = output-channel half (16 oc), y = image. 256 threads.
__global__ void k_conv2(const float* __restrict__ w, const float* __restrict__ b) {
    __shared__ __align__(16) float sin_[16 * 256];   // [ci][16][16]
    __shared__ __align__(16) float sw[16 * 144];     // [ci][k][16 local oc]
    __shared__ __align__(16) float sb[16];
    const int half = blockIdx.x;
    const int n = blockIdx.y;
    const int oc0 = half * 16;
    const int t = threadIdx.x;  // 256
    for (int i = t; i < 4096; i += 256) sin_[i] = 0.f;
    for (int i = t; i < 2304; i += 256) {
        int ocl = i / 144, r = i % 144, ci = r / 9, k = r % 9;
        sw[ci * 144 + k * 16 + ocl] = w[(oc0 + ocl) * 144 + r];
    }
    if (t < 16) sb[t] = b[oc0 + t];
    __syncthreads();
    const float* hi = g_h1 + n * 3136;
    for (int i = t; i < 3136; i += 256) {
        int ci = i / 196, p = i % 196, y = p / 14, xx = p % 14;
        sin_[ci * 256 + (y + 1) * 16 + (xx + 1)] = hi[i];
    }
    __syncthreads();
    if (t < 196) {
        int cg = t / 49, p = t % 49;
        int c0 = cg * 4;
        int py = p / 7, px = p % 7;
        u64 b01 = *(const u64*)&sb[c0];
        u64 b23 = *(const u64*)&sb[c0 + 2];
        u64 acc01[4] = {b01, b01, b01, b01};
        u64 acc23[4] = {b23, b23, b23, b23};
        for (int ci = 0; ci < 16; ci++) {
            const float* ip = sin_ + ci * 256 + 2 * py * 16 + 2 * px;
            float v[4][4];
#pragma unroll
            for (int r = 0; r < 4; r++) {
                float2 a = *(const float2*)&ip[r * 16];
                float2 c = *(const float2*)&ip[r * 16 + 2];
                v[r][0] = a.x; v[r][1] = a.y; v[r][2] = c.x; v[r][3] = c.y;
            }
            const float* wp0 = sw + ci * 144 + c0;
#pragma unroll
            for (int ky = 0; ky < 3; ky++)
#pragma unroll
                for (int kx = 0; kx < 3; kx++) {
                    u64 w01 = *(const u64*)&wp0[(ky * 3 + kx) * 16];
                    u64 w23 = *(const u64*)&wp0[(ky * 3 + kx) * 16 + 2];
#pragma unroll
                    for (int q = 0; q < 4; q++) {
                        int dy = q >> 1, dx = q & 1;
                        u64 vb = pkb(v[dy + ky][dx + kx]);
                        acc01[q] = ffma2(w01, vb, acc01[q]);
                        acc23[q] = ffma2(w23, vb, acc23[q]);
                    }
                }
        }
        float2 a0 = upk(acc01[0]), b0 = upk(acc23[0]);
        float m0 = a0.x, m1 = a0.y, m2 = b0.x, m3 = b0.y;
#pragma unroll
        for (int q = 1; q < 4; q++) {
            float2 aq = upk(acc01[q]), bq = upk(acc23[q]);
            m0 = fmaxf(m0, aq.x); m1 = fmaxf(m1, aq.y);
            m2 = fmaxf(m2, bq.x); m3 = fmaxf(m3, bq.y);
        }
        float* outp = g_h2 + (size_t)n * GIN + (oc0 + c0) * 49 + p;
        outp[0]   = fmaxf(m0, 0.f);
        outp[49]  = fmaxf(m1, 0.f);
        outp[98]  = fmaxf(m2, 0.f);
        outp[147] = fmaxf(m3, 0.f);
    }
}

// ---- TF32 TC dual-weight GEMM v2: 256 thr / 8 warps, reg double-buffer ------
// BM=128, BN=64, BK=32; warp tile 32x32 (2 m16 x 4 n8); BNP=72 (8 mod 32 -> B
// fragment loads are a lane bijection, conflict-free).
__global__ void k_gemm_tc(const float* __restrict__ A,
                          const float* __restrict__ B0, const float* __restrict__ B1,
                          const float* __restrict__ bias0, const float* __restrict__ bias1,
                          float* __restrict__ C0, float* __restrict__ C1,
                          int K, int NC) {
    constexpr int BM = 128, BN = 64, BK = 32;
    constexpr int BKP = 36, BNP = 72;
    __shared__ __align__(16) unsigned As[BM * BKP];
    __shared__ __align__(16) unsigned Bs[BK * BNP];
    const int t = threadIdx.x, lane = t & 31, w = t >> 5;
    const int wm = (w >> 1) * 32, wn = (w & 1) * 32;
    const int ncolb = NC / BN;
    const int which = blockIdx.x / ncolb;
    const int bn = (blockIdx.x % ncolb) * BN;
    const int bm = blockIdx.y * BM;
    const float* B = which ? B1 : B0;
    const float* bias = which ? bias1 : bias0;
    float* C = which ? C1 : C0;

    float acc[2][4][4];
#pragma unroll
    for (int mt = 0; mt < 2; mt++)
#pragma unroll
        for (int nt = 0; nt < 4; nt++)
#pragma unroll
            for (int c = 0; c < 4; c++) acc[mt][nt][c] = 0.f;

    const int ar = t >> 1, ac = (t & 1) * 16;     // A: 16 floats/thread
    const int brow = t >> 3, bcol = (t & 7) * 8;  // B: 8 floats/thread
    const float* ap = A + (size_t)(bm + ar) * K + ac;
    const float* bp = B + (size_t)brow * NC + bn + bcol;

    float4 ra0, ra1, ra2, ra3, rb0, rb1;
    // prologue: load tile 0
    ra0 = *(const float4*)(ap + 0);
    ra1 = *(const float4*)(ap + 4);
    ra2 = *(const float4*)(ap + 8);
    ra3 = *(const float4*)(ap + 12);
    rb0 = *(const float4*)(bp + 0);
    rb1 = *(const float4*)(bp + 4);

    for (int k0 = 0; k0 < K; k0 += BK) {
        // store current tile (tf32-rounded) to smem
        *(uint4*)&As[ar * BKP + ac] =
            make_uint4(cvt_tf32(ra0.x), cvt_tf32(ra0.y), cvt_tf32(ra0.z), cvt_tf32(ra0.w));
        *(uint4*)&As[ar * BKP + ac + 4] =
            make_uint4(cvt_tf32(ra1.x), cvt_tf32(ra1.y), cvt_tf32(ra1.z), cvt_tf32(ra1.w));
        *(uint4*)&As[ar * BKP + ac + 8] =
            make_uint4(cvt_tf32(ra2.x), cvt_tf32(ra2.y), cvt_tf32(ra2.z), cvt_tf32(ra2.w));
        *(uint4*)&As[ar * BKP + ac + 12] =
            make_uint4(cvt_tf32(ra3.x), cvt_tf32(ra3.y), cvt_tf32(ra3.z), cvt_tf32(ra3.w));
        *(uint4*)&Bs[brow * BNP + bcol] =
            make_uint4(cvt_tf32(rb0.x), cvt_tf32(rb0.y), cvt_tf32(rb0.z), cvt_tf32(rb0.w));
        *(uint4*)&Bs[brow * BNP + bcol + 4] =
            make_uint4(cvt_tf32(rb1.x), cvt_tf32(rb1.y), cvt_tf32(rb1.z), cvt_tf32(rb1.w));
        __syncthreads();

        // prefetch next tile while computing this one
        const bool more = (k0 + BK) < K;
        if (more) {
            const float* apn = ap + k0 + BK;
            const float* bpn = bp + (size_t)(k0 + BK) * NC;
            ra0 = *(const float4*)(apn + 0);
            ra1 = *(const float4*)(apn + 4);
            ra2 = *(const float4*)(apn + 8);
            ra3 = *(const float4*)(apn + 12);
            rb0 = *(const float4*)(bpn + 0);
            rb1 = *(const float4*)(bpn + 4);
        }
#pragma unroll
        for (int ks = 0; ks < BK / 8; ks++) {
            const int kk = ks * 8;
            unsigned af[2][4], bf[4][2];
#pragma unroll
            for (int mt = 0; mt < 2; mt++) {
                int r = wm + mt * 16 + (lane >> 2);
                int c = kk + (lane & 3);
                af[mt][0] = As[r * BKP + c];
                af[mt][1] = As[(r + 8) * BKP + c];
                af[mt][2] = As[r * BKP + c + 4];
                af[mt][3] = As[(r + 8) * BKP + c + 4];
            }
#pragma unroll
            for (int nt = 0; nt < 4; nt++) {
                int cb = wn + nt * 8 + (lane >> 2);
                bf[nt][0] = Bs[(kk + (lane & 3)) * BNP + cb];
                bf[nt][1] = Bs[(kk + (lane & 3) + 4) * BNP + cb];
            }
#pragma unroll
            for (int mt = 0; mt < 2; mt++)
#pragma unroll
                for (int nt = 0; nt < 4; nt++)
                    mma_tf32(acc[mt][nt], af[mt], bf[nt]);
        }
        __syncthreads();
    }
#pragma unroll
    for (int nt = 0; nt < 4; nt++) {
        int col = bn + wn + nt * 8 + 2 * (lane & 3);
        float2 bv = *(const float2*)&bias[col];
#pragma unroll
        for (int mt = 0; mt < 2; mt++) {
            int r = bm + wm + mt * 16 + (lane >> 2);
            *(float2*)&C[(size_t)r * NC + col] =
                make_float2(acc[mt][nt][0] + bv.x, acc[mt][nt][1] + bv.y);
            *(float2*)&C[(size_t)(r + 8) * NC + col] =
                make_float2(acc[mt][nt][2] + bv.x, acc[mt][nt][3] + bv.y);
        }
    }
}

// ---------------- GAT layer 1: fused gather, 2-edge pipelined ----------------
__global__ void k_gat1(const float* __restrict__ att, const float* __restrict__ bias) {
    int d = (blockIdx.x * blockDim.x + threadIdx.x) >> 5;
    int lane = threadIdx.x & 31;
    if (d >= NN) return;
    const float4 at = *(const float4*)&att[lane * 4];
    float4 xr = *(const float4*)&g_xr1[(size_t)d * 128 + lane * 4];
    float4 xd = *(const float4*)&g_xl1[(size_t)d * 128 + lane * 4];
    float a = lrelu(xd.x + xr.x) * at.x + lrelu(xd.y + xr.y) * at.y +
              lrelu(xd.z + xr.z) * at.z + lrelu(xd.w + xr.w) * at.w;
    a += __shfl_xor_sync(0xffffffffu, a, 8);
    a += __shfl_xor_sync(0xffffffffu, a, 4);
    a += __shfl_xor_sync(0xffffffffu, a, 2);
    a += __shfl_xor_sync(0xffffffffu, a, 1);
    float ex = __expf(a);
    float den = ex;
    float4 acc = make_float4(ex * xd.x, ex * xd.y, ex * xd.z, ex * xd.w);

    const int i0 = g_roff[d], i1 = g_roff[d + 1];
    int i = i0;
    for (; i + 1 < i1; i += 2) {
        int s0 = g_esrc[i];
        int s1 = g_esrc[i + 1];
        float4 x0 = *(const float4*)&g_xl1[(size_t)s0 * 128 + lane * 4];
        float4 x1 = *(const float4*)&g_xl1[(size_t)s1 * 128 + lane * 4];
        float a0 = lrelu(x0.x + xr.x) * at.x + lrelu(x0.y + xr.y) * at.y +
                   lrelu(x0.z + xr.z) * at.z + lrelu(x0.w + xr.w) * at.w;
        float a1 = lrelu(x1.x + xr.x) * at.x + lrelu(x1.y + xr.y) * at.y +
                   lrelu(x1.z + xr.z) * at.z + lrelu(x1.w + xr.w) * at.w;
        a0 += __shfl_xor_sync(0xffffffffu, a0, 8);
        a1 += __shfl_xor_sync(0xffffffffu, a1, 8);
        a0 += __shfl_xor_sync(0xffffffffu, a0, 4);
        a1 += __shfl_xor_sync(0xffffffffu, a1, 4);
        a0 += __shfl_xor_sync(0xffffffffu, a0, 2);
        a1 += __shfl_xor_sync(0xffffffffu, a1, 2);
        a0 += __shfl_xor_sync(0xffffffffu, a0, 1);
        a1 += __shfl_xor_sync(0xffffffffu, a1, 1);
        float e0 = __expf(a0);
        float e1 = __expf(a1);
        den += e0 + e1;
        acc.x += e0 * x0.x + e1 * x1.x;
        acc.y += e0 * x0.y + e1 * x1.y;
        acc.z += e0 * x0.z + e1 * x1.z;
        acc.w += e0 * x0.w + e1 * x1.w;
    }
    if (i < i1) {
        int s = g_esrc[i];
        float4 xs = *(const float4*)&g_xl1[(size_t)s * 128 + lane * 4];
        float a2 = lrelu(xs.x + xr.x) * at.x + lrelu(xs.y + xr.y) * at.y +
                   lrelu(xs.z + xr.z) * at.z + lrelu(xs.w + xr.w) * at.w;
        a2 += __shfl_xor_sync(0xffffffffu, a2, 8);
        a2 += __shfl_xor_sync(0xffffffffu, a2, 4);
        a2 += __shfl_xor_sync(0xffffffffu, a2, 2);
        a2 += __shfl_xor_sync(0xffffffffu, a2, 1);
        float e2 = __expf(a2);
        den += e2;
        acc.x += e2 * xs.x; acc.y += e2 * xs.y;
        acc.z += e2 * xs.z; acc.w += e2 * xs.w;
    }
    float inv = 1.f / den;
    float4 bv = *(const float4*)&bias[lane * 4];
    float4 o;
    o.x = fmaxf(acc.x * inv + bv.x, 0.f);
    o.y = fmaxf(acc.y * inv + bv.y, 0.f);
    o.z = fmaxf(acc.z * inv + bv.z, 0.f);
    o.w = fmaxf(acc.w * inv + bv.w, 0.f);
    *(float4*)&g_o1[(size_t)d * 128 + lane * 4] = o;
}

// ---------------- GAT layer 2: fused gather, 2-edge pipelined ----------------
__global__ void k_gat2(const float* __restrict__ att) {
    int d = (blockIdx.x * blockDim.x + threadIdx.x) >> 5;
    int lane = threadIdx.x & 31;
    if (d >= NN) return;
    const float2 at = *(const float2*)&att[lane * 2];
    float2 xr = *(const float2*)&g_xr2[(size_t)d * 64 + lane * 2];
    float2 xd = *(const float2*)&g_xl2[(size_t)d * 64 + lane * 2];
    float a = lrelu(xd.x + xr.x) * at.x + lrelu(xd.y + xr.y) * at.y;
    a += __shfl_xor_sync(0xffffffffu, a, 16);
    a += __shfl_xor_sync(0xffffffffu, a, 8);
    a += __shfl_xor_sync(0xffffffffu, a, 4);
    a += __shfl_xor_sync(0xffffffffu, a, 2);
    a += __shfl_xor_sync(0xffffffffu, a, 1);
    float ex = __expf(a);
    float den = ex;
    float2 acc = make_float2(ex * xd.x, ex * xd.y);

    const int i0 = g_roff[d], i1 = g_roff[d + 1];
    int i = i0;
    for (; i + 1 < i1; i += 2) {
        int s0 = g_esrc[i];
        int s1 = g_esrc[i + 1];
        float2 x0 = *(const float2*)&g_xl2[(size_t)s0 * 64 + lane * 2];
        float2 x1 = *(const float2*)&g_xl2[(size_t)s1 * 64 + lane * 2];
        float a0 = lrelu(x0.x + xr.x) * at.x + lrelu(x0.y + xr.y) * at.y;
        float a1 = lrelu(x1.x + xr.x) * at.x + lrelu(x1.y + xr.y) * at.y;
        a0 += __shfl_xor_sync(0xffffffffu, a0, 16);
        a1 += __shfl_xor_sync(0xffffffffu, a1, 16);
        a0 += __shfl_xor_sync(0xffffffffu, a0, 8);
        a1 += __shfl_xor_sync(0xffffffffu, a1, 8);
        a0 += __shfl_xor_sync(0xffffffffu, a0, 4);
        a1 += __shfl_xor_sync(0xffffffffu, a1, 4);
        a0 += __shfl_xor_sync(0xffffffffu, a0, 2);
        a1 += __shfl_xor_sync(0xffffffffu, a1, 2);
        a0 += __shfl_xor_sync(0xffffffffu, a0, 1);
        a1 += __shfl_xor_sync(0xffffffffu, a1, 1);
        float e0 = __expf(a0);
        float e1 = __expf(a1);
        den += e0 + e1;
        acc.x += e0 * x0.x + e1 * x1.x;
        acc.y += e0 * x0.y + e1 * x1.y;
    }
    if (i < i1) {
        int s = g_esrc[i];
        float2 xs = *(const float2*)&g_xl2[(size_t)s * 64 + lane * 2];
        float a2 = lrelu(xs.x + xr.x) * at.x + lrelu(xs.y + xr.y) * at.y;
        a2 += __shfl_xor_sync(0xffffffffu, a2, 16);
        a2 += __shfl_xor_sync(0xffffffffu, a2, 8);
        a2 += __shfl_xor_sync(0xffffffffu, a2, 4);
        a2 += __shfl_xor_sync(0xffffffffu, a2, 2);
        a2 += __shfl_xor_sync(0xffffffffu, a2, 1);
        float e2 = __expf(a2);
        den += e2;
        acc.x += e2 * xs.x; acc.y += e2 * xs.y;
    }
    float inv = 1.f / den;
    *(float2*)&g_o2[(size_t)d * 64 + lane * 2] = make_float2(acc.x * inv, acc.y * inv);
}

// ---------------- classifier: (o2 + bias2) @ Wc + bc -------------------------
__global__ void k_cls(const float* __restrict__ Wc, const float* __restrict__ bc,
                      const float* __restrict__ bias2, float* __restrict__ out) {
    int i = blockIdx.x * blockDim.x + threadIdx.x;
    if (i >= NN * 10) return;
    int n = i / 10, j = i % 10;
    const float* r = g_o2 + (size_t)n * 64;
    float acc = bc[j];
#pragma unroll
    for (int c = 0; c < 64; c++) acc += (r[c] + bias2[c]) * Wc[c * 10 + j];
    out[i] = acc;
}

// ---------------- launcher ----------------------------------------------------
extern "C" void kernel_launch(void* const* d_in, const int* in_sizes, int n_in,
                              void* d_out, int out_size) {
    const float* x = (const float*)d_in[0];
    const int* ei = (const int*)d_in[1];
    const float* c1w = (const float*)d_in[2];
    const float* c1b = (const float*)d_in[3];
    const float* c2w = (const float*)d_in[4];
    const float* c2b = (const float*)d_in[5];
    const float* Wl1 = (const float*)d_in[6];
    const float* bl1 = (const float*)d_in[7];
    const float* Wr1 = (const float*)d_in[8];
    const float* br1 = (const float*)d_in[9];
    const float* att1 = (const float*)d_in[10];
    const float* bias1 = (const float*)d_in[11];
    const float* Wl2 = (const float*)d_in[12];
    const float* bl2 = (const float*)d_in[13];
    const float* Wr2 = (const float*)d_in[14];
    const float* br2 = (const float*)d_in[15];
    const float* att2 = (const float*)d_in[16];
    const float* bias2 = (const float*)d_in[17];
    const float* Wc = (const float*)d_in[18];
    const float* bc = (const float*)d_in[19];
    float* out = (float*)d_out;

    void *ph2, *pxl1, *pxr1, *po1, *pxl2, *pxr2;
    cudaGetSymbolAddress(&ph2, g_h2);
    cudaGetSymbolAddress(&pxl1, g_xl1);
    cudaGetSymbolAddress(&pxr1, g_xr1);
    cudaGetSymbolAddress(&po1, g_o1);
    cudaGetSymbolAddress(&pxl2, g_xl2);
    cudaGetSymbolAddress(&pxr2, g_xr2);

    // Launch order puts the BIG TF32 GEMM in the ncu-profiled slot (4th).
    // Deps: zero_deg<hist<scan<scatter<gat1; conv1<conv2<gemm_big<gat1.
    k_zero_deg<<<NN / 256, 256>>>();                       // 1
    k_conv1<<<NN, 256>>>(x, c1w, c1b);                     // 2
    k_conv2<<<dim3(2, NN), 256>>>(c2w, c2b);               // 3
    k_gemm_tc<<<dim3(4, NN / 128), 256>>>(                  // 4 <- profiled
        (const float*)ph2, Wl1, Wr1, bl1, br1, (float*)pxl1, (float*)pxr1, GIN, 128);
    k_hist<<<EE / 256, 256>>>(ei);                         // 5
    k_scan<<<1, 1024>>>();                                 // 6
    k_scatter<<<EE / 256, 256>>>(ei);                      // 7
    k_gat1<<<NN / 8, 256>>>(att1, bias1);                  // 8
    k_gemm_tc<<<dim3(2, NN / 128), 256>>>(                 // 9
        (const float*)po1, Wl2, Wr2, bl2, br2, (float*)pxl2, (float*)pxr2, 128, 64);
    k_gat2<<<NN / 8, 256>>>(att2);                         // 10
    k_cls<<<(NN * 10 + 255) / 256, 256>>>(Wc, bc, bias2, out);  // 11
}

// round 14
// speedup vs baseline: 1.4749x; 1.0194x over previous
#include <cuda_runtime.h>
#include <cuda_bf16.h>
#include <math.h>

#define NN 16384
#define EE 524288
#define GIN 1568       // 32*7*7

typedef unsigned long long u64;

// ---------------- packed / tf32 helpers ---------------------------------------
__device__ __forceinline__ u64 pk2(float x, float y) {
    u64 r; asm("mov.b64 %0, {%1,%2};" : "=l"(r) : "f"(x), "f"(y)); return r;
}
__device__ __forceinline__ u64 pkb(float x) { return pk2(x, x); }
__device__ __forceinline__ u64 ffma2(u64 a, u64 b, u64 c) {
    u64 d; asm("fma.rn.f32x2 %0, %1, %2, %3;" : "=l"(d) : "l"(a), "l"(b), "l"(c)); return d;
}
__device__ __forceinline__ float2 upk(u64 v) {
    float2 r; asm("mov.b64 {%0,%1}, %2;" : "=f"(r.x), "=f"(r.y) : "l"(v)); return r;
}
__device__ __forceinline__ void mma_tf32(float* d, const unsigned* a, const unsigned* b) {
    asm volatile(
        "mma.sync.aligned.m16n8k8.row.col.f32.tf32.tf32.f32 "
        "{%0,%1,%2,%3}, {%4,%5,%6,%7}, {%8,%9}, {%0,%1,%2,%3};"
        : "+f"(d[0]), "+f"(d[1]), "+f"(d[2]), "+f"(d[3])
        : "r"(a[0]), "r"(a[1]), "r"(a[2]), "r"(a[3]), "r"(b[0]), "r"(b[1]));
}
__device__ __forceinline__ void cpasync16(unsigned s, const float* g) {
    asm volatile("cp.async.ca.shared.global [%0], [%1], 16;" :: "r"(s), "l"(g));
}
__device__ __forceinline__ void cp_commit() {
    asm volatile("cp.async.commit_group;");
}
__device__ __forceinline__ void cp_wait1() {
    asm volatile("cp.async.wait_group 1;");
}
__device__ __forceinline__ void ldsm_x4(unsigned* r, unsigned saddr) {
    asm volatile("ldmatrix.sync.aligned.m8n8.x4.shared.b16 {%0,%1,%2,%3}, [%4];"
                 : "=r"(r[0]), "=r"(r[1]), "=r"(r[2]), "=r"(r[3]) : "r"(saddr));
}

// ---------------- scratch (device globals; no allocs allowed) ----------------
__device__ float g_h1[NN * 16 * 14 * 14];  // conv1+pool output
__device__ float g_h2[NN * GIN];           // conv2+pool output (flattened NCHW)
__device__ float g_xl1[NN * 128];
__device__ float g_xr1[NN * 128];
__device__ float g_o1[NN * 128];           // gat1 out (bias+relu fused)
__device__ float g_xl2[NN * 64];
__device__ float g_xr2[NN * 64];
__device__ float g_o2[NN * 64];            // gat2 out (pre-bias)
// CSR by destination
__device__ int g_deg[NN];                  // histogram, then scatter cursor
__device__ int g_roff[NN + 1];
__device__ int g_esrc[EE];

__device__ __forceinline__ float lrelu(float v) { return v > 0.f ? v : 0.2f * v; }

// ---------------- CSR build ---------------------------------------------------
__global__ void k_zero_deg() {
    int i = blockIdx.x * blockDim.x + threadIdx.x;
    if (i < NN) g_deg[i] = 0;
}

__global__ void k_hist(const int* __restrict__ ei) {
    int e = blockIdx.x * blockDim.x + threadIdx.x;
    if (e < EE) atomicAdd(&g_deg[ei[EE + e]], 1);
}

// single CTA, 1024 threads, 16 nodes/thread exclusive scan
__global__ void k_scan() {
    __shared__ int wsum[32];
    int t = threadIdx.x, lane = t & 31, wid = t >> 5;
    int base = t * 16;
    int c[16];
    int s = 0;
#pragma unroll
    for (int i = 0; i < 16; i++) { c[i] = s; s += g_deg[base + i]; }
    int v = s;
#pragma unroll
    for (int off = 1; off < 32; off <<= 1) {
        int n = __shfl_up_sync(0xffffffffu, v, off);
        if (lane >= off) v += n;
    }
    if (lane == 31) wsum[wid] = v;
    __syncthreads();
    if (wid == 0) {
        int w = wsum[lane];
#pragma unroll
        for (int off = 1; off < 32; off <<= 1) {
            int n = __shfl_up_sync(0xffffffffu, w, off);
            if (lane >= off) w += n;
        }
        wsum[lane] = w;  // inclusive
    }
    __syncthreads();
    int wbase = (wid == 0) ? 0 : wsum[wid - 1];
    int tbase = wbase + (v - s);  // exclusive base for this thread
#pragma unroll
    for (int i = 0; i < 16; i++) {
        int r = tbase + c[i];
        g_roff[base + i] = r;
        g_deg[base + i] = r;   // cursor for scatter
    }
    if (t == 1023) g_roff[NN] = EE;
}

__global__ void k_scatter(const int* __restrict__ ei) {
    int e = blockIdx.x * blockDim.x + threadIdx.x;
    if (e >= EE) return;
    int d = ei[EE + e];
    int pos = atomicAdd(&g_deg[d], 1);
    g_esrc[pos] = ei[e];
}

// ---------------- conv1 (1->16, 3x3 SAME) + relu + maxpool2 ------------------
__global__ void k_conv1(const float* __restrict__ x, const float* __restrict__ w,
                        const float* __restrict__ b) {
    __shared__ __align__(16) float sin_[30 * 30];
    __shared__ __align__(16) float sw[9 * 16];   // [k][oc]
    __shared__ __align__(16) float sb[16];
    const int n = blockIdx.x;
    const int t = threadIdx.x;  // 256
    for (int i = t; i < 900; i += 256) sin_[i] = 0.f;
    if (t < 144) { int oc = t / 9, k = t % 9; sw[k * 16 + oc] = w[t]; }
    if (t < 16) sb[t] = b[t];
    __syncthreads();
    const float* xi = x + n * 784;
    for (int i = t; i < 784; i += 256) {
        int y = i / 28, xx = i % 28;
        sin_[(y + 1) * 30 + xx + 1] = xi[i];
    }
    __syncthreads();
    for (int item = t; item < 8 * 196; item += 256) {
        int cp = item / 196, p = item % 196;
        int c0 = cp * 2;
        int py = p / 14, px = p % 14;
        float v[4][4];
#pragma unroll
        for (int r = 0; r < 4; r++) {
            float2 a = *(const float2*)&sin_[(2 * py + r) * 30 + 2 * px];
            float2 c = *(const float2*)&sin_[(2 * py + r) * 30 + 2 * px + 2];
            v[r][0] = a.x; v[r][1] = a.y; v[r][2] = c.x; v[r][3] = c.y;
        }
        u64 bi = *(const u64*)&sb[c0];
        u64 acc[4] = {bi, bi, bi, bi};
#pragma unroll
        for (int ky = 0; ky < 3; ky++)
#pragma unroll
            for (int kx = 0; kx < 3; kx++) {
                u64 wp = *(const u64*)&sw[(ky * 3 + kx) * 16 + c0];
#pragma unroll
                for (int q = 0; q < 4; q++) {
                    int dy = q >> 1, dx = q & 1;
                    acc[q] = ffma2(wp, pkb(v[dy + ky][dx + kx]), acc[q]);
                }
            }
        float2 m0 = upk(acc[0]);
        float mx0 = m0.x, mx1 = m0.y;
#pragma unroll
        for (int q = 1; q < 4; q++) {
            float2 mq = upk(acc[q]);
            mx0 = fmaxf(mx0, mq.x); mx1 = fmaxf(mx1, mq.y);
        }
        g_h1[n * 3136 + c0 * 196 + p] = fmaxf(mx0, 0.f);
        g_h1[n * 3136 + (c0 + 1) * 196 + p] = fmaxf(mx1, 0.f);
    }
}

// ---------------- conv2 (16->32, 3x3 SAME) + relu + maxpool2 -----------------
// grid (2, NN): x = output-channel half (16 oc), y = image. 256 threads.
__global__ void k_conv2(const float* __restrict__ w, const float* __restrict__ b) {
    __shared__ __align__(16) float sin_[16 * 256];   // [ci][16][16]
    __shared__ __align__(16) float sw[16 * 144];     // [ci][k][16 local oc]
    __shared__ __align__(16) float sb[16];
    const int half = blockIdx.x;
    const int n = blockIdx.y;
    const int oc0 = half * 16;
    const int t = threadIdx.x;  // 256
    for (int i = t; i < 4096; i += 256) sin_[i] = 0.f;
    for (int i = t; i < 2304; i += 256) {
        int ocl = i / 144, r = i % 144, ci = r / 9, k = r % 9;
        sw[ci * 144 + k * 16 + ocl] = w[(oc0 + ocl) * 144 + r];
    }
    if (t < 16) sb[t] = b[oc0 + t];
    __syncthreads();
    const float* hi = g_h1 + n * 3136;
    for (int i = t; i < 3136; i += 256) {
        int ci = i / 196, p = i % 196, y = p / 14, xx = p % 14;
        sin_[ci * 256 + (y + 1) * 16 + (xx + 1)] = hi[i];
    }
    __syncthreads();
    if (t < 196) {
        int cg = t / 49, p = t % 49;
        int c0 = cg * 4;
        int py = p / 7, px = p % 7;
        u64 b01 = *(const u64*)&sb[c0];
        u64 b23 = *(const u64*)&sb[c0 + 2];
        u64 acc01[4] = {b01, b01, b01, b01};
        u64 acc23[4] = {b23, b23, b23, b23};
        for (int ci = 0; ci < 16; ci++) {
            const float* ip = sin_ + ci * 256 + 2 * py * 16 + 2 * px;
            float v[4][4];
#pragma unroll
            for (int r = 0; r < 4; r++) {
                float2 a = *(const float2*)&ip[r * 16];
                float2 c = *(const float2*)&ip[r * 16 + 2];
                v[r][0] = a.x; v[r][1] = a.y; v[r][2] = c.x; v[r][3] = c.y;
            }
            const float* wp0 = sw + ci * 144 + c0;
#pragma unroll
            for (int ky = 0; ky < 3; ky++)
#pragma unroll
                for (int kx = 0; kx < 3; kx++) {
                    u64 w01 = *(const u64*)&wp0[(ky * 3 + kx) * 16];
                    u64 w23 = *(const u64*)&wp0[(ky * 3 + kx) * 16 + 2];
#pragma unroll
                    for (int q = 0; q < 4; q++) {
                        int dy = q >> 1, dx = q & 1;
                        u64 vb = pkb(v[dy + ky][dx + kx]);
                        acc01[q] = ffma2(w01, vb, acc01[q]);
                        acc23[q] = ffma2(w23, vb, acc23[q]);
                    }
                }
        }
        float2 a0 = upk(acc01[0]), b0 = upk(acc23[0]);
        float m0 = a0.x, m1 = a0.y, m2 = b0.x, m3 = b0.y;
#pragma unroll
        for (int q = 1; q < 4; q++) {
            float2 aq = upk(acc01[q]), bq = upk(acc23[q]);
            m0 = fmaxf(m0, aq.x); m1 = fmaxf(m1, aq.y);
            m2 = fmaxf(m2, bq.x); m3 = fmaxf(m3, bq.y);
        }
        float* outp = g_h2 + (size_t)n * GIN + (oc0 + c0) * 49 + p;
        outp[0]   = fmaxf(m0, 0.f);
        outp[49]  = fmaxf(m1, 0.f);
        outp[98]  = fmaxf(m2, 0.f);
        outp[147] = fmaxf(m3, 0.f);
    }
}

// ---- TF32 TC dual-weight GEMM v3: cp.async 2-stage + ldmatrix A -------------
// BM=128, BN=64, BK=16 (x2 stages); 8 warps (4 m-rows x 2 n-cols), warp 32x32.
// Raw f32 fed to HMMA.TF32 (HW truncation) - no explicit cvt.
__global__ void __launch_bounds__(256, 3) k_gemm_tc(
        const float* __restrict__ A,
        const float* __restrict__ B0, const float* __restrict__ B1,
        const float* __restrict__ bias0, const float* __restrict__ bias1,
        float* __restrict__ C0, float* __restrict__ C1,
        int K, int NC) {
    constexpr int BM = 128, BN = 64, BK = 16;
    constexpr int BKP = 20, BNP = 72;
    constexpr int ASZ = BM * BKP;   // 2560 words
    constexpr int BSZ = BK * BNP;   // 1152 words
    __shared__ __align__(16) unsigned As[2][ASZ];
    __shared__ __align__(16) unsigned Bs[2][BSZ];
    const int t = threadIdx.x, lane = t & 31, w = t >> 5;
    const int wm = (w >> 1) * 32, wn = (w & 1) * 32;
    const int ncolb = NC / BN;
    const int which = blockIdx.x / ncolb;
    const int bn = (blockIdx.x % ncolb) * BN;
    const int bm = blockIdx.y * BM;
    const float* B = which ? B1 : B0;
    const float* bias = which ? bias1 : bias0;
    float* C = which ? C1 : C0;

    float acc[2][4][4];
#pragma unroll
    for (int mt = 0; mt < 2; mt++)
#pragma unroll
        for (int nt = 0; nt < 4; nt++)
#pragma unroll
            for (int c = 0; c < 4; c++) acc[mt][nt][c] = 0.f;

    const unsigned asb = (unsigned)__cvta_generic_to_shared(&As[0][0]);
    const unsigned bsb = (unsigned)__cvta_generic_to_shared(&Bs[0][0]);

    // fill indices: A 8 floats/thread (2x16B), B 4 floats/thread (1x16B)
    const int ar = t >> 1, ac = (t & 1) * 8;
    const int brow = t >> 4, bcol = (t & 15) * 4;
    const float* agp = A + (size_t)(bm + ar) * K + ac;
    const float* bgp = B + (size_t)brow * NC + bn + bcol;
    const unsigned aso = (unsigned)(ar * BKP + ac) * 4;
    const unsigned bso = (unsigned)(brow * BNP + bcol) * 4;

    // ldmatrix address pieces (per thread, fixed across loop)
    const int lr = lane & 15;
    const int lco = (lane >> 4) << 2;

    // prologue: fill stages 0,1
#pragma unroll
    for (int s = 0; s < 2; s++) {
        int k0 = s * BK;
        cpasync16(asb + s * ASZ * 4 + aso, agp + k0);
        cpasync16(asb + s * ASZ * 4 + aso + 16, agp + k0 + 4);
        cpasync16(bsb + s * BSZ * 4 + bso, bgp + (size_t)k0 * NC);
        cp_commit();
    }

    const int nIter = K / BK;
    for (int kt = 0; kt < nIter; kt++) {
        const int cur = kt & 1;
        cp_wait1();
        __syncthreads();
        const unsigned* BsC = Bs[cur];
        const unsigned abase = asb + cur * ASZ * 4;
#pragma unroll
        for (int ks = 0; ks < 2; ks++) {
            const int kk = ks * 8;
            unsigned af[2][4], bf[4][2];
#pragma unroll
            for (int mt = 0; mt < 2; mt++) {
                unsigned sa = abase + (unsigned)((wm + mt * 16 + lr) * BKP + kk + lco) * 4;
                ldsm_x4(af[mt], sa);
            }
#pragma unroll
            for (int nt = 0; nt < 4; nt++) {
                int cb = wn + nt * 8 + (lane >> 2);
                bf[nt][0] = BsC[(kk + (lane & 3)) * BNP + cb];
                bf[nt][1] = BsC[(kk + (lane & 3) + 4) * BNP + cb];
            }
#pragma unroll
            for (int mt = 0; mt < 2; mt++)
#pragma unroll
                for (int nt = 0; nt < 4; nt++)
                    mma_tf32(acc[mt][nt], af[mt], bf[nt]);
        }
        __syncthreads();
        const int knext = (kt + 2) * BK;
        if (knext < K) {
            cpasync16(asb + cur * ASZ * 4 + aso, agp + knext);
            cpasync16(asb + cur * ASZ * 4 + aso + 16, agp + knext + 4);
            cpasync16(bsb + cur * BSZ * 4 + bso, bgp + (size_t)knext * NC);
        }
        cp_commit();   // commit (possibly empty) to keep group accounting uniform
    }
#pragma unroll
    for (int nt = 0; nt < 4; nt++) {
        int col = bn + wn + nt * 8 + 2 * (lane & 3);
        float2 bv = *(const float2*)&bias[col];
#pragma unroll
        for (int mt = 0; mt < 2; mt++) {
            int r = bm + wm + mt * 16 + (lane >> 2);
            *(float2*)&C[(size_t)r * NC + col] =
                make_float2(acc[mt][nt][0] + bv.x, acc[mt][nt][1] + bv.y);
            *(float2*)&C[(size_t)(r + 8) * NC + col] =
                make_float2(acc[mt][nt][2] + bv.x, acc[mt][nt][3] + bv.y);
        }
    }
}

// ---------------- GAT layer 1: fused gather, 2-edge pipelined ----------------
__global__ void k_gat1(const float* __restrict__ att, const float* __restrict__ bias) {
    int d = (blockIdx.x * blockDim.x + threadIdx.x) >> 5;
    int lane = threadIdx.x & 31;
    if (d >= NN) return;
    const float4 at = *(const float4*)&att[lane * 4];
    float4 xr = *(const float4*)&g_xr1[(size_t)d * 128 + lane * 4];
    float4 xd = *(const float4*)&g_xl1[(size_t)d * 128 + lane * 4];
    float a = lrelu(xd.x + xr.x) * at.x + lrelu(xd.y + xr.y) * at.y +
              lrelu(xd.z + xr.z) * at.z + lrelu(xd.w + xr.w) * at.w;
    a += __shfl_xor_sync(0xffffffffu, a, 8);
    a += __shfl_xor_sync(0xffffffffu, a, 4);
    a += __shfl_xor_sync(0xffffffffu, a, 2);
    a += __shfl_xor_sync(0xffffffffu, a, 1);
    float ex = __expf(a);
    float den = ex;
    float4 acc = make_float4(ex * xd.x, ex * xd.y, ex * xd.z, ex * xd.w);

    const int i0 = g_roff[d], i1 = g_roff[d + 1];
    int i = i0;
    for (; i + 1 < i1; i += 2) {
        int s0 = g_esrc[i];
        int s1 = g_esrc[i + 1];
        float4 x0 = *(const float4*)&g_xl1[(size_t)s0 * 128 + lane * 4];
        float4 x1 = *(const float4*)&g_xl1[(size_t)s1 * 128 + lane * 4];
        float a0 = lrelu(x0.x + xr.x) * at.x + lrelu(x0.y + xr.y) * at.y +
                   lrelu(x0.z + xr.z) * at.z + lrelu(x0.w + xr.w) * at.w;
        float a1 = lrelu(x1.x + xr.x) * at.x + lrelu(x1.y + xr.y) * at.y +
                   lrelu(x1.z + xr.z) * at.z + lrelu(x1.w + xr.w) * at.w;
        a0 += __shfl_xor_sync(0xffffffffu, a0, 8);
        a1 += __shfl_xor_sync(0xffffffffu, a1, 8);
        a0 += __shfl_xor_sync(0xffffffffu, a0, 4);
        a1 += __shfl_xor_sync(0xffffffffu, a1, 4);
        a0 += __shfl_xor_sync(0xffffffffu, a0, 2);
        a1 += __shfl_xor_sync(0xffffffffu, a1, 2);
        a0 += __shfl_xor_sync(0xffffffffu, a0, 1);
        a1 += __shfl_xor_sync(0xffffffffu, a1, 1);
        float e0 = __expf(a0);
        float e1 = __expf(a1);
        den += e0 + e1;
        acc.x += e0 * x0.x + e1 * x1.x;
        acc.y += e0 * x0.y + e1 * x1.y;
        acc.z += e0 * x0.z + e1 * x1.z;
        acc.w += e0 * x0.w + e1 * x1.w;
    }
    if (i < i1) {
        int s = g_esrc[i];
        float4 xs = *(const float4*)&g_xl1[(size_t)s * 128 + lane * 4];
        float a2 = lrelu(xs.x + xr.x) * at.x + lrelu(xs.y + xr.y) * at.y +
                   lrelu(xs.z + xr.z) * at.z + lrelu(xs.w + xr.w) * at.w;
        a2 += __shfl_xor_sync(0xffffffffu, a2, 8);
        a2 += __shfl_xor_sync(0xffffffffu, a2, 4);
        a2 += __shfl_xor_sync(0xffffffffu, a2, 2);
        a2 += __shfl_xor_sync(0xffffffffu, a2, 1);
        float e2 = __expf(a2);
        den += e2;
        acc.x += e2 * xs.x; acc.y += e2 * xs.y;
        acc.z += e2 * xs.z; acc.w += e2 * xs.w;
    }
    float inv = 1.f / den;
    float4 bv = *(const float4*)&bias[lane * 4];
    float4 o;
    o.x = fmaxf(acc.x * inv + bv.x, 0.f);
    o.y = fmaxf(acc.y * inv + bv.y, 0.f);
    o.z = fmaxf(acc.z * inv + bv.z, 0.f);
    o.w = fmaxf(acc.w * inv + bv.w, 0.f);
    *(float4*)&g_o1[(size_t)d * 128 + lane * 4] = o;
}

// ---------------- GAT layer 2: fused gather, 2-edge pipelined ----------------
__global__ void k_gat2(const float* __restrict__ att) {
    int d = (blockIdx.x * blockDim.x + threadIdx.x) >> 5;
    int lane = threadIdx.x & 31;
    if (d >= NN) return;
    const float2 at = *(const float2*)&att[lane * 2];
    float2 xr = *(const float2*)&g_xr2[(size_t)d * 64 + lane * 2];
    float2 xd = *(const float2*)&g_xl2[(size_t)d * 64 + lane * 2];
    float a = lrelu(xd.x + xr.x) * at.x + lrelu(xd.y + xr.y) * at.y;
    a += __shfl_xor_sync(0xffffffffu, a, 16);
    a += __shfl_xor_sync(0xffffffffu, a, 8);
    a += __shfl_xor_sync(0xffffffffu, a, 4);
    a += __shfl_xor_sync(0xffffffffu, a, 2);
    a += __shfl_xor_sync(0xffffffffu, a, 1);
    float ex = __expf(a);
    float den = ex;
    float2 acc = make_float2(ex * xd.x, ex * xd.y);

    const int i0 = g_roff[d], i1 = g_roff[d + 1];
    int i = i0;
    for (; i + 1 < i1; i += 2) {
        int s0 = g_esrc[i];
        int s1 = g_esrc[i + 1];
        float2 x0 = *(const float2*)&g_xl2[(size_t)s0 * 64 + lane * 2];
        float2 x1 = *(const float2*)&g_xl2[(size_t)s1 * 64 + lane * 2];
        float a0 = lrelu(x0.x + xr.x) * at.x + lrelu(x0.y + xr.y) * at.y;
        float a1 = lrelu(x1.x + xr.x) * at.x + lrelu(x1.y + xr.y) * at.y;
        a0 += __shfl_xor_sync(0xffffffffu, a0, 16);
        a1 += __shfl_xor_sync(0xffffffffu, a1, 16);
        a0 += __shfl_xor_sync(0xffffffffu, a0, 8);
        a1 += __shfl_xor_sync(0xffffffffu, a1, 8);
        a0 += __shfl_xor_sync(0xffffffffu, a0, 4);
        a1 += __shfl_xor_sync(0xffffffffu, a1, 4);
        a0 += __shfl_xor_sync(0xffffffffu, a0, 2);
        a1 += __shfl_xor_sync(0xffffffffu, a1, 2);
        a0 += __shfl_xor_sync(0xffffffffu, a0, 1);
        a1 += __shfl_xor_sync(0xffffffffu, a1, 1);
        float e0 = __expf(a0);
        float e1 = __expf(a1);
        den += e0 + e1;
        acc.x += e0 * x0.x + e1 * x1.x;
        acc.y += e0 * x0.y + e1 * x1.y;
    }
    if (i < i1) {
        int s = g_esrc[i];
        float2 xs = *(const float2*)&g_xl2[(size_t)s * 64 + lane * 2];
        float a2 = lrelu(xs.x + xr.x) * at.x + lrelu(xs.y + xr.y) * at.y;
        a2 += __shfl_xor_sync(0xffffffffu, a2, 16);
        a2 += __shfl_xor_sync(0xffffffffu, a2, 8);
        a2 += __shfl_xor_sync(0xffffffffu, a2, 4);
        a2 += __shfl_xor_sync(0xffffffffu, a2, 2);
        a2 += __shfl_xor_sync(0xffffffffu, a2, 1);
        float e2 = __expf(a2);
        den += e2;
        acc.x += e2 * xs.x; acc.y += e2 * xs.y;
    }
    float inv = 1.f / den;
    *(float2*)&g_o2[(size_t)d * 64 + lane * 2] = make_float2(acc.x * inv, acc.y * inv);
}

// ---------------- classifier: (o2 + bias2) @ Wc + bc -------------------------
__global__ void k_cls(const float* __restrict__ Wc, const float* __restrict__ bc,
                      const float* __restrict__ bias2, float* __restrict__ out) {
    int i = blockIdx.x * blockDim.x + threadIdx.x;
    if (i >= NN * 10) return;
    int n = i / 10, j = i % 10;
    const float* r = g_o2 + (size_t)n * 64;
    float acc = bc[j];
#pragma unroll
    for (int c = 0; c < 64; c++) acc += (r[c] + bias2[c]) * Wc[c * 10 + j];
    out[i] = acc;
}

// ---------------- launcher ----------------------------------------------------
extern "C" void kernel_launch(void* const* d_in, const int* in_sizes, int n_in,
                              void* d_out, int out_size) {
    const float* x = (const float*)d_in[0];
    const int* ei = (const int*)d_in[1];
    const float* c1w = (const float*)d_in[2];
    const float* c1b = (const float*)d_in[3];
    const float* c2w = (const float*)d_in[4];
    const float* c2b = (const float*)d_in[5];
    const float* Wl1 = (const float*)d_in[6];
    const float* bl1 = (const float*)d_in[7];
    const float* Wr1 = (const float*)d_in[8];
    const float* br1 = (const float*)d_in[9];
    const float* att1 = (const float*)d_in[10];
    const float* bias1 = (const float*)d_in[11];
    const float* Wl2 = (const float*)d_in[12];
    const float* bl2 = (const float*)d_in[13];
    const float* Wr2 = (const float*)d_in[14];
    const float* br2 = (const float*)d_in[15];
    const float* att2 = (const float*)d_in[16];
    const float* bias2 = (const float*)d_in[17];
    const float* Wc = (const float*)d_in[18];
    const float* bc = (const float*)d_in[19];
    float* out = (float*)d_out;

    void *ph2, *pxl1, *pxr1, *po1, *pxl2, *pxr2;
    cudaGetSymbolAddress(&ph2, g_h2);
    cudaGetSymbolAddress(&pxl1, g_xl1);
    cudaGetSymbolAddress(&pxr1, g_xr1);
    cudaGetSymbolAddress(&po1, g_o1);
    cudaGetSymbolAddress(&pxl2, g_xl2);
    cudaGetSymbolAddress(&pxr2, g_xr2);

    // Launch order puts the BIG TF32 GEMM in the ncu-profiled slot (4th).
    // Deps: zero_deg<hist<scan<scatter<gat1; conv1<conv2<gemm_big<gat1.
    k_zero_deg<<<NN / 256, 256>>>();                       // 1
    k_conv1<<<NN, 256>>>(x, c1w, c1b);                     // 2
    k_conv2<<<dim3(2, NN), 256>>>(c2w, c2b);               // 3
    k_gemm_tc<<<dim3(4, NN / 128), 256>>>(                  // 4 <- profiled
        (const float*)ph2, Wl1, Wr1, bl1, br1, (float*)pxl1, (float*)pxr1, GIN, 128);
    k_hist<<<EE / 256, 256>>>(ei);                         // 5
    k_scan<<<1, 1024>>>();                                 // 6
    k_scatter<<<EE / 256, 256>>>(ei);                      // 7
    k_gat1<<<NN / 8, 256>>>(att1, bias1);                  // 8
    k_gemm_tc<<<dim3(2, NN / 128), 256>>>(                 // 9
        (const float*)po1, Wl2, Wr2, bl2, br2, (float*)pxl2, (float*)pxr2, 128, 64);
    k_gat2<<<NN / 8, 256>>>(att2);                         // 10
    k_cls<<<(NN * 10 + 255) / 256, 256>>>(Wc, bc, bias2, out);  // 11
}

// round 15
// speedup vs baseline: 1.5151x; 1.0273x over previous
#include <cuda_runtime.h>
#include <cuda_bf16.h>
#include <cuda_fp16.h>
#include <math.h>

#define NN 16384
#define EE 524288
#define GIN 1568       // 32*7*7

typedef unsigned long long u64;

// ---------------- packed / tf32 helpers ---------------------------------------
__device__ __forceinline__ u64 pk2(float x, float y) {
    u64 r; asm("mov.b64 %0, {%1,%2};" : "=l"(r) : "f"(x), "f"(y)); return r;
}
__device__ __forceinline__ u64 pkb(float x) { return pk2(x, x); }
__device__ __forceinline__ u64 ffma2(u64 a, u64 b, u64 c) {
    u64 d; asm("fma.rn.f32x2 %0, %1, %2, %3;" : "=l"(d) : "l"(a), "l"(b), "l"(c)); return d;
}
__device__ __forceinline__ float2 upk(u64 v) {
    float2 r; asm("mov.b64 {%0,%1}, %2;" : "=f"(r.x), "=f"(r.y) : "l"(v)); return r;
}
__device__ __forceinline__ unsigned cvt_tf32(unsigned f) {
    unsigned r; asm("cvt.rna.tf32.f32 %0, %1;" : "=r"(r) : "r"(f)); return r;
}
__device__ __forceinline__ void mma_tf32(float* d, const unsigned* a, const unsigned* b) {
    asm volatile(
        "mma.sync.aligned.m16n8k8.row.col.f32.tf32.tf32.f32 "
        "{%0,%1,%2,%3}, {%4,%5,%6,%7}, {%8,%9}, {%0,%1,%2,%3};"
        : "+f"(d[0]), "+f"(d[1]), "+f"(d[2]), "+f"(d[3])
        : "r"(a[0]), "r"(a[1]), "r"(a[2]), "r"(a[3]), "r"(b[0]), "r"(b[1]));
}
__device__ __forceinline__ void cpasync16(unsigned s, const float* g) {
    asm volatile("cp.async.ca.shared.global [%0], [%1], 16;" :: "r"(s), "l"(g));
}
__device__ __forceinline__ void cp_commit() {
    asm volatile("cp.async.commit_group;");
}
__device__ __forceinline__ void cp_wait1() {
    asm volatile("cp.async.wait_group 1;");
}
__device__ __forceinline__ void ldsm_x4(unsigned* r, unsigned saddr) {
    asm volatile("ldmatrix.sync.aligned.m8n8.x4.shared.b16 {%0,%1,%2,%3}, [%4];"
                 : "=r"(r[0]), "=r"(r[1]), "=r"(r[2]), "=r"(r[3]) : "r"(saddr));
}

// ---------------- scratch (device globals; no allocs allowed) ----------------
__device__ __half g_h1h[NN * 16 * 14 * 14];  // conv1+pool output (fp16)
__device__ float g_h2[NN * GIN];           // conv2+pool output (flattened NCHW)
__device__ float g_xl1[NN * 128];
__device__ float g_xr1[NN * 128];
__device__ float g_o1[NN * 128];           // gat1 out (bias+relu fused)
__device__ float g_xl2[NN * 64];
__device__ float g_xr2[NN * 64];
__device__ float g_o2[NN * 64];            // gat2 out (pre-bias)
// CSR by destination
__device__ int g_deg[NN];                  // histogram, then scatter cursor
__device__ int g_roff[NN + 1];
__device__ int g_esrc[EE];

__device__ __forceinline__ float lrelu(float v) { return v > 0.f ? v : 0.2f * v; }

// ---------------- CSR build ---------------------------------------------------
__global__ void k_zero_deg() {
    int i = blockIdx.x * blockDim.x + threadIdx.x;
    if (i < NN) g_deg[i] = 0;
}

__global__ void k_hist(const int* __restrict__ ei) {
    int e = blockIdx.x * blockDim.x + threadIdx.x;
    if (e < EE) atomicAdd(&g_deg[ei[EE + e]], 1);
}

// single CTA, 1024 threads, 16 nodes/thread exclusive scan
__global__ void k_scan() {
    __shared__ int wsum[32];
    int t = threadIdx.x, lane = t & 31, wid = t >> 5;
    int base = t * 16;
    int c[16];
    int s = 0;
#pragma unroll
    for (int i = 0; i < 16; i++) { c[i] = s; s += g_deg[base + i]; }
    int v = s;
#pragma unroll
    for (int off = 1; off < 32; off <<= 1) {
        int n = __shfl_up_sync(0xffffffffu, v, off);
        if (lane >= off) v += n;
    }
    if (lane == 31) wsum[wid] = v;
    __syncthreads();
    if (wid == 0) {
        int w = wsum[lane];
#pragma unroll
        for (int off = 1; off < 32; off <<= 1) {
            int n = __shfl_up_sync(0xffffffffu, w, off);
            if (lane >= off) w += n;
        }
        wsum[lane] = w;  // inclusive
    }
    __syncthreads();
    int wbase = (wid == 0) ? 0 : wsum[wid - 1];
    int tbase = wbase + (v - s);  // exclusive base for this thread
#pragma unroll
    for (int i = 0; i < 16; i++) {
        int r = tbase + c[i];
        g_roff[base + i] = r;
        g_deg[base + i] = r;   // cursor for scatter
    }
    if (t == 1023) g_roff[NN] = EE;
}

__global__ void k_scatter(const int* __restrict__ ei) {
    int e = blockIdx.x * blockDim.x + threadIdx.x;
    if (e >= EE) return;
    int d = ei[EE + e];
    int pos = atomicAdd(&g_deg[d], 1);
    g_esrc[pos] = ei[e];
}

// ---------------- conv1 (1->16, 3x3 SAME) + relu + maxpool2 -> fp16 ----------
__global__ void k_conv1(const float* __restrict__ x, const float* __restrict__ w,
                        const float* __restrict__ b) {
    __shared__ __align__(16) float sin_[30 * 30];
    __shared__ __align__(16) float sw[9 * 16];   // [k][oc]
    __shared__ __align__(16) float sb[16];
    const int n = blockIdx.x;
    const int t = threadIdx.x;  // 256
    for (int i = t; i < 900; i += 256) sin_[i] = 0.f;
    if (t < 144) { int oc = t / 9, k = t % 9; sw[k * 16 + oc] = w[t]; }
    if (t < 16) sb[t] = b[t];
    __syncthreads();
    const float* xi = x + n * 784;
    for (int i = t; i < 784; i += 256) {
        int y = i / 28, xx = i % 28;
        sin_[(y + 1) * 30 + xx + 1] = xi[i];
    }
    __syncthreads();
    for (int item = t; item < 8 * 196; item += 256) {
        int cp = item / 196, p = item % 196;
        int c0 = cp * 2;
        int py = p / 14, px = p % 14;
        float v[4][4];
#pragma unroll
        for (int r = 0; r < 4; r++) {
            float2 a = *(const float2*)&sin_[(2 * py + r) * 30 + 2 * px];
            float2 c = *(const float2*)&sin_[(2 * py + r) * 30 + 2 * px + 2];
            v[r][0] = a.x; v[r][1] = a.y; v[r][2] = c.x; v[r][3] = c.y;
        }
        u64 bi = *(const u64*)&sb[c0];
        u64 acc[4] = {bi, bi, bi, bi};
#pragma unroll
        for (int ky = 0; ky < 3; ky++)
#pragma unroll
            for (int kx = 0; kx < 3; kx++) {
                u64 wp = *(const u64*)&sw[(ky * 3 + kx) * 16 + c0];
#pragma unroll
                for (int q = 0; q < 4; q++) {
                    int dy = q >> 1, dx = q & 1;
                    acc[q] = ffma2(wp, pkb(v[dy + ky][dx + kx]), acc[q]);
                }
            }
        float2 m0 = upk(acc[0]);
        float mx0 = m0.x, mx1 = m0.y;
#pragma unroll
        for (int q = 1; q < 4; q++) {
            float2 mq = upk(acc[q]);
            mx0 = fmaxf(mx0, mq.x); mx1 = fmaxf(mx1, mq.y);
        }
        g_h1h[n * 3136 + c0 * 196 + p] = __float2half(fmaxf(mx0, 0.f));
        g_h1h[n * 3136 + (c0 + 1) * 196 + p] = __float2half(fmaxf(mx1, 0.f));
    }
}

// ---------------- conv2 (16->32, 3x3 SAME) + relu + maxpool2 -----------------
// grid (2, NN): x = output-channel half (16 oc), y = image. 256 threads.
__global__ void k_conv2(const float* __restrict__ w, const float* __restrict__ b) {
    __shared__ __align__(16) float sin_[16 * 256];   // [ci][16][16]
    __shared__ __align__(16) float sw[16 * 144];     // [ci][k][16 local oc]
    __shared__ __align__(16) float sb[16];
    const int half = blockIdx.x;
    const int n = blockIdx.y;
    const int oc0 = half * 16;
    const int t = threadIdx.x;  // 256
    for (int i = t; i < 4096; i += 256) sin_[i] = 0.f;
    for (int i = t; i < 2304; i += 256) {
        int ocl = i / 144, r = i % 144, ci = r / 9, k = r % 9;
        sw[ci * 144 + k * 16 + ocl] = w[(oc0 + ocl) * 144 + r];
    }
    if (t < 16) sb[t] = b[oc0 + t];
    __syncthreads();
    const __half* hi = g_h1h + (size_t)n * 3136;
    for (int i = t; i < 3136; i += 256) {
        int ci = i / 196, p = i % 196, y = p / 14, xx = p % 14;
        sin_[ci * 256 + (y + 1) * 16 + (xx + 1)] = __half2float(hi[i]);
    }
    __syncthreads();
    if (t < 196) {
        int cg = t / 49, p = t % 49;
        int c0 = cg * 4;
        int py = p / 7, px = p % 7;
        u64 b01 = *(const u64*)&sb[c0];
        u64 b23 = *(const u64*)&sb[c0 + 2];
        u64 acc01[4] = {b01, b01, b01, b01};
        u64 acc23[4] = {b23, b23, b23, b23};
        for (int ci = 0; ci < 16; ci++) {
            const float* ip = sin_ + ci * 256 + 2 * py * 16 + 2 * px;
            float v[4][4];
#pragma unroll
            for (int r = 0; r < 4; r++) {
                float2 a = *(const float2*)&ip[r * 16];
                float2 c = *(const float2*)&ip[r * 16 + 2];
                v[r][0] = a.x; v[r][1] = a.y; v[r][2] = c.x; v[r][3] = c.y;
            }
            const float* wp0 = sw + ci * 144 + c0;
#pragma unroll
            for (int ky = 0; ky < 3; ky++)
#pragma unroll
                for (int kx = 0; kx < 3; kx++) {
                    u64 w01 = *(const u64*)&wp0[(ky * 3 + kx) * 16];
                    u64 w23 = *(const u64*)&wp0[(ky * 3 + kx) * 16 + 2];
#pragma unroll
                    for (int q = 0; q < 4; q++) {
                        int dy = q >> 1, dx = q & 1;
                        u64 vb = pkb(v[dy + ky][dx + kx]);
                        acc01[q] = ffma2(w01, vb, acc01[q]);
                        acc23[q] = ffma2(w23, vb, acc23[q]);
                    }
                }
        }
        float2 a0 = upk(acc01[0]), b0 = upk(acc23[0]);
        float m0 = a0.x, m1 = a0.y, m2 = b0.x, m3 = b0.y;
#pragma unroll
        for (int q = 1; q < 4; q++) {
            float2 aq = upk(acc01[q]), bq = upk(acc23[q]);
            m0 = fmaxf(m0, aq.x); m1 = fmaxf(m1, aq.y);
            m2 = fmaxf(m2, bq.x); m3 = fmaxf(m3, bq.y);
        }
        float* outp = g_h2 + (size_t)n * GIN + (oc0 + c0) * 49 + p;
        outp[0]   = fmaxf(m0, 0.f);
        outp[49]  = fmaxf(m1, 0.f);
        outp[98]  = fmaxf(m2, 0.f);
        outp[147] = fmaxf(m3, 0.f);
    }
}

// ---- TF32 TC dual-weight GEMM v3b: cp.async 2-stage + ldmatrix + cvt.rna ----
// BM=128, BN=64, BK=16 (x2 stages); 8 warps (4 m-rows x 2 n-cols), warp 32x32.
// Fragments rounded to tf32 (rna) in registers before MMA.
__global__ void __launch_bounds__(256, 3) k_gemm_tc(
        const float* __restrict__ A,
        const float* __restrict__ B0, const float* __restrict__ B1,
        const float* __restrict__ bias0, const float* __restrict__ bias1,
        float* __restrict__ C0, float* __restrict__ C1,
        int K, int NC) {
    constexpr int BM = 128, BN = 64, BK = 16;
    constexpr int BKP = 20, BNP = 72;
    constexpr int ASZ = BM * BKP;   // 2560 words
    constexpr int BSZ = BK * BNP;   // 1152 words
    __shared__ __align__(16) unsigned As[2][ASZ];
    __shared__ __align__(16) unsigned Bs[2][BSZ];
    const int t = threadIdx.x, lane = t & 31, w = t >> 5;
    const int wm = (w >> 1) * 32, wn = (w & 1) * 32;
    const int ncolb = NC / BN;
    const int which = blockIdx.x / ncolb;
    const int bn = (blockIdx.x % ncolb) * BN;
    const int bm = blockIdx.y * BM;
    const float* B = which ? B1 : B0;
    const float* bias = which ? bias1 : bias0;
    float* C = which ? C1 : C0;

    float acc[2][4][4];
#pragma unroll
    for (int mt = 0; mt < 2; mt++)
#pragma unroll
        for (int nt = 0; nt < 4; nt++)
#pragma unroll
            for (int c = 0; c < 4; c++) acc[mt][nt][c] = 0.f;

    const unsigned asb = (unsigned)__cvta_generic_to_shared(&As[0][0]);
    const unsigned bsb = (unsigned)__cvta_generic_to_shared(&Bs[0][0]);

    // fill indices: A 8 floats/thread (2x16B), B 4 floats/thread (1x16B)
    const int ar = t >> 1, ac = (t & 1) * 8;
    const int brow = t >> 4, bcol = (t & 15) * 4;
    const float* agp = A + (size_t)(bm + ar) * K + ac;
    const float* bgp = B + (size_t)brow * NC + bn + bcol;
    const unsigned aso = (unsigned)(ar * BKP + ac) * 4;
    const unsigned bso = (unsigned)(brow * BNP + bcol) * 4;

    // ldmatrix address pieces (per thread, fixed across loop)
    const int lr = lane & 15;
    const int lco = (lane >> 4) << 2;

    // prologue: fill stages 0,1
#pragma unroll
    for (int s = 0; s < 2; s++) {
        int k0 = s * BK;
        cpasync16(asb + s * ASZ * 4 + aso, agp + k0);
        cpasync16(asb + s * ASZ * 4 + aso + 16, agp + k0 + 4);
        cpasync16(bsb + s * BSZ * 4 + bso, bgp + (size_t)k0 * NC);
        cp_commit();
    }

    const int nIter = K / BK;
    for (int kt = 0; kt < nIter; kt++) {
        const int cur = kt & 1;
        cp_wait1();
        __syncthreads();
        const unsigned* BsC = Bs[cur];
        const unsigned abase = asb + cur * ASZ * 4;
#pragma unroll
        for (int ks = 0; ks < 2; ks++) {
            const int kk = ks * 8;
            unsigned af[2][4], bf[4][2];
#pragma unroll
            for (int mt = 0; mt < 2; mt++) {
                unsigned sa = abase + (unsigned)((wm + mt * 16 + lr) * BKP + kk + lco) * 4;
                ldsm_x4(af[mt], sa);
#pragma unroll
                for (int q = 0; q < 4; q++) af[mt][q] = cvt_tf32(af[mt][q]);
            }
#pragma unroll
            for (int nt = 0; nt < 4; nt++) {
                int cb = wn + nt * 8 + (lane >> 2);
                bf[nt][0] = cvt_tf32(BsC[(kk + (lane & 3)) * BNP + cb]);
                bf[nt][1] = cvt_tf32(BsC[(kk + (lane & 3) + 4) * BNP + cb]);
            }
#pragma unroll
            for (int mt = 0; mt < 2; mt++)
#pragma unroll
                for (int nt = 0; nt < 4; nt++)
                    mma_tf32(acc[mt][nt], af[mt], bf[nt]);
        }
        __syncthreads();
        const int knext = (kt + 2) * BK;
        if (knext < K) {
            cpasync16(asb + cur * ASZ * 4 + aso, agp + knext);
            cpasync16(asb + cur * ASZ * 4 + aso + 16, agp + knext + 4);
            cpasync16(bsb + cur * BSZ * 4 + bso, bgp + (size_t)knext * NC);
        }
        cp_commit();   // commit (possibly empty) to keep group accounting uniform
    }
#pragma unroll
    for (int nt = 0; nt < 4; nt++) {
        int col = bn + wn + nt * 8 + 2 * (lane & 3);
        float2 bv = *(const float2*)&bias[col];
#pragma unroll
        for (int mt = 0; mt < 2; mt++) {
            int r = bm + wm + mt * 16 + (lane >> 2);
            *(float2*)&C[(size_t)r * NC + col] =
                make_float2(acc[mt][nt][0] + bv.x, acc[mt][nt][1] + bv.y);
            *(float2*)&C[(size_t)(r + 8) * NC + col] =
                make_float2(acc[mt][nt][2] + bv.x, acc[mt][nt][3] + bv.y);
        }
    }
}

// ---------------- GAT layer 1: fused gather, 2-edge pipelined ----------------
__global__ void k_gat1(const float* __restrict__ att, const float* __restrict__ bias) {
    int d = (blockIdx.x * blockDim.x + threadIdx.x) >> 5;
    int lane = threadIdx.x & 31;
    if (d >= NN) return;
    const float4 at = *(const float4*)&att[lane * 4];
    float4 xr = *(const float4*)&g_xr1[(size_t)d * 128 + lane * 4];
    float4 xd = *(const float4*)&g_xl1[(size_t)d * 128 + lane * 4];
    float a = lrelu(xd.x + xr.x) * at.x + lrelu(xd.y + xr.y) * at.y +
              lrelu(xd.z + xr.z) * at.z + lrelu(xd.w + xr.w) * at.w;
    a += __shfl_xor_sync(0xffffffffu, a, 8);
    a += __shfl_xor_sync(0xffffffffu, a, 4);
    a += __shfl_xor_sync(0xffffffffu, a, 2);
    a += __shfl_xor_sync(0xffffffffu, a, 1);
    float ex = __expf(a);
    float den = ex;
    float4 acc = make_float4(ex * xd.x, ex * xd.y, ex * xd.z, ex * xd.w);

    const int i0 = g_roff[d], i1 = g_roff[d + 1];
    int i = i0;
    for (; i + 1 < i1; i += 2) {
        int s0 = g_esrc[i];
        int s1 = g_esrc[i + 1];
        float4 x0 = *(const float4*)&g_xl1[(size_t)s0 * 128 + lane * 4];
        float4 x1 = *(const float4*)&g_xl1[(size_t)s1 * 128 + lane * 4];
        float a0 = lrelu(x0.x + xr.x) * at.x + lrelu(x0.y + xr.y) * at.y +
                   lrelu(x0.z + xr.z) * at.z + lrelu(x0.w + xr.w) * at.w;
        float a1 = lrelu(x1.x + xr.x) * at.x + lrelu(x1.y + xr.y) * at.y +
                   lrelu(x1.z + xr.z) * at.z + lrelu(x1.w + xr.w) * at.w;
        a0 += __shfl_xor_sync(0xffffffffu, a0, 8);
        a1 += __shfl_xor_sync(0xffffffffu, a1, 8);
        a0 += __shfl_xor_sync(0xffffffffu, a0, 4);
        a1 += __shfl_xor_sync(0xffffffffu, a1, 4);
        a0 += __shfl_xor_sync(0xffffffffu, a0, 2);
        a1 += __shfl_xor_sync(0xffffffffu, a1, 2);
        a0 += __shfl_xor_sync(0xffffffffu, a0, 1);
        a1 += __shfl_xor_sync(0xffffffffu, a1, 1);
        float e0 = __expf(a0);
        float e1 = __expf(a1);
        den += e0 + e1;
        acc.x += e0 * x0.x + e1 * x1.x;
        acc.y += e0 * x0.y + e1 * x1.y;
        acc.z += e0 * x0.z + e1 * x1.z;
        acc.w += e0 * x0.w + e1 * x1.w;
    }
    if (i < i1) {
        int s = g_esrc[i];
        float4 xs = *(const float4*)&g_xl1[(size_t)s * 128 + lane * 4];
        float a2 = lrelu(xs.x + xr.x) * at.x + lrelu(xs.y + xr.y) * at.y +
                   lrelu(xs.z + xr.z) * at.z + lrelu(xs.w + xr.w) * at.w;
        a2 += __shfl_xor_sync(0xffffffffu, a2, 8);
        a2 += __shfl_xor_sync(0xffffffffu, a2, 4);
        a2 += __shfl_xor_sync(0xffffffffu, a2, 2);
        a2 += __shfl_xor_sync(0xffffffffu, a2, 1);
        float e2 = __expf(a2);
        den += e2;
        acc.x += e2 * xs.x; acc.y += e2 * xs.y;
        acc.z += e2 * xs.z; acc.w += e2 * xs.w;
    }
    float inv = 1.f / den;
    float4 bv = *(const float4*)&bias[lane * 4];
    float4 o;
    o.x = fmaxf(acc.x * inv + bv.x, 0.f);
    o.y = fmaxf(acc.y * inv + bv.y, 0.f);
    o.z = fmaxf(acc.z * inv + bv.z, 0.f);
    o.w = fmaxf(acc.w * inv + bv.w, 0.f);
    *(float4*)&g_o1[(size_t)d * 128 + lane * 4] = o;
}

// ---------------- GAT layer 2: fused gather, 2-edge pipelined ----------------
__global__ void k_gat2(const float* __restrict__ att) {
    int d = (blockIdx.x * blockDim.x + threadIdx.x) >> 5;
    int lane = threadIdx.x & 31;
    if (d >= NN) return;
    const float2 at = *(const float2*)&att[lane * 2];
    float2 xr = *(const float2*)&g_xr2[(size_t)d * 64 + lane * 2];
    float2 xd = *(const float2*)&g_xl2[(size_t)d * 64 + lane * 2];
    float a = lrelu(xd.x + xr.x) * at.x + lrelu(xd.y + xr.y) * at.y;
    a += __shfl_xor_sync(0xffffffffu, a, 16);
    a += __shfl_xor_sync(0xffffffffu, a, 8);
    a += __shfl_xor_sync(0xffffffffu, a, 4);
    a += __shfl_xor_sync(0xffffffffu, a, 2);
    a += __shfl_xor_sync(0xffffffffu, a, 1);
    float ex = __expf(a);
    float den = ex;
    float2 acc = make_float2(ex * xd.x, ex * xd.y);

    const int i0 = g_roff[d], i1 = g_roff[d + 1];
    int i = i0;
    for (; i + 1 < i1; i += 2) {
        int s0 = g_esrc[i];
        int s1 = g_esrc[i + 1];
        float2 x0 = *(const float2*)&g_xl2[(size_t)s0 * 64 + lane * 2];
        float2 x1 = *(const float2*)&g_xl2[(size_t)s1 * 64 + lane * 2];
        float a0 = lrelu(x0.x + xr.x) * at.x + lrelu(x0.y + xr.y) * at.y;
        float a1 = lrelu(x1.x + xr.x) * at.x + lrelu(x1.y + xr.y) * at.y;
        a0 += __shfl_xor_sync(0xffffffffu, a0, 16);
        a1 += __shfl_xor_sync(0xffffffffu, a1, 16);
        a0 += __shfl_xor_sync(0xffffffffu, a0, 8);
        a1 += __shfl_xor_sync(0xffffffffu, a1, 8);
        a0 += __shfl_xor_sync(0xffffffffu, a0, 4);
        a1 += __shfl_xor_sync(0xffffffffu, a1, 4);
        a0 += __shfl_xor_sync(0xffffffffu, a0, 2);
        a1 += __shfl_xor_sync(0xffffffffu, a1, 2);
        a0 += __shfl_xor_sync(0xffffffffu, a0, 1);
        a1 += __shfl_xor_sync(0xffffffffu, a1, 1);
        float e0 = __expf(a0);
        float e1 = __expf(a1);
        den += e0 + e1;
        acc.x += e0 * x0.x + e1 * x1.x;
        acc.y += e0 * x0.y + e1 * x1.y;
    }
    if (i < i1) {
        int s = g_esrc[i];
        float2 xs = *(const float2*)&g_xl2[(size_t)s * 64 + lane * 2];
        float a2 = lrelu(xs.x + xr.x) * at.x + lrelu(xs.y + xr.y) * at.y;
        a2 += __shfl_xor_sync(0xffffffffu, a2, 16);
        a2 += __shfl_xor_sync(0xffffffffu, a2, 8);
        a2 += __shfl_xor_sync(0xffffffffu, a2, 4);
        a2 += __shfl_xor_sync(0xffffffffu, a2, 2);
        a2 += __shfl_xor_sync(0xffffffffu, a2, 1);
        float e2 = __expf(a2);
        den += e2;
        acc.x += e2 * xs.x; acc.y += e2 * xs.y;
    }
    float inv = 1.f / den;
    *(float2*)&g_o2[(size_t)d * 64 + lane * 2] = make_float2(acc.x * inv, acc.y * inv);
}

// ---------------- classifier: (o2 + bias2) @ Wc + bc -------------------------
__global__ void k_cls(const float* __restrict__ Wc, const float* __restrict__ bc,
                      const float* __restrict__ bias2, float* __restrict__ out) {
    int i = blockIdx.x * blockDim.x + threadIdx.x;
    if (i >= NN * 10) return;
    int n = i / 10, j = i % 10;
    const float* r = g_o2 + (size_t)n * 64;
    float acc = bc[j];
#pragma unroll
    for (int c = 0; c < 64; c++) acc += (r[c] + bias2[c]) * Wc[c * 10 + j];
    out[i] = acc;
}

// ---------------- launcher ----------------------------------------------------
extern "C" void kernel_launch(void* const* d_in, const int* in_sizes, int n_in,
                              void* d_out, int out_size) {
    const float* x = (const float*)d_in[0];
    const int* ei = (const int*)d_in[1];
    const float* c1w = (const float*)d_in[2];
    const float* c1b = (const float*)d_in[3];
    const float* c2w = (const float*)d_in[4];
    const float* c2b = (const float*)d_in[5];
    const float* Wl1 = (const float*)d_in[6];
    const float* bl1 = (const float*)d_in[7];
    const float* Wr1 = (const float*)d_in[8];
    const float* br1 = (const float*)d_in[9];
    const float* att1 = (const float*)d_in[10];
    const float* bias1 = (const float*)d_in[11];
    const float* Wl2 = (const float*)d_in[12];
    const float* bl2 = (const float*)d_in[13];
    const float* Wr2 = (const float*)d_in[14];
    const float* br2 = (const float*)d_in[15];
    const float* att2 = (const float*)d_in[16];
    const float* bias2 = (const float*)d_in[17];
    const float* Wc = (const float*)d_in[18];
    const float* bc = (const float*)d_in[19];
    float* out = (float*)d_out;

    void *ph2, *pxl1, *pxr1, *po1, *pxl2, *pxr2;
    cudaGetSymbolAddress(&ph2, g_h2);
    cudaGetSymbolAddress(&pxl1, g_xl1);
    cudaGetSymbolAddress(&pxr1, g_xr1);
    cudaGetSymbolAddress(&po1, g_o1);
    cudaGetSymbolAddress(&pxl2, g_xl2);
    cudaGetSymbolAddress(&pxr2, g_xr2);

    // Launch order puts k_conv1 in the ncu-profiled slot (4th) to test the
    // DRAM-traffic theory. Deps: hist<scan<scatter<gat1; conv1<conv2<gemm<gat1.
    k_zero_deg<<<NN / 256, 256>>>();                       // 1
    k_hist<<<EE / 256, 256>>>(ei);                         // 2
    k_scan<<<1, 1024>>>();                                 // 3
    k_conv1<<<NN, 256>>>(x, c1w, c1b);                     // 4 <- profiled
    k_conv2<<<dim3(2, NN), 256>>>(c2w, c2b);               // 5
    k_gemm_tc<<<dim3(4, NN / 128), 256>>>(                 // 6
        (const float*)ph2, Wl1, Wr1, bl1, br1, (float*)pxl1, (float*)pxr1, GIN, 128);
    k_scatter<<<EE / 256, 256>>>(ei);                      // 7
    k_gat1<<<NN / 8, 256>>>(att1, bias1);                  // 8
    k_gemm_tc<<<dim3(2, NN / 128), 256>>>(                 // 9
        (const float*)po1, Wl2, Wr2, bl2, br2, (float*)pxl2, (float*)pxr2, 128, 64);
    k_gat2<<<NN / 8, 256>>>(att2);                         // 10
    k_cls<<<(NN * 10 + 255) / 256, 256>>>(Wc, bc, bias2, out);  // 11
}

// round 16
// speedup vs baseline: 1.5212x; 1.0041x over previous
#include <cuda_runtime.h>
#include <cuda_bf16.h>
#include <cuda_fp16.h>
#include <math.h>

#define NN 16384
#define EE 524288
#define GIN 1568       // 32*7*7

typedef unsigned long long u64;

// ---------------- packed / tf32 helpers ---------------------------------------
__device__ __forceinline__ u64 pk2(float x, float y) {
    u64 r; asm("mov.b64 %0, {%1,%2};" : "=l"(r) : "f"(x), "f"(y)); return r;
}
__device__ __forceinline__ u64 pkb(float x) { return pk2(x, x); }
__device__ __forceinline__ u64 ffma2(u64 a, u64 b, u64 c) {
    u64 d; asm("fma.rn.f32x2 %0, %1, %2, %3;" : "=l"(d) : "l"(a), "l"(b), "l"(c)); return d;
}
__device__ __forceinline__ float2 upk(u64 v) {
    float2 r; asm("mov.b64 {%0,%1}, %2;" : "=f"(r.x), "=f"(r.y) : "l"(v)); return r;
}
__device__ __forceinline__ unsigned cvt_tf32(unsigned f) {
    unsigned r; asm("cvt.rna.tf32.f32 %0, %1;" : "=r"(r) : "r"(f)); return r;
}
__device__ __forceinline__ void mma_tf32(float* d, const unsigned* a, const unsigned* b) {
    asm volatile(
        "mma.sync.aligned.m16n8k8.row.col.f32.tf32.tf32.f32 "
        "{%0,%1,%2,%3}, {%4,%5,%6,%7}, {%8,%9}, {%0,%1,%2,%3};"
        : "+f"(d[0]), "+f"(d[1]), "+f"(d[2]), "+f"(d[3])
        : "r"(a[0]), "r"(a[1]), "r"(a[2]), "r"(a[3]), "r"(b[0]), "r"(b[1]));
}
__device__ __forceinline__ void cpasync16(unsigned s, const float* g) {
    asm volatile("cp.async.ca.shared.global [%0], [%1], 16;" :: "r"(s), "l"(g));
}
__device__ __forceinline__ void cp_commit() {
    asm volatile("cp.async.commit_group;");
}
__device__ __forceinline__ void cp_wait1() {
    asm volatile("cp.async.wait_group 1;");
}
__device__ __forceinline__ void ldsm_x4(unsigned* r, unsigned saddr) {
    asm volatile("ldmatrix.sync.aligned.m8n8.x4.shared.b16 {%0,%1,%2,%3}, [%4];"
                 : "=r"(r[0]), "=r"(r[1]), "=r"(r[2]), "=r"(r[3]) : "r"(saddr));
}

// ---------------- scratch (device globals; no allocs allowed) ----------------
__device__ __half g_h1h[NN * 16 * 14 * 14];  // conv1+pool output (fp16)
__device__ float g_h2[NN * GIN];           // conv2+pool output (flattened NCHW)
__device__ float g_xl1[NN * 128];
__device__ float g_xr1[NN * 128];
__device__ float g_o1[NN * 128];           // gat1 out (bias+relu fused)
__device__ float g_xl2[NN * 64];
__device__ float g_xr2[NN * 64];
__device__ float g_o2[NN * 64];            // gat2 out (pre-bias)
// CSR by destination
__device__ int g_deg[NN];                  // histogram, then scatter cursor
__device__ int g_roff[NN + 1];
__device__ int g_esrc[EE];

__device__ __forceinline__ float lrelu(float v) { return v > 0.f ? v : 0.2f * v; }

// ---------------- CSR build ---------------------------------------------------
__global__ void k_zero_deg() {
    int i = blockIdx.x * blockDim.x + threadIdx.x;
    if (i < NN) g_deg[i] = 0;
}

__global__ void k_hist(const int* __restrict__ ei) {
    int e = blockIdx.x * blockDim.x + threadIdx.x;
    if (e < EE) atomicAdd(&g_deg[ei[EE + e]], 1);
}

// single CTA, 1024 threads, 16 nodes/thread exclusive scan
__global__ void k_scan() {
    __shared__ int wsum[32];
    int t = threadIdx.x, lane = t & 31, wid = t >> 5;
    int base = t * 16;
    int c[16];
    int s = 0;
#pragma unroll
    for (int i = 0; i < 16; i++) { c[i] = s; s += g_deg[base + i]; }
    int v = s;
#pragma unroll
    for (int off = 1; off < 32; off <<= 1) {
        int n = __shfl_up_sync(0xffffffffu, v, off);
        if (lane >= off) v += n;
    }
    if (lane == 31) wsum[wid] = v;
    __syncthreads();
    if (wid == 0) {
        int w = wsum[lane];
#pragma unroll
        for (int off = 1; off < 32; off <<= 1) {
            int n = __shfl_up_sync(0xffffffffu, w, off);
            if (lane >= off) w += n;
        }
        wsum[lane] = w;  // inclusive
    }
    __syncthreads();
    int wbase = (wid == 0) ? 0 : wsum[wid - 1];
    int tbase = wbase + (v - s);  // exclusive base for this thread
#pragma unroll
    for (int i = 0; i < 16; i++) {
        int r = tbase + c[i];
        g_roff[base + i] = r;
        g_deg[base + i] = r;   // cursor for scatter
    }
    if (t == 1023) g_roff[NN] = EE;
}

__global__ void k_scatter(const int* __restrict__ ei) {
    int e = blockIdx.x * blockDim.x + threadIdx.x;
    if (e >= EE) return;
    int d = ei[EE + e];
    int pos = atomicAdd(&g_deg[d], 1);
    g_esrc[pos] = ei[e];
}

// ---------------- conv1 (1->16, 3x3 SAME) + relu + maxpool2 -> fp16 ----------
// 196 threads: thread = one pooled position (py,px computed ONCE), v window in
// registers reused across all 8 channel-pairs. No div/mod in the main loop.
__global__ void k_conv1(const float* __restrict__ x, const float* __restrict__ w,
                        const float* __restrict__ b) {
    __shared__ __align__(16) float sin_[30 * 30];
    __shared__ __align__(16) float sw[9 * 16];   // [k][oc]
    __shared__ __align__(16) float sb[16];
    const int n = blockIdx.x;
    const int t = threadIdx.x;  // 196
    for (int i = t; i < 900; i += 196) sin_[i] = 0.f;
    if (t < 144) { int oc = t / 9, k = t % 9; sw[k * 16 + oc] = w[t]; }
    if (t < 16) sb[t] = b[t];
    __syncthreads();
    const float* xi = x + n * 784;
    for (int i = t; i < 784; i += 196) {
        int y = i / 28, xx = i % 28;
        sin_[(y + 1) * 30 + xx + 1] = xi[i];
    }
    __syncthreads();

    const int py = t / 14, px = t % 14;   // once per thread
    float v[4][4];
#pragma unroll
    for (int r = 0; r < 4; r++) {
        float2 a = *(const float2*)&sin_[(2 * py + r) * 30 + 2 * px];
        float2 c = *(const float2*)&sin_[(2 * py + r) * 30 + 2 * px + 2];
        v[r][0] = a.x; v[r][1] = a.y; v[r][2] = c.x; v[r][3] = c.y;
    }
    __half* outp = g_h1h + (size_t)n * 3136 + t;
#pragma unroll
    for (int cp = 0; cp < 8; cp++) {
        const int c0 = cp * 2;
        u64 bi = *(const u64*)&sb[c0];
        u64 acc[4] = {bi, bi, bi, bi};
#pragma unroll
        for (int ky = 0; ky < 3; ky++)
#pragma unroll
            for (int kx = 0; kx < 3; kx++) {
                u64 wp = *(const u64*)&sw[(ky * 3 + kx) * 16 + c0];
#pragma unroll
                for (int q = 0; q < 4; q++) {
                    int dy = q >> 1, dx = q & 1;
                    acc[q] = ffma2(wp, pkb(v[dy + ky][dx + kx]), acc[q]);
                }
            }
        float2 m0 = upk(acc[0]);
        float mx0 = m0.x, mx1 = m0.y;
#pragma unroll
        for (int q = 1; q < 4; q++) {
            float2 mq = upk(acc[q]);
            mx0 = fmaxf(mx0, mq.x); mx1 = fmaxf(mx1, mq.y);
        }
        outp[c0 * 196]       = __float2half(fmaxf(mx0, 0.f));
        outp[(c0 + 1) * 196] = __float2half(fmaxf(mx1, 0.f));
    }
}

// ---------------- conv2 (16->32, 3x3 SAME) + relu + maxpool2 -----------------
// grid (2, NN): x = output-channel half (16 oc), y = image. 256 threads.
__global__ void k_conv2(const float* __restrict__ w, const float* __restrict__ b) {
    __shared__ __align__(16) float sin_[16 * 256];   // [ci][16][16]
    __shared__ __align__(16) float sw[16 * 144];     // [ci][k][16 local oc]
    __shared__ __align__(16) float sb[16];
    const int half = blockIdx.x;
    const int n = blockIdx.y;
    const int oc0 = half * 16;
    const int t = threadIdx.x;  // 256
    for (int i = t; i < 4096; i += 256) sin_[i] = 0.f;
    for (int i = t; i < 2304; i += 256) {
        int ocl = i / 144, r = i % 144, ci = r / 9, k = r % 9;
        sw[ci * 144 + k * 16 + ocl] = w[(oc0 + ocl) * 144 + r];
    }
    if (t < 16) sb[t] = b[oc0 + t];
    __syncthreads();
    const __half* hi = g_h1h + (size_t)n * 3136;
    for (int i = t; i < 3136; i += 256) {
        int ci = i / 196, p = i % 196, y = p / 14, xx = p % 14;
        sin_[ci * 256 + (y + 1) * 16 + (xx + 1)] = __half2float(hi[i]);
    }
    __syncthreads();
    if (t < 196) {
        int cg = t / 49, p = t % 49;
        int c0 = cg * 4;
        int py = p / 7, px = p % 7;
        u64 b01 = *(const u64*)&sb[c0];
        u64 b23 = *(const u64*)&sb[c0 + 2];
        u64 acc01[4] = {b01, b01, b01, b01};
        u64 acc23[4] = {b23, b23, b23, b23};
        for (int ci = 0; ci < 16; ci++) {
            const float* ip = sin_ + ci * 256 + 2 * py * 16 + 2 * px;
            float v[4][4];
#pragma unroll
            for (int r = 0; r < 4; r++) {
                float2 a = *(const float2*)&ip[r * 16];
                float2 c = *(const float2*)&ip[r * 16 + 2];
                v[r][0] = a.x; v[r][1] = a.y; v[r][2] = c.x; v[r][3] = c.y;
            }
            const float* wp0 = sw + ci * 144 + c0;
#pragma unroll
            for (int ky = 0; ky < 3; ky++)
#pragma unroll
                for (int kx = 0; kx < 3; kx++) {
                    u64 w01 = *(const u64*)&wp0[(ky * 3 + kx) * 16];
                    u64 w23 = *(const u64*)&wp0[(ky * 3 + kx) * 16 + 2];
#pragma unroll
                    for (int q = 0; q < 4; q++) {
                        int dy = q >> 1, dx = q & 1;
                        u64 vb = pkb(v[dy + ky][dx + kx]);
                        acc01[q] = ffma2(w01, vb, acc01[q]);
                        acc23[q] = ffma2(w23, vb, acc23[q]);
                    }
                }
        }
        float2 a0 = upk(acc01[0]), b0 = upk(acc23[0]);
        float m0 = a0.x, m1 = a0.y, m2 = b0.x, m3 = b0.y;
#pragma unroll
        for (int q = 1; q < 4; q++) {
            float2 aq = upk(acc01[q]), bq = upk(acc23[q]);
            m0 = fmaxf(m0, aq.x); m1 = fmaxf(m1, aq.y);
            m2 = fmaxf(m2, bq.x); m3 = fmaxf(m3, bq.y);
        }
        float* outp = g_h2 + (size_t)n * GIN + (oc0 + c0) * 49 + p;
        outp[0]   = fmaxf(m0, 0.f);
        outp[49]  = fmaxf(m1, 0.f);
        outp[98]  = fmaxf(m2, 0.f);
        outp[147] = fmaxf(m3, 0.f);
    }
}

// ---- TF32 TC dual-weight GEMM v3b: cp.async 2-stage + ldmatrix + cvt.rna ----
__global__ void __launch_bounds__(256, 3) k_gemm_tc(
        const float* __restrict__ A,
        const float* __restrict__ B0, const float* __restrict__ B1,
        const float* __restrict__ bias0, const float* __restrict__ bias1,
        float* __restrict__ C0, float* __restrict__ C1,
        int K, int NC) {
    constexpr int BM = 128, BN = 64, BK = 16;
    constexpr int BKP = 20, BNP = 72;
    constexpr int ASZ = BM * BKP;   // 2560 words
    constexpr int BSZ = BK * BNP;   // 1152 words
    __shared__ __align__(16) unsigned As[2][ASZ];
    __shared__ __align__(16) unsigned Bs[2][BSZ];
    const int t = threadIdx.x, lane = t & 31, w = t >> 5;
    const int wm = (w >> 1) * 32, wn = (w & 1) * 32;
    const int ncolb = NC / BN;
    const int which = blockIdx.x / ncolb;
    const int bn = (blockIdx.x % ncolb) * BN;
    const int bm = blockIdx.y * BM;
    const float* B = which ? B1 : B0;
    const float* bias = which ? bias1 : bias0;
    float* C = which ? C1 : C0;

    float acc[2][4][4];
#pragma unroll
    for (int mt = 0; mt < 2; mt++)
#pragma unroll
        for (int nt = 0; nt < 4; nt++)
#pragma unroll
            for (int c = 0; c < 4; c++) acc[mt][nt][c] = 0.f;

    const unsigned asb = (unsigned)__cvta_generic_to_shared(&As[0][0]);
    const unsigned bsb = (unsigned)__cvta_generic_to_shared(&Bs[0][0]);

    const int ar = t >> 1, ac = (t & 1) * 8;
    const int brow = t >> 4, bcol = (t & 15) * 4;
    const float* agp = A + (size_t)(bm + ar) * K + ac;
    const float* bgp = B + (size_t)brow * NC + bn + bcol;
    const unsigned aso = (unsigned)(ar * BKP + ac) * 4;
    const unsigned bso = (unsigned)(brow * BNP + bcol) * 4;

    const int lr = lane & 15;
    const int lco = (lane >> 4) << 2;

#pragma unroll
    for (int s = 0; s < 2; s++) {
        int k0 = s * BK;
        cpasync16(asb + s * ASZ * 4 + aso, agp + k0);
        cpasync16(asb + s * ASZ * 4 + aso + 16, agp + k0 + 4);
        cpasync16(bsb + s * BSZ * 4 + bso, bgp + (size_t)k0 * NC);
        cp_commit();
    }

    const int nIter = K / BK;
    for (int kt = 0; kt < nIter; kt++) {
        const int cur = kt & 1;
        cp_wait1();
        __syncthreads();
        const unsigned* BsC = Bs[cur];
        const unsigned abase = asb + cur * ASZ * 4;
#pragma unroll
        for (int ks = 0; ks < 2; ks++) {
            const int kk = ks * 8;
            unsigned af[2][4], bf[4][2];
#pragma unroll
            for (int mt = 0; mt < 2; mt++) {
                unsigned sa = abase + (unsigned)((wm + mt * 16 + lr) * BKP + kk + lco) * 4;
                ldsm_x4(af[mt], sa);
#pragma unroll
                for (int q = 0; q < 4; q++) af[mt][q] = cvt_tf32(af[mt][q]);
            }
#pragma unroll
            for (int nt = 0; nt < 4; nt++) {
                int cb = wn + nt * 8 + (lane >> 2);
                bf[nt][0] = cvt_tf32(BsC[(kk + (lane & 3)) * BNP + cb]);
                bf[nt][1] = cvt_tf32(BsC[(kk + (lane & 3) + 4) * BNP + cb]);
            }
#pragma unroll
            for (int mt = 0; mt < 2; mt++)
#pragma unroll
                for (int nt = 0; nt < 4; nt++)
                    mma_tf32(acc[mt][nt], af[mt], bf[nt]);
        }
        __syncthreads();
        const int knext = (kt + 2) * BK;
        if (knext < K) {
            cpasync16(asb + cur * ASZ * 4 + aso, agp + knext);
            cpasync16(asb + cur * ASZ * 4 + aso + 16, agp + knext + 4);
            cpasync16(bsb + cur * BSZ * 4 + bso, bgp + (size_t)knext * NC);
        }
        cp_commit();
    }
#pragma unroll
    for (int nt = 0; nt < 4; nt++) {
        int col = bn + wn + nt * 8 + 2 * (lane & 3);
        float2 bv = *(const float2*)&bias[col];
#pragma unroll
        for (int mt = 0; mt < 2; mt++) {
            int r = bm + wm + mt * 16 + (lane >> 2);
            *(float2*)&C[(size_t)r * NC + col] =
                make_float2(acc[mt][nt][0] + bv.x, acc[mt][nt][1] + bv.y);
            *(float2*)&C[(size_t)(r + 8) * NC + col] =
                make_float2(acc[mt][nt][2] + bv.x, acc[mt][nt][3] + bv.y);
        }
    }
}

// ---------------- GAT layer 1: fused gather, 2-edge pipelined ----------------
__global__ void k_gat1(const float* __restrict__ att, const float* __restrict__ bias) {
    int d = (blockIdx.x * blockDim.x + threadIdx.x) >> 5;
    int lane = threadIdx.x & 31;
    if (d >= NN) return;
    const float4 at = *(const float4*)&att[lane * 4];
    float4 xr = *(const float4*)&g_xr1[(size_t)d * 128 + lane * 4];
    float4 xd = *(const float4*)&g_xl1[(size_t)d * 128 + lane * 4];
    float a = lrelu(xd.x + xr.x) * at.x + lrelu(xd.y + xr.y) * at.y +
              lrelu(xd.z + xr.z) * at.z + lrelu(xd.w + xr.w) * at.w;
    a += __shfl_xor_sync(0xffffffffu, a, 8);
    a += __shfl_xor_sync(0xffffffffu, a, 4);
    a += __shfl_xor_sync(0xffffffffu, a, 2);
    a += __shfl_xor_sync(0xffffffffu, a, 1);
    float ex = __expf(a);
    float den = ex;
    float4 acc = make_float4(ex * xd.x, ex * xd.y, ex * xd.z, ex * xd.w);

    const int i0 = g_roff[d], i1 = g_roff[d + 1];
    int i = i0;
    for (; i + 1 < i1; i += 2) {
        int s0 = g_esrc[i];
        int s1 = g_esrc[i + 1];
        float4 x0 = *(const float4*)&g_xl1[(size_t)s0 * 128 + lane * 4];
        float4 x1 = *(const float4*)&g_xl1[(size_t)s1 * 128 + lane * 4];
        float a0 = lrelu(x0.x + xr.x) * at.x + lrelu(x0.y + xr.y) * at.y +
                   lrelu(x0.z + xr.z) * at.z + lrelu(x0.w + xr.w) * at.w;
        float a1 = lrelu(x1.x + xr.x) * at.x + lrelu(x1.y + xr.y) * at.y +
                   lrelu(x1.z + xr.z) * at.z + lrelu(x1.w + xr.w) * at.w;
        a0 += __shfl_xor_sync(0xffffffffu, a0, 8);
        a1 += __shfl_xor_sync(0xffffffffu, a1, 8);
        a0 += __shfl_xor_sync(0xffffffffu, a0, 4);
        a1 += __shfl_xor_sync(0xffffffffu, a1, 4);
        a0 += __shfl_xor_sync(0xffffffffu, a0, 2);
        a1 += __shfl_xor_sync(0xffffffffu, a1, 2);
        a0 += __shfl_xor_sync(0xffffffffu, a0, 1);
        a1 += __shfl_xor_sync(0xffffffffu, a1, 1);
        float e0 = __expf(a0);
        float e1 = __expf(a1);
        den += e0 + e1;
        acc.x += e0 * x0.x + e1 * x1.x;
        acc.y += e0 * x0.y + e1 * x1.y;
        acc.z += e0 * x0.z + e1 * x1.z;
        acc.w += e0 * x0.w + e1 * x1.w;
    }
    if (i < i1) {
        int s = g_esrc[i];
        float4 xs = *(const float4*)&g_xl1[(size_t)s * 128 + lane * 4];
        float a2 = lrelu(xs.x + xr.x) * at.x + lrelu(xs.y + xr.y) * at.y +
                   lrelu(xs.z + xr.z) * at.z + lrelu(xs.w + xr.w) * at.w;
        a2 += __shfl_xor_sync(0xffffffffu, a2, 8);
        a2 += __shfl_xor_sync(0xffffffffu, a2, 4);
        a2 += __shfl_xor_sync(0xffffffffu, a2, 2);
        a2 += __shfl_xor_sync(0xffffffffu, a2, 1);
        float e2 = __expf(a2);
        den += e2;
        acc.x += e2 * xs.x; acc.y += e2 * xs.y;
        acc.z += e2 * xs.z; acc.w += e2 * xs.w;
    }
    float inv = 1.f / den;
    float4 bv = *(const float4*)&bias[lane * 4];
    float4 o;
    o.x = fmaxf(acc.x * inv + bv.x, 0.f);
    o.y = fmaxf(acc.y * inv + bv.y, 0.f);
    o.z = fmaxf(acc.z * inv + bv.z, 0.f);
    o.w = fmaxf(acc.w * inv + bv.w, 0.f);
    *(float4*)&g_o1[(size_t)d * 128 + lane * 4] = o;
}

// ---------------- GAT layer 2: fused gather, 2-edge pipelined ----------------
__global__ void k_gat2(const float* __restrict__ att) {
    int d = (blockIdx.x * blockDim.x + threadIdx.x) >> 5;
    int lane = threadIdx.x & 31;
    if (d >= NN) return;
    const float2 at = *(const float2*)&att[lane * 2];
    float2 xr = *(const float2*)&g_xr2[(size_t)d * 64 + lane * 2];
    float2 xd = *(const float2*)&g_xl2[(size_t)d * 64 + lane * 2];
    float a = lrelu(xd.x + xr.x) * at.x + lrelu(xd.y + xr.y) * at.y;
    a += __shfl_xor_sync(0xffffffffu, a, 16);
    a += __shfl_xor_sync(0xffffffffu, a, 8);
    a += __shfl_xor_sync(0xffffffffu, a, 4);
    a += __shfl_xor_sync(0xffffffffu, a, 2);
    a += __shfl_xor_sync(0xffffffffu, a, 1);
    float ex = __expf(a);
    float den = ex;
    float2 acc = make_float2(ex * xd.x, ex * xd.y);

    const int i0 = g_roff[d], i1 = g_roff[d + 1];
    int i = i0;
    for (; i + 1 < i1; i += 2) {
        int s0 = g_esrc[i];
        int s1 = g_esrc[i + 1];
        float2 x0 = *(const float2*)&g_xl2[(size_t)s0 * 64 + lane * 2];
        float2 x1 = *(const float2*)&g_xl2[(size_t)s1 * 64 + lane * 2];
        float a0 = lrelu(x0.x + xr.x) * at.x + lrelu(x0.y + xr.y) * at.y;
        float a1 = lrelu(x1.x + xr.x) * at.x + lrelu(x1.y + xr.y) * at.y;
        a0 += __shfl_xor_sync(0xffffffffu, a0, 16);
        a1 += __shfl_xor_sync(0xffffffffu, a1, 16);
        a0 += __shfl_xor_sync(0xffffffffu, a0, 8);
        a1 += __shfl_xor_sync(0xffffffffu, a1, 8);
        a0 += __shfl_xor_sync(0xffffffffu, a0, 4);
        a1 += __shfl_xor_sync(0xffffffffu, a1, 4);
        a0 += __shfl_xor_sync(0xffffffffu, a0, 2);
        a1 += __shfl_xor_sync(0xffffffffu, a1, 2);
        a0 += __shfl_xor_sync(0xffffffffu, a0, 1);
        a1 += __shfl_xor_sync(0xffffffffu, a1, 1);
        float e0 = __expf(a0);
        float e1 = __expf(a1);
        den += e0 + e1;
        acc.x += e0 * x0.x + e1 * x1.x;
        acc.y += e0 * x0.y + e1 * x1.y;
    }
    if (i < i1) {
        int s = g_esrc[i];
        float2 xs = *(const float2*)&g_xl2[(size_t)s * 64 + lane * 2];
        float a2 = lrelu(xs.x + xr.x) * at.x + lrelu(xs.y + xr.y) * at.y;
        a2 += __shfl_xor_sync(0xffffffffu, a2, 16);
        a2 += __shfl_xor_sync(0xffffffffu, a2, 8);
        a2 += __shfl_xor_sync(0xffffffffu, a2, 4);
        a2 += __shfl_xor_sync(0xffffffffu, a2, 2);
        a2 += __shfl_xor_sync(0xffffffffu, a2, 1);
        float e2 = __expf(a2);
        den += e2;
        acc.x += e2 * xs.x; acc.y += e2 * xs.y;
    }
    float inv = 1.f / den;
    *(float2*)&g_o2[(size_t)d * 64 + lane * 2] = make_float2(acc.x * inv, acc.y * inv);
}

// ---------------- classifier: (o2 + bias2) @ Wc + bc -------------------------
__global__ void k_cls(const float* __restrict__ Wc, const float* __restrict__ bc,
                      const float* __restrict__ bias2, float* __restrict__ out) {
    int i = blockIdx.x * blockDim.x + threadIdx.x;
    if (i >= NN * 10) return;
    int n = i / 10, j = i % 10;
    const float* r = g_o2 + (size_t)n * 64;
    float acc = bc[j];
#pragma unroll
    for (int c = 0; c < 64; c++) acc += (r[c] + bias2[c]) * Wc[c * 10 + j];
    out[i] = acc;
}

// ---------------- launcher ----------------------------------------------------
extern "C" void kernel_launch(void* const* d_in, const int* in_sizes, int n_in,
                              void* d_out, int out_size) {
    const float* x = (const float*)d_in[0];
    const int* ei = (const int*)d_in[1];
    const float* c1w = (const float*)d_in[2];
    const float* c1b = (const float*)d_in[3];
    const float* c2w = (const float*)d_in[4];
    const float* c2b = (const float*)d_in[5];
    const float* Wl1 = (const float*)d_in[6];
    const float* bl1 = (const float*)d_in[7];
    const float* Wr1 = (const float*)d_in[8];
    const float* br1 = (const float*)d_in[9];
    const float* att1 = (const float*)d_in[10];
    const float* bias1 = (const float*)d_in[11];
    const float* Wl2 = (const float*)d_in[12];
    const float* bl2 = (const float*)d_in[13];
    const float* Wr2 = (const float*)d_in[14];
    const float* br2 = (const float*)d_in[15];
    const float* att2 = (const float*)d_in[16];
    const float* bias2 = (const float*)d_in[17];
    const float* Wc = (const float*)d_in[18];
    const float* bc = (const float*)d_in[19];
    float* out = (float*)d_out;

    void *ph2, *pxl1, *pxr1, *po1, *pxl2, *pxr2;
    cudaGetSymbolAddress(&ph2, g_h2);
    cudaGetSymbolAddress(&pxl1, g_xl1);
    cudaGetSymbolAddress(&pxr1, g_xr1);
    cudaGetSymbolAddress(&po1, g_o1);
    cudaGetSymbolAddress(&pxl2, g_xl2);
    cudaGetSymbolAddress(&pxr2, g_xr2);

    // Launch order puts k_conv2 in the ncu-profiled slot (4th).
    // Deps: hist<scan<scatter<gat1; conv1<conv2<gemm_big<gat1.
    k_zero_deg<<<NN / 256, 256>>>();                       // 1
    k_hist<<<EE / 256, 256>>>(ei);                         // 2
    k_conv1<<<NN, 196>>>(x, c1w, c1b);                     // 3
    k_conv2<<<dim3(2, NN), 256>>>(c2w, c2b);               // 4 <- profiled
    k_scan<<<1, 1024>>>();                                 // 5
    k_scatter<<<EE / 256, 256>>>(ei);                      // 6
    k_gemm_tc<<<dim3(4, NN / 128), 256>>>(                 // 7
        (const float*)ph2, Wl1, Wr1, bl1, br1, (float*)pxl1, (float*)pxr1, GIN, 128);
    k_gat1<<<NN / 8, 256>>>(att1, bias1);                  // 8
    k_gemm_tc<<<dim3(2, NN / 128), 256>>>(                 // 9
        (const float*)po1, Wl2, Wr2, bl2, br2, (float*)pxl2, (float*)pxr2, 128, 64);
    k_gat2<<<NN / 8, 256>>>(att2);                         // 10
    k_cls<<<(NN * 10 + 255) / 256, 256>>>(Wc, bc, bias2, out);  // 11
}